// round 1
// baseline (speedup 1.0000x reference)
#include <cuda_runtime.h>
#include <cuda_bf16.h>
#include <math.h>

// Problem constants
#define BB   2
#define SS   768
#define CA   768
#define CS   384
#define CZ   128
#define HH   16
#define HD   48
#define MM   (BB*SS)          // 1536
#define EPS  1e-5f
#define SCALE (0.14433756729740643f)  // 1/sqrt(48)

// ---------------- scratch (device globals; no allocation allowed) ----------
__device__ float g_sn   [MM*CS];            // LN(s)*gamma
__device__ float g_lna  [MM*CA];            // LN(a)
__device__ float g_tg   [MM*CA];            // s_n @ W_ada_g + b_ada_g
__device__ float g_an   [MM*CA];            // adaLN output
__device__ float g_q    [BB*HH*SS*HD];      // [b,h,s,d]
__device__ float g_kt   [BB*HH*HD*SS];      // [b,h,d,s]
__device__ float g_v    [BB*HH*SS*HD];      // [b,h,s,d]
__device__ float g_gate [MM*CA];            // a_n @ Wg (pre-sigmoid), natural layout
__device__ float g_logits[BB*HH*SS*SS];     // bias -> logits -> attn (75.5 MB)
__device__ float g_go   [MM*CA];            // sigmoid(g)*o, natural layout

// ---------------- helpers ---------------------------------------------------
__device__ __forceinline__ float sigmoidf_(float x) {
    return 1.0f / (1.0f + expf(-x));
}

__device__ float2 blockReduceSum2(float a, float b) {
    __shared__ float sa[32], sb[32];
    int lane = threadIdx.x & 31, wid = threadIdx.x >> 5;
    #pragma unroll
    for (int o = 16; o; o >>= 1) {
        a += __shfl_xor_sync(0xffffffffu, a, o);
        b += __shfl_xor_sync(0xffffffffu, b, o);
    }
    if (lane == 0) { sa[wid] = a; sb[wid] = b; }
    __syncthreads();
    if (wid == 0) {
        int nw = (blockDim.x + 31) >> 5;
        a = (lane < nw) ? sa[lane] : 0.0f;
        b = (lane < nw) ? sb[lane] : 0.0f;
        #pragma unroll
        for (int o = 16; o; o >>= 1) {
            a += __shfl_xor_sync(0xffffffffu, a, o);
            b += __shfl_xor_sync(0xffffffffu, b, o);
        }
        if (lane == 0) { sa[0] = a; sb[0] = b; }
    }
    __syncthreads();
    float2 r = make_float2(sa[0], sb[0]);
    __syncthreads();
    return r;
}

// ---------------- LN kernel: per row, s_n = LN(s)*gamma ; lna = LN(a) -------
__global__ void ln_kernel(const float* __restrict__ s, const float* __restrict__ a,
                          const float* __restrict__ gamma_s) {
    int r = blockIdx.x;                   // 0..MM-1
    int tid = threadIdx.x;

    // ---- s (CS=384)
    const float* srow = s + (long)r * CS;
    float sum = 0.f, sq = 0.f;
    for (int c = tid; c < CS; c += blockDim.x) {
        float v = srow[c]; sum += v; sq += v * v;
    }
    float2 t = blockReduceSum2(sum, sq);
    float mean = t.x / CS;
    float var  = t.y / CS - mean * mean;
    float rstd = rsqrtf(var + EPS);
    for (int c = tid; c < CS; c += blockDim.x)
        g_sn[(long)r * CS + c] = (srow[c] - mean) * rstd * gamma_s[c];

    // ---- a (CA=768)
    const float* arow = a + (long)r * CA;
    sum = 0.f; sq = 0.f;
    for (int c = tid; c < CA; c += blockDim.x) {
        float v = arow[c]; sum += v; sq += v * v;
    }
    t = blockReduceSum2(sum, sq);
    mean = t.x / CA;
    var  = t.y / CA - mean * mean;
    rstd = rsqrtf(var + EPS);
    for (int c = tid; c < CA; c += blockDim.x)
        g_lna[(long)r * CA + c] = (arow[c] - mean) * rstd;
}

// ---------------- generic tiled SGEMM with fused epilogues ------------------
// C(M,N) = A(M,K) @ B(K,N), row-major, optional batch strides (blockIdx.z).
// MODE: 0 plain (+bias), 1 adaLN combine, 2 scatter q(+bias), 3 scatter kT,
//       4 scatter v, 5 logits accumulate (*SCALE + old), 6 AV + sigmoid(gate),
//       8 multiply d_out by sigmoid(acc+bias)
#define BM 64
#define BN 64
#define BKT 16

template <int MODE>
__global__ void __launch_bounds__(256)
gemm_kernel(const float* __restrict__ A, int lda, long sA,
            const float* __restrict__ B, int ldb, long sB,
            float* __restrict__ C, int ldc, long sC,
            int M, int N, int K,
            const float* __restrict__ bias,
            const float* __restrict__ aux1,
            const float* __restrict__ aux2) {
    int batch = blockIdx.z;
    A += (long)batch * sA;
    B += (long)batch * sB;

    __shared__ float As[BKT][BM];
    __shared__ float Bs[BKT][BN];

    int tid = threadIdx.x;
    int row0 = blockIdx.y * BM;
    int col0 = blockIdx.x * BN;

    int tx = tid & 15, ty = tid >> 4;
    int arow = tid >> 2;              // 0..63
    int ak   = (tid & 3) * 4;         // 0,4,8,12
    int bk   = tid >> 4;              // 0..15
    int bcol = (tid & 15) * 4;        // 0..60

    float acc[4][4];
    #pragma unroll
    for (int i = 0; i < 4; i++)
        #pragma unroll
        for (int j = 0; j < 4; j++) acc[i][j] = 0.f;

    for (int k0 = 0; k0 < K; k0 += BKT) {
        float4 av = make_float4(0.f, 0.f, 0.f, 0.f);
        int gr = row0 + arow;
        if (gr < M) av = *(const float4*)&A[(long)gr * lda + (k0 + ak)];
        As[ak + 0][arow] = av.x;
        As[ak + 1][arow] = av.y;
        As[ak + 2][arow] = av.z;
        As[ak + 3][arow] = av.w;

        float4 bv = make_float4(0.f, 0.f, 0.f, 0.f);
        int gc = col0 + bcol;
        if (gc < N) bv = *(const float4*)&B[(long)(k0 + bk) * ldb + gc];
        *(float4*)&Bs[bk][bcol] = bv;
        __syncthreads();

        #pragma unroll
        for (int kk = 0; kk < BKT; kk++) {
            float4 a4 = *(const float4*)&As[kk][ty * 4];
            float4 b4 = *(const float4*)&Bs[kk][tx * 4];
            float aa[4] = {a4.x, a4.y, a4.z, a4.w};
            float bb[4] = {b4.x, b4.y, b4.z, b4.w};
            #pragma unroll
            for (int i = 0; i < 4; i++)
                #pragma unroll
                for (int j = 0; j < 4; j++)
                    acc[i][j] += aa[i] * bb[j];
        }
        __syncthreads();
    }

    #pragma unroll
    for (int i = 0; i < 4; i++) {
        #pragma unroll
        for (int j = 0; j < 4; j++) {
            int m = row0 + ty * 4 + i;
            int n = col0 + tx * 4 + j;
            if (m >= M || n >= N) continue;
            float v = acc[i][j];
            if (MODE == 0) {
                if (bias) v += bias[n];
                C[(long)batch * sC + (long)m * ldc + n] = v;
            } else if (MODE == 1) {
                float tg = aux1[(long)m * CA + n];
                C[(long)m * ldc + n] = sigmoidf_(tg) * aux2[(long)m * CA + n] + v;
            } else if (MODE == 2) {
                v += bias[n];
                int b = m / SS, si = m % SS, h = n / HD, d = n % HD;
                C[(((long)(b * HH + h) * SS) + si) * HD + d] = v;
            } else if (MODE == 3) {
                int b = m / SS, si = m % SS, h = n / HD, d = n % HD;
                C[(((long)(b * HH + h) * HD) + d) * SS + si] = v;
            } else if (MODE == 4) {
                int b = m / SS, si = m % SS, h = n / HD, d = n % HD;
                C[(((long)(b * HH + h) * SS) + si) * HD + d] = v;
            } else if (MODE == 5) {
                long off = (long)batch * sC + (long)m * ldc + n;
                C[off] = C[off] + SCALE * v;
            } else if (MODE == 6) {
                int b = batch / HH, h = batch % HH;
                long gi = ((long)(b * SS + m)) * CA + h * HD + n;
                C[gi] = v * sigmoidf_(aux1[gi]);
            } else if (MODE == 8) {
                long off = (long)m * ldc + n;
                C[off] = C[off] * sigmoidf_(v + bias[n]);
            }
        }
    }
}

// ---------------- pair bias: LN(z)*gz+bz @ Wb + beta, transposed store ------
// block: 256 threads; grid (S/32, S, B).  Handles z rows (b, p0..p0+31, q).
// Writes logits[b,h,q,p] (= b_pair[b,p,q,h]) coalesced along p.
__global__ void __launch_bounds__(256)
pairbias_kernel(const float* __restrict__ z, const float* __restrict__ beta,
                const float* __restrict__ Wb, const float* __restrict__ gz,
                const float* __restrict__ bz) {
    __shared__ float WbT[HH * CZ];      // [h][c]
    __shared__ float gzs[CZ], bzs[CZ];
    __shared__ float res[32][HH + 1];

    int tid = threadIdx.x;
    int lane = tid & 31, w = tid >> 5;
    for (int idx = tid; idx < CZ * HH; idx += 256) {
        int c = idx >> 4, h = idx & 15;
        WbT[h * CZ + c] = Wb[idx];      // Wb is [CZ, HH] row-major
    }
    for (int idx = tid; idx < CZ; idx += 256) { gzs[idx] = gz[idx]; bzs[idx] = bz[idx]; }
    __syncthreads();

    int b = blockIdx.z, q = blockIdx.y, p0 = blockIdx.x * 32;

    for (int rr = 0; rr < 4; rr++) {
        int pl = w * 4 + rr;
        int p = p0 + pl;
        const float* zr = z + (((long)(b * SS + p) * SS) + q) * CZ;
        float v[4];
        float sum = 0.f, sq = 0.f;
        #pragma unroll
        for (int t = 0; t < 4; t++) {
            v[t] = zr[lane + 32 * t];
            sum += v[t]; sq += v[t] * v[t];
        }
        #pragma unroll
        for (int o = 16; o; o >>= 1) {
            sum += __shfl_xor_sync(0xffffffffu, sum, o);
            sq  += __shfl_xor_sync(0xffffffffu, sq,  o);
        }
        float mean = sum * (1.0f / CZ);
        float var  = sq * (1.0f / CZ) - mean * mean;
        float rstd = rsqrtf(var + EPS);
        float zn[4];
        #pragma unroll
        for (int t = 0; t < 4; t++) {
            int c = lane + 32 * t;
            zn[t] = (v[t] - mean) * rstd * gzs[c] + bzs[c];
        }
        float ph[HH];
        #pragma unroll
        for (int h = 0; h < HH; h++) {
            float acc = 0.f;
            #pragma unroll
            for (int t = 0; t < 4; t++)
                acc += zn[t] * WbT[h * CZ + lane + 32 * t];
            ph[h] = acc;
        }
        #pragma unroll
        for (int o = 16; o; o >>= 1) {
            #pragma unroll
            for (int h = 0; h < HH; h++)
                ph[h] += __shfl_xor_sync(0xffffffffu, ph[h], o);
        }
        if (lane < HH) {
            float bet = beta[(((long)(b * SS + p) * SS) + q) * HH + lane];
            res[pl][lane] = ph[lane] + bet;
        }
    }
    __syncthreads();
    for (int idx = tid; idx < 32 * HH; idx += 256) {
        int h = idx >> 5, pl = idx & 31;
        g_logits[(((long)(b * HH + h) * SS) + q) * SS + p0 + pl] = res[pl][h];
    }
}

// ---------------- softmax over last dim of logits ---------------------------
__global__ void __launch_bounds__(256)
softmax_kernel(float* __restrict__ logits) {
    long r = blockIdx.x;                 // BB*HH*SS rows
    float* row = logits + r * SS;
    __shared__ float buf[SS];
    __shared__ float red[32];
    int tid = threadIdx.x, lane = tid & 31, wid = tid >> 5;

    float mx = -3.4e38f;
    for (int c = tid; c < SS; c += blockDim.x) {
        float v = row[c];
        buf[c] = v;
        mx = fmaxf(mx, v);
    }
    #pragma unroll
    for (int o = 16; o; o >>= 1) mx = fmaxf(mx, __shfl_xor_sync(0xffffffffu, mx, o));
    if (lane == 0) red[wid] = mx;
    __syncthreads();
    if (wid == 0) {
        mx = (lane < 8) ? red[lane] : -3.4e38f;
        #pragma unroll
        for (int o = 16; o; o >>= 1) mx = fmaxf(mx, __shfl_xor_sync(0xffffffffu, mx, o));
        if (lane == 0) red[0] = mx;
    }
    __syncthreads();
    mx = red[0];
    __syncthreads();

    float sum = 0.f;
    for (int c = tid; c < SS; c += blockDim.x) {
        float e = __expf(buf[c] - mx);
        buf[c] = e;
        sum += e;
    }
    #pragma unroll
    for (int o = 16; o; o >>= 1) sum += __shfl_xor_sync(0xffffffffu, sum, o);
    if (lane == 0) red[wid] = sum;
    __syncthreads();
    if (wid == 0) {
        sum = (lane < 8) ? red[lane] : 0.f;
        #pragma unroll
        for (int o = 16; o; o >>= 1) sum += __shfl_xor_sync(0xffffffffu, sum, o);
        if (lane == 0) red[0] = sum;
    }
    __syncthreads();
    float inv = 1.0f / red[0];
    for (int c = tid; c < SS; c += blockDim.x)
        row[c] = buf[c] * inv;
}

// ---------------- host side -------------------------------------------------
static float* sym(const void* symbol) {
    void* p = nullptr;
    cudaGetSymbolAddress(&p, symbol);
    return (float*)p;
}

extern "C" void kernel_launch(void* const* d_in, const int* in_sizes, int n_in,
                              void* d_out, int out_size) {
    const float* a        = (const float*)d_in[0];
    const float* s        = (const float*)d_in[1];
    const float* z        = (const float*)d_in[2];
    const float* beta     = (const float*)d_in[3];
    const float* gamma_s  = (const float*)d_in[4];
    const float* W_ada_g  = (const float*)d_in[5];
    const float* b_ada_g  = (const float*)d_in[6];
    const float* W_ada_o  = (const float*)d_in[7];
    const float* Wq       = (const float*)d_in[8];
    const float* bq       = (const float*)d_in[9];
    const float* Wk       = (const float*)d_in[10];
    const float* Wv       = (const float*)d_in[11];
    const float* Wb       = (const float*)d_in[12];
    const float* gz       = (const float*)d_in[13];
    const float* bz       = (const float*)d_in[14];
    const float* Wg       = (const float*)d_in[15];
    const float* Wout     = (const float*)d_in[16];
    const float* Ws_gate  = (const float*)d_in[17];
    const float* bs_gate  = (const float*)d_in[18];
    float* out = (float*)d_out;

    float* p_sn     = sym(g_sn);
    float* p_lna    = sym(g_lna);
    float* p_tg     = sym(g_tg);
    float* p_an     = sym(g_an);
    float* p_q      = sym(g_q);
    float* p_kt     = sym(g_kt);
    float* p_v      = sym(g_v);
    float* p_gate   = sym(g_gate);
    float* p_logits = sym(g_logits);
    float* p_go     = sym(g_go);

    // 1. layer norms
    ln_kernel<<<MM, 256>>>(s, a, gamma_s);

    dim3 g12x24(CA / BN, MM / BM, 1);           // N=768, M=1536
    // 2. t_g = s_n @ W_ada_g + b_ada_g
    gemm_kernel<0><<<g12x24, 256>>>(p_sn, CS, 0, W_ada_g, CA, 0, p_tg, CA, 0,
                                    MM, CA, CS, b_ada_g, nullptr, nullptr);
    // 3. a_n = sigmoid(t_g) * lna + s_n @ W_ada_o
    gemm_kernel<1><<<g12x24, 256>>>(p_sn, CS, 0, W_ada_o, CA, 0, p_an, CA, 0,
                                    MM, CA, CS, nullptr, p_tg, p_lna);
    // 4-7. projections
    gemm_kernel<2><<<g12x24, 256>>>(p_an, CA, 0, Wq, CA, 0, p_q, 0, 0,
                                    MM, CA, CA, bq, nullptr, nullptr);
    gemm_kernel<3><<<g12x24, 256>>>(p_an, CA, 0, Wk, CA, 0, p_kt, 0, 0,
                                    MM, CA, CA, nullptr, nullptr, nullptr);
    gemm_kernel<4><<<g12x24, 256>>>(p_an, CA, 0, Wv, CA, 0, p_v, 0, 0,
                                    MM, CA, CA, nullptr, nullptr, nullptr);
    gemm_kernel<0><<<g12x24, 256>>>(p_an, CA, 0, Wg, CA, 0, p_gate, CA, 0,
                                    MM, CA, CA, nullptr, nullptr, nullptr);
    // 8. pair bias -> g_logits (transposed store)
    pairbias_kernel<<<dim3(SS / 32, SS, BB), 256>>>(z, beta, Wb, gz, bz);
    // 9. logits += SCALE * q @ kT   (batched over b*h)
    gemm_kernel<5><<<dim3(SS / BN, SS / BM, BB * HH), 256>>>(
        p_q, HD, (long)SS * HD, p_kt, SS, (long)HD * SS,
        p_logits, SS, (long)SS * SS, SS, SS, HD, nullptr, nullptr, nullptr);
    // 10. softmax rows
    softmax_kernel<<<BB * HH * SS, 256>>>(p_logits);
    // 11. g_go = sigmoid(gate) * (attn @ v)   (batched)
    gemm_kernel<6><<<dim3(1, SS / BM, BB * HH), 256>>>(
        p_logits, SS, (long)SS * SS, p_v, HD, (long)SS * HD,
        p_go, 0, 0, SS, HD, SS, nullptr, p_gate, nullptr);
    // 12. out = g_go @ Wout
    gemm_kernel<0><<<g12x24, 256>>>(p_go, CA, 0, Wout, CA, 0, out, CA, 0,
                                    MM, CA, CA, nullptr, nullptr, nullptr);
    // 13. out *= sigmoid(s @ Ws_gate + bs_gate)
    gemm_kernel<8><<<g12x24, 256>>>(s, CS, 0, Ws_gate, CA, 0, out, CA, 0,
                                    MM, CA, CS, bs_gate, nullptr, nullptr);
}

// round 3
// speedup vs baseline: 1.0781x; 1.0781x over previous
#include <cuda_runtime.h>
#include <cuda_bf16.h>
#include <math.h>
#include <cstdint>

// Problem constants
#define BB   2
#define SS   768
#define CA   768
#define CS   384
#define CZ   128
#define HH   16
#define HD   48
#define MM   (BB*SS)          // 1536
#define EPS  1e-5f
#define SCALE (0.14433756729740643f)  // 1/sqrt(48)

// ---------------- scratch (device globals) ----------------------------------
__device__ float g_sn   [MM*CS];
__device__ float g_lna  [MM*CA];
__device__ float g_tg   [MM*CA];
__device__ float g_an   [MM*CA];
__device__ float g_q    [BB*HH*SS*HD];      // [b,h,s,d]
__device__ float g_k    [BB*HH*SS*HD];      // [b,h,s,d]
__device__ float g_v    [BB*HH*SS*HD];      // [b,h,s,d]
__device__ float g_gate [MM*CA];
__device__ float g_logits[BB*HH*SS*SS];
__device__ float g_go   [MM*CA];

// ---------------- helpers ----------------------------------------------------
__device__ __forceinline__ float sigmoidf_(float x) { return 1.0f / (1.0f + expf(-x)); }

__device__ __forceinline__ uint32_t f2tf32(float f) {
    uint32_t r;
    asm("cvt.rna.tf32.f32 %0, %1;" : "=r"(r) : "f"(f));
    return r;
}

__device__ __forceinline__ void mma_tf32(float* d, const uint32_t* a, const uint32_t* b) {
    asm volatile("mma.sync.aligned.m16n8k8.row.col.f32.tf32.tf32.f32 "
        "{%0,%1,%2,%3}, {%4,%5,%6,%7}, {%8,%9}, {%0,%1,%2,%3};"
        : "+f"(d[0]), "+f"(d[1]), "+f"(d[2]), "+f"(d[3])
        : "r"(a[0]), "r"(a[1]), "r"(a[2]), "r"(a[3]), "r"(b[0]), "r"(b[1]));
}

__device__ float2 blockReduceSum2(float a, float b) {
    __shared__ float sa[32], sb[32];
    int lane = threadIdx.x & 31, wid = threadIdx.x >> 5;
    #pragma unroll
    for (int o = 16; o; o >>= 1) {
        a += __shfl_xor_sync(0xffffffffu, a, o);
        b += __shfl_xor_sync(0xffffffffu, b, o);
    }
    if (lane == 0) { sa[wid] = a; sb[wid] = b; }
    __syncthreads();
    if (wid == 0) {
        int nw = (blockDim.x + 31) >> 5;
        a = (lane < nw) ? sa[lane] : 0.0f;
        b = (lane < nw) ? sb[lane] : 0.0f;
        #pragma unroll
        for (int o = 16; o; o >>= 1) {
            a += __shfl_xor_sync(0xffffffffu, a, o);
            b += __shfl_xor_sync(0xffffffffu, b, o);
        }
        if (lane == 0) { sa[0] = a; sb[0] = b; }
    }
    __syncthreads();
    float2 r = make_float2(sa[0], sb[0]);
    __syncthreads();
    return r;
}

// ---------------- LN kernel --------------------------------------------------
__global__ void ln_kernel(const float* __restrict__ s, const float* __restrict__ a,
                          const float* __restrict__ gamma_s) {
    int r = blockIdx.x;
    int tid = threadIdx.x;
    const float* srow = s + (long)r * CS;
    float sum = 0.f, sq = 0.f;
    for (int c = tid; c < CS; c += blockDim.x) { float v = srow[c]; sum += v; sq += v * v; }
    float2 t = blockReduceSum2(sum, sq);
    float mean = t.x / CS, var = t.y / CS - mean * mean;
    float rstd = rsqrtf(var + EPS);
    for (int c = tid; c < CS; c += blockDim.x)
        g_sn[(long)r * CS + c] = (srow[c] - mean) * rstd * gamma_s[c];

    const float* arow = a + (long)r * CA;
    sum = 0.f; sq = 0.f;
    for (int c = tid; c < CA; c += blockDim.x) { float v = arow[c]; sum += v; sq += v * v; }
    t = blockReduceSum2(sum, sq);
    mean = t.x / CA; var = t.y / CA - mean * mean;
    rstd = rsqrtf(var + EPS);
    for (int c = tid; c < CA; c += blockDim.x)
        g_lna[(long)r * CA + c] = (arow[c] - mean) * rstd;
}

// ---------------- tf32 mma.sync GEMM with fused epilogues --------------------
// C(M,N) = A(M,K) @ B(K,N). A is [M,K] row-major.
// BTRANS=true : B given as [K,N] row-major (transpose-load into [n][k] smem)
// BTRANS=false: B given as [N,K] row-major (direct K-major load)
// Tile: 128 x 64, BK=32 fp32, 8 warps each computing 32x32.
// MODE: 0 plain(+bias), 1 adaLN combine, 2 q scatter(+bias), 3/4 k/v scatter,
//       5 logits C=C+SCALE*acc, 6 AV*sigmoid(gate) scatter, 8 C*=sigmoid(acc+bias)
#define APITCH 36
#define BPITCH 36
#define A_WORDS (128 * APITCH)               // 4608
#define SMEM_TILES ((A_WORDS + 64 * BPITCH) * 4)   // 27648 B
#define SPITCH 68
#define SMEM_STAGE (128 * SPITCH * 4)        // 34816 B
#define SMEM_BYTES (SMEM_STAGE > SMEM_TILES ? SMEM_STAGE : SMEM_TILES)

template <int MODE, bool BTRANS>
__global__ void __launch_bounds__(256, 1)
gemm_mma(const float* __restrict__ A, int lda, long sA,
         const float* __restrict__ B, int ldb, long sB,
         float* __restrict__ C, int ldc, long sC,
         int M, int N, int K,
         const float* __restrict__ bias,
         const float* __restrict__ aux1) {
    extern __shared__ char smem[];
    uint32_t* As = (uint32_t*)smem;                 // [128][APITCH]
    uint32_t* Bs = (uint32_t*)smem + A_WORDS;       // [64][BPITCH]

    int tid = threadIdx.x, wid = tid >> 5, lane = tid & 31;
    int batch = blockIdx.z;
    A += (long)batch * sA;
    B += (long)batch * sB;
    int row0 = blockIdx.y * 128, col0 = blockIdx.x * 64;

    int wr = (wid & 3) * 32;       // warp row within tile
    int wc = (wid >> 2) * 32;      // warp col within tile
    int g4 = lane >> 2;            // 0..7
    int q4 = lane & 3;             // 0..3

    float acc[2][4][4];
    #pragma unroll
    for (int i = 0; i < 2; i++)
        #pragma unroll
        for (int j = 0; j < 4; j++)
            #pragma unroll
            for (int t = 0; t < 4; t++) acc[i][j][t] = 0.f;

    const int KT = (K + 31) / 32;
    for (int kt = 0; kt < KT; kt++) {
        int k0 = kt * 32;
        // ---- load A tile: 128 x 32
        #pragma unroll
        for (int rep = 0; rep < 4; rep++) {
            int lin = rep * 256 + tid;
            int r = lin >> 3, c4 = (lin & 7) * 4;
            float4 v = make_float4(0.f, 0.f, 0.f, 0.f);
            if (k0 + c4 + 4 <= K) v = *(const float4*)&A[(long)(row0 + r) * lda + k0 + c4];
            uint32_t* dst = &As[r * APITCH + c4];
            dst[0] = f2tf32(v.x); dst[1] = f2tf32(v.y);
            dst[2] = f2tf32(v.z); dst[3] = f2tf32(v.w);
        }
        // ---- load B tile: 64 (n) x 32 (k) stored as [n][k]
        if (BTRANS) {
            #pragma unroll
            for (int rep = 0; rep < 8; rep++) {
                int lin = rep * 256 + tid;        // 2048 = 32k x 64n
                int kk = lin >> 6, n = lin & 63;
                float v = 0.f;
                if (k0 + kk < K && col0 + n < N) v = B[(long)(k0 + kk) * ldb + col0 + n];
                Bs[n * BPITCH + kk] = f2tf32(v);
            }
        } else {
            #pragma unroll
            for (int rep = 0; rep < 2; rep++) {
                int lin = rep * 256 + tid;        // 512 = 64n x 8 float4
                int n = lin >> 3, c4 = (lin & 7) * 4;
                float4 v = make_float4(0.f, 0.f, 0.f, 0.f);
                if (col0 + n < N && k0 + c4 + 4 <= K)
                    v = *(const float4*)&B[(long)(col0 + n) * ldb + k0 + c4];
                uint32_t* dst = &Bs[n * BPITCH + c4];
                dst[0] = f2tf32(v.x); dst[1] = f2tf32(v.y);
                dst[2] = f2tf32(v.z); dst[3] = f2tf32(v.w);
            }
        }
        __syncthreads();

        // ---- compute: 4 k-chunks of 8
        #pragma unroll
        for (int kc = 0; kc < 4; kc++) {
            int kb = kc * 8 + q4;
            uint32_t af[2][4];
            #pragma unroll
            for (int mt = 0; mt < 2; mt++) {
                int r = wr + mt * 16 + g4;
                af[mt][0] = As[r * APITCH + kb];
                af[mt][1] = As[(r + 8) * APITCH + kb];
                af[mt][2] = As[r * APITCH + kb + 4];
                af[mt][3] = As[(r + 8) * APITCH + kb + 4];
            }
            uint32_t bf[4][2];
            #pragma unroll
            for (int nt = 0; nt < 4; nt++) {
                int c = wc + nt * 8 + g4;
                bf[nt][0] = Bs[c * BPITCH + kb];
                bf[nt][1] = Bs[c * BPITCH + kb + 4];
            }
            #pragma unroll
            for (int mt = 0; mt < 2; mt++)
                #pragma unroll
                for (int nt = 0; nt < 4; nt++)
                    mma_tf32(acc[mt][nt], af[mt], bf[nt]);
        }
        __syncthreads();
    }

    // ---- stage accumulators to SMEM (coalesced epilogue)
    float* st = (float*)smem;
    #pragma unroll
    for (int mt = 0; mt < 2; mt++) {
        #pragma unroll
        for (int nt = 0; nt < 4; nt++) {
            int rr = wr + mt * 16 + g4;
            int cc = wc + nt * 8 + 2 * q4;
            st[rr * SPITCH + cc]           = acc[mt][nt][0];
            st[rr * SPITCH + cc + 1]       = acc[mt][nt][1];
            st[(rr + 8) * SPITCH + cc]     = acc[mt][nt][2];
            st[(rr + 8) * SPITCH + cc + 1] = acc[mt][nt][3];
        }
    }
    __syncthreads();

    // ---- fused epilogue, coalesced stores
    #pragma unroll
    for (int rep = 0; rep < 32; rep++) {
        int idx = rep * 256 + tid;
        int r = idx >> 6, c = idx & 63;
        int m = row0 + r, n = col0 + c;
        if (n >= N) continue;
        float v = st[r * SPITCH + c];
        if (MODE == 0) {
            if (bias) v += bias[n];
            C[(long)batch * sC + (long)m * ldc + n] = v;
        } else if (MODE == 1) {
            float tg = aux1[(long)m * CA + n];
            C[(long)m * ldc + n] = sigmoidf_(tg) * g_lna[(long)m * CA + n] + v;
        } else if (MODE == 2) {
            v += bias[n];
            int b = m / SS, si = m % SS, h = n / HD, d = n % HD;
            C[(((long)(b * HH + h) * SS) + si) * HD + d] = v;
        } else if (MODE == 3 || MODE == 4) {
            int b = m / SS, si = m % SS, h = n / HD, d = n % HD;
            C[(((long)(b * HH + h) * SS) + si) * HD + d] = v;
        } else if (MODE == 5) {
            long off = (long)batch * sC + (long)m * ldc + n;
            C[off] = C[off] + SCALE * v;
        } else if (MODE == 6) {
            int b = batch / HH, h = batch % HH;
            long gi = ((long)(b * SS + m)) * CA + h * HD + n;
            C[gi] = v * sigmoidf_(aux1[gi]);
        } else if (MODE == 8) {
            long off = (long)m * ldc + n;
            C[off] = C[off] * sigmoidf_(v + bias[n]);
        }
    }
}

// ---------------- pair bias: LN(z)*gz+bz @ Wb + beta, transposed store ------
__global__ void __launch_bounds__(256)
pairbias_kernel(const float* __restrict__ z, const float* __restrict__ beta,
                const float* __restrict__ Wb, const float* __restrict__ gz,
                const float* __restrict__ bz) {
    __shared__ float WbT[HH * CZ];
    __shared__ float gzs[CZ], bzs[CZ];
    __shared__ float res[32][HH + 1];

    int tid = threadIdx.x;
    int lane = tid & 31, w = tid >> 5;
    for (int idx = tid; idx < CZ * HH; idx += 256) {
        int c = idx >> 4, h = idx & 15;
        WbT[h * CZ + c] = Wb[idx];
    }
    for (int idx = tid; idx < CZ; idx += 256) { gzs[idx] = gz[idx]; bzs[idx] = bz[idx]; }
    __syncthreads();

    int b = blockIdx.z, q = blockIdx.y, p0 = blockIdx.x * 32;

    for (int rr = 0; rr < 4; rr++) {
        int pl = w * 4 + rr;
        int p = p0 + pl;
        const float* zr = z + (((long)(b * SS + p) * SS) + q) * CZ;
        float v[4];
        float sum = 0.f, sq = 0.f;
        #pragma unroll
        for (int t = 0; t < 4; t++) {
            v[t] = zr[lane + 32 * t];
            sum += v[t]; sq += v[t] * v[t];
        }
        #pragma unroll
        for (int o = 16; o; o >>= 1) {
            sum += __shfl_xor_sync(0xffffffffu, sum, o);
            sq  += __shfl_xor_sync(0xffffffffu, sq,  o);
        }
        float mean = sum * (1.0f / CZ);
        float var  = sq * (1.0f / CZ) - mean * mean;
        float rstd = rsqrtf(var + EPS);
        float zn[4];
        #pragma unroll
        for (int t = 0; t < 4; t++) {
            int c = lane + 32 * t;
            zn[t] = (v[t] - mean) * rstd * gzs[c] + bzs[c];
        }
        float ph[HH];
        #pragma unroll
        for (int h = 0; h < HH; h++) {
            float acc = 0.f;
            #pragma unroll
            for (int t = 0; t < 4; t++)
                acc += zn[t] * WbT[h * CZ + lane + 32 * t];
            ph[h] = acc;
        }
        #pragma unroll
        for (int o = 16; o; o >>= 1) {
            #pragma unroll
            for (int h = 0; h < HH; h++)
                ph[h] += __shfl_xor_sync(0xffffffffu, ph[h], o);
        }
        if (lane < HH) {
            float bet = beta[(((long)(b * SS + p) * SS) + q) * HH + lane];
            res[pl][lane] = ph[lane] + bet;
        }
    }
    __syncthreads();
    for (int idx = tid; idx < 32 * HH; idx += 256) {
        int h = idx >> 5, pl = idx & 31;
        g_logits[(((long)(b * HH + h) * SS) + q) * SS + p0 + pl] = res[pl][h];
    }
}

// ---------------- softmax ----------------------------------------------------
__global__ void __launch_bounds__(256)
softmax_kernel(float* __restrict__ logits) {
    long r = blockIdx.x;
    float* row = logits + r * SS;
    __shared__ float buf[SS];
    __shared__ float red[32];
    int tid = threadIdx.x, lane = tid & 31, wid = tid >> 5;

    float mx = -3.4e38f;
    for (int c = tid; c < SS; c += blockDim.x) {
        float v = row[c];
        buf[c] = v;
        mx = fmaxf(mx, v);
    }
    #pragma unroll
    for (int o = 16; o; o >>= 1) mx = fmaxf(mx, __shfl_xor_sync(0xffffffffu, mx, o));
    if (lane == 0) red[wid] = mx;
    __syncthreads();
    if (wid == 0) {
        mx = (lane < 8) ? red[lane] : -3.4e38f;
        #pragma unroll
        for (int o = 16; o; o >>= 1) mx = fmaxf(mx, __shfl_xor_sync(0xffffffffu, mx, o));
        if (lane == 0) red[0] = mx;
    }
    __syncthreads();
    mx = red[0];
    __syncthreads();

    float sum = 0.f;
    for (int c = tid; c < SS; c += blockDim.x) {
        float e = __expf(buf[c] - mx);
        buf[c] = e;
        sum += e;
    }
    #pragma unroll
    for (int o = 16; o; o >>= 1) sum += __shfl_xor_sync(0xffffffffu, sum, o);
    if (lane == 0) red[wid] = sum;
    __syncthreads();
    if (wid == 0) {
        sum = (lane < 8) ? red[lane] : 0.f;
        #pragma unroll
        for (int o = 16; o; o >>= 1) sum += __shfl_xor_sync(0xffffffffu, sum, o);
        if (lane == 0) red[0] = sum;
    }
    __syncthreads();
    float inv = 1.0f / red[0];
    for (int c = tid; c < SS; c += blockDim.x)
        row[c] = buf[c] * inv;
}

// ---------------- host side --------------------------------------------------
static float* sym(const void* symbol) {
    void* p = nullptr;
    cudaGetSymbolAddress(&p, symbol);
    return (float*)p;
}

extern "C" void kernel_launch(void* const* d_in, const int* in_sizes, int n_in,
                              void* d_out, int out_size) {
    const float* a        = (const float*)d_in[0];
    const float* s        = (const float*)d_in[1];
    const float* z        = (const float*)d_in[2];
    const float* beta     = (const float*)d_in[3];
    const float* gamma_s  = (const float*)d_in[4];
    const float* W_ada_g  = (const float*)d_in[5];
    const float* b_ada_g  = (const float*)d_in[6];
    const float* W_ada_o  = (const float*)d_in[7];
    const float* Wq       = (const float*)d_in[8];
    const float* bq       = (const float*)d_in[9];
    const float* Wk       = (const float*)d_in[10];
    const float* Wv       = (const float*)d_in[11];
    const float* Wb       = (const float*)d_in[12];
    const float* gz       = (const float*)d_in[13];
    const float* bz       = (const float*)d_in[14];
    const float* Wg       = (const float*)d_in[15];
    const float* Wout     = (const float*)d_in[16];
    const float* Ws_gate  = (const float*)d_in[17];
    const float* bs_gate  = (const float*)d_in[18];
    float* out = (float*)d_out;

    float* p_sn     = sym(g_sn);
    float* p_tg     = sym(g_tg);
    float* p_an     = sym(g_an);
    float* p_q      = sym(g_q);
    float* p_k      = sym(g_k);
    float* p_v      = sym(g_v);
    float* p_gate   = sym(g_gate);
    float* p_logits = sym(g_logits);
    float* p_go     = sym(g_go);

    cudaFuncSetAttribute(gemm_mma<0, true>,  cudaFuncAttributeMaxDynamicSharedMemorySize, SMEM_BYTES);
    cudaFuncSetAttribute(gemm_mma<1, true>,  cudaFuncAttributeMaxDynamicSharedMemorySize, SMEM_BYTES);
    cudaFuncSetAttribute(gemm_mma<2, true>,  cudaFuncAttributeMaxDynamicSharedMemorySize, SMEM_BYTES);
    cudaFuncSetAttribute(gemm_mma<3, true>,  cudaFuncAttributeMaxDynamicSharedMemorySize, SMEM_BYTES);
    cudaFuncSetAttribute(gemm_mma<4, true>,  cudaFuncAttributeMaxDynamicSharedMemorySize, SMEM_BYTES);
    cudaFuncSetAttribute(gemm_mma<5, false>, cudaFuncAttributeMaxDynamicSharedMemorySize, SMEM_BYTES);
    cudaFuncSetAttribute(gemm_mma<6, true>,  cudaFuncAttributeMaxDynamicSharedMemorySize, SMEM_BYTES);
    cudaFuncSetAttribute(gemm_mma<8, true>,  cudaFuncAttributeMaxDynamicSharedMemorySize, SMEM_BYTES);

    // 1. layer norms
    ln_kernel<<<MM, 256>>>(s, a, gamma_s);

    dim3 gP(CA / 64, MM / 128, 1);   // (12, 12)
    // 2. t_g = s_n @ W_ada_g + b_ada_g
    gemm_mma<0, true><<<gP, 256, SMEM_BYTES>>>(p_sn, CS, 0, W_ada_g, CA, 0, p_tg, CA, 0,
                                               MM, CA, CS, b_ada_g, nullptr);
    // 3. a_n = sigmoid(t_g)*lna + s_n @ W_ada_o
    gemm_mma<1, true><<<gP, 256, SMEM_BYTES>>>(p_sn, CS, 0, W_ada_o, CA, 0, p_an, CA, 0,
                                               MM, CA, CS, nullptr, p_tg);
    // 4-7. projections (scatter to [b,h,s,d])
    gemm_mma<2, true><<<gP, 256, SMEM_BYTES>>>(p_an, CA, 0, Wq, CA, 0, p_q, 0, 0,
                                               MM, CA, CA, bq, nullptr);
    gemm_mma<3, true><<<gP, 256, SMEM_BYTES>>>(p_an, CA, 0, Wk, CA, 0, p_k, 0, 0,
                                               MM, CA, CA, nullptr, nullptr);
    gemm_mma<4, true><<<gP, 256, SMEM_BYTES>>>(p_an, CA, 0, Wv, CA, 0, p_v, 0, 0,
                                               MM, CA, CA, nullptr, nullptr);
    gemm_mma<0, true><<<gP, 256, SMEM_BYTES>>>(p_an, CA, 0, Wg, CA, 0, p_gate, CA, 0,
                                               MM, CA, CA, nullptr, nullptr);
    // 8. pair bias -> g_logits (transposed store)
    pairbias_kernel<<<dim3(SS / 32, SS, BB), 256>>>(z, beta, Wb, gz, bz);
    // 9. logits += SCALE * q @ k^T  (batched over b*h; k is [N,K] direct)
    gemm_mma<5, false><<<dim3(SS / 64, SS / 128, BB * HH), 256, SMEM_BYTES>>>(
        p_q, HD, (long)SS * HD, p_k, HD, (long)SS * HD,
        p_logits, SS, (long)SS * SS, SS, SS, HD, nullptr, nullptr);
    // 10. softmax rows
    softmax_kernel<<<BB * HH * SS, 256>>>(p_logits);
    // 11. g_go = sigmoid(gate) * (attn @ v)  (batched; v is [K,N] -> transpose-load)
    gemm_mma<6, true><<<dim3(1, SS / 128, BB * HH), 256, SMEM_BYTES>>>(
        p_logits, SS, (long)SS * SS, p_v, HD, (long)SS * HD,
        p_go, 0, 0, SS, HD, SS, nullptr, p_gate);
    // 12. out = g_go @ Wout
    gemm_mma<0, true><<<gP, 256, SMEM_BYTES>>>(p_go, CA, 0, Wout, CA, 0, out, CA, 0,
                                               MM, CA, CA, nullptr, nullptr);
    // 13. out *= sigmoid(s @ Ws_gate + bs_gate)
    gemm_mma<8, true><<<gP, 256, SMEM_BYTES>>>(s, CS, 0, Ws_gate, CA, 0, out, CA, 0,
                                               MM, CA, CS, bs_gate, nullptr);
}

// round 4
// speedup vs baseline: 1.8080x; 1.6770x over previous
#include <cuda_runtime.h>
#include <cuda_bf16.h>
#include <math.h>
#include <cstdint>

// Problem constants
#define BB   2
#define SS   768
#define CA   768
#define CS   384
#define CZ   128
#define HH   16
#define HD   48
#define MM   (BB*SS)          // 1536
#define EPS  1e-5f
#define SCALE (0.14433756729740643f)  // 1/sqrt(48)

// ---------------- scratch (device globals) ----------------------------------
__device__ float g_sn   [MM*CS];
__device__ float g_lna  [MM*CA];
__device__ float g_tg   [MM*CA];
__device__ float g_an   [MM*CA];
__device__ float g_q    [BB*HH*SS*HD];      // [b,h,s,d]
__device__ float g_k    [BB*HH*SS*HD];      // [b,h,s,d]
__device__ float g_v    [BB*HH*SS*HD];      // [b,h,s,d]
__device__ float g_gate [MM*CA];
__device__ float g_bias [BB*HH*SS*SS];      // pair bias, [b,h,i,j]
__device__ float g_go   [MM*CA];

// ---------------- helpers ----------------------------------------------------
__device__ __forceinline__ float sigmoidf_(float x) { return 1.0f / (1.0f + expf(-x)); }

__device__ __forceinline__ uint32_t f2tf32(float f) {
    uint32_t r;
    asm("cvt.rna.tf32.f32 %0, %1;" : "=r"(r) : "f"(f));
    return r;
}

__device__ __forceinline__ void mma_tf32(float* d, const uint32_t* a, const uint32_t* b) {
    asm volatile("mma.sync.aligned.m16n8k8.row.col.f32.tf32.tf32.f32 "
        "{%0,%1,%2,%3}, {%4,%5,%6,%7}, {%8,%9}, {%0,%1,%2,%3};"
        : "+f"(d[0]), "+f"(d[1]), "+f"(d[2]), "+f"(d[3])
        : "r"(a[0]), "r"(a[1]), "r"(a[2]), "r"(a[3]), "r"(b[0]), "r"(b[1]));
}

__device__ float2 blockReduceSum2(float a, float b) {
    __shared__ float sa[32], sb[32];
    int lane = threadIdx.x & 31, wid = threadIdx.x >> 5;
    #pragma unroll
    for (int o = 16; o; o >>= 1) {
        a += __shfl_xor_sync(0xffffffffu, a, o);
        b += __shfl_xor_sync(0xffffffffu, b, o);
    }
    if (lane == 0) { sa[wid] = a; sb[wid] = b; }
    __syncthreads();
    if (wid == 0) {
        int nw = (blockDim.x + 31) >> 5;
        a = (lane < nw) ? sa[lane] : 0.0f;
        b = (lane < nw) ? sb[lane] : 0.0f;
        #pragma unroll
        for (int o = 16; o; o >>= 1) {
            a += __shfl_xor_sync(0xffffffffu, a, o);
            b += __shfl_xor_sync(0xffffffffu, b, o);
        }
        if (lane == 0) { sa[0] = a; sb[0] = b; }
    }
    __syncthreads();
    float2 r = make_float2(sa[0], sb[0]);
    __syncthreads();
    return r;
}

// ---------------- LN kernel --------------------------------------------------
__global__ void ln_kernel(const float* __restrict__ s, const float* __restrict__ a,
                          const float* __restrict__ gamma_s) {
    int r = blockIdx.x;
    int tid = threadIdx.x;
    const float* srow = s + (long)r * CS;
    float sum = 0.f, sq = 0.f;
    for (int c = tid; c < CS; c += blockDim.x) { float v = srow[c]; sum += v; sq += v * v; }
    float2 t = blockReduceSum2(sum, sq);
    float mean = t.x / CS, var = t.y / CS - mean * mean;
    float rstd = rsqrtf(var + EPS);
    for (int c = tid; c < CS; c += blockDim.x)
        g_sn[(long)r * CS + c] = (srow[c] - mean) * rstd * gamma_s[c];

    const float* arow = a + (long)r * CA;
    sum = 0.f; sq = 0.f;
    for (int c = tid; c < CA; c += blockDim.x) { float v = arow[c]; sum += v; sq += v * v; }
    t = blockReduceSum2(sum, sq);
    mean = t.x / CA; var = t.y / CA - mean * mean;
    rstd = rsqrtf(var + EPS);
    for (int c = tid; c < CA; c += blockDim.x)
        g_lna[(long)r * CA + c] = (arow[c] - mean) * rstd;
}

// ---------------- tf32 mma.sync GEMM with fused epilogues --------------------
#define APITCH 36
#define BPITCH 36
#define A_WORDS (128 * APITCH)               // 4608
#define SMEM_TILES ((A_WORDS + 64 * BPITCH) * 4)
#define SPITCH 68
#define SMEM_STAGE (128 * SPITCH * 4)
#define SMEM_BYTES (SMEM_STAGE > SMEM_TILES ? SMEM_STAGE : SMEM_TILES)

template <int MODE, bool BTRANS>
__global__ void __launch_bounds__(256, 1)
gemm_mma(const float* __restrict__ A, int lda, long sA,
         const float* __restrict__ B, int ldb, long sB,
         float* __restrict__ C, int ldc, long sC,
         int M, int N, int K,
         const float* __restrict__ bias,
         const float* __restrict__ aux1) {
    extern __shared__ char smem[];
    uint32_t* As = (uint32_t*)smem;
    uint32_t* Bs = (uint32_t*)smem + A_WORDS;

    int tid = threadIdx.x, wid = tid >> 5, lane = tid & 31;
    int batch = blockIdx.z;
    A += (long)batch * sA;
    B += (long)batch * sB;
    int row0 = blockIdx.y * 128, col0 = blockIdx.x * 64;

    int wr = (wid & 3) * 32;
    int wc = (wid >> 2) * 32;
    int g4 = lane >> 2;
    int q4 = lane & 3;

    float acc[2][4][4];
    #pragma unroll
    for (int i = 0; i < 2; i++)
        #pragma unroll
        for (int j = 0; j < 4; j++)
            #pragma unroll
            for (int t = 0; t < 4; t++) acc[i][j][t] = 0.f;

    const int KT = (K + 31) / 32;
    for (int kt = 0; kt < KT; kt++) {
        int k0 = kt * 32;
        #pragma unroll
        for (int rep = 0; rep < 4; rep++) {
            int lin = rep * 256 + tid;
            int r = lin >> 3, c4 = (lin & 7) * 4;
            float4 v = make_float4(0.f, 0.f, 0.f, 0.f);
            if (k0 + c4 + 4 <= K) v = *(const float4*)&A[(long)(row0 + r) * lda + k0 + c4];
            uint32_t* dst = &As[r * APITCH + c4];
            dst[0] = f2tf32(v.x); dst[1] = f2tf32(v.y);
            dst[2] = f2tf32(v.z); dst[3] = f2tf32(v.w);
        }
        if (BTRANS) {
            #pragma unroll
            for (int rep = 0; rep < 8; rep++) {
                int lin = rep * 256 + tid;
                int kk = lin >> 6, n = lin & 63;
                float v = 0.f;
                if (k0 + kk < K && col0 + n < N) v = B[(long)(k0 + kk) * ldb + col0 + n];
                Bs[n * BPITCH + kk] = f2tf32(v);
            }
        } else {
            #pragma unroll
            for (int rep = 0; rep < 2; rep++) {
                int lin = rep * 256 + tid;
                int n = lin >> 3, c4 = (lin & 7) * 4;
                float4 v = make_float4(0.f, 0.f, 0.f, 0.f);
                if (col0 + n < N && k0 + c4 + 4 <= K)
                    v = *(const float4*)&B[(long)(col0 + n) * ldb + k0 + c4];
                uint32_t* dst = &Bs[n * BPITCH + c4];
                dst[0] = f2tf32(v.x); dst[1] = f2tf32(v.y);
                dst[2] = f2tf32(v.z); dst[3] = f2tf32(v.w);
            }
        }
        __syncthreads();

        #pragma unroll
        for (int kc = 0; kc < 4; kc++) {
            int kb = kc * 8 + q4;
            uint32_t af[2][4];
            #pragma unroll
            for (int mt = 0; mt < 2; mt++) {
                int r = wr + mt * 16 + g4;
                af[mt][0] = As[r * APITCH + kb];
                af[mt][1] = As[(r + 8) * APITCH + kb];
                af[mt][2] = As[r * APITCH + kb + 4];
                af[mt][3] = As[(r + 8) * APITCH + kb + 4];
            }
            uint32_t bf[4][2];
            #pragma unroll
            for (int nt = 0; nt < 4; nt++) {
                int c = wc + nt * 8 + g4;
                bf[nt][0] = Bs[c * BPITCH + kb];
                bf[nt][1] = Bs[c * BPITCH + kb + 4];
            }
            #pragma unroll
            for (int mt = 0; mt < 2; mt++)
                #pragma unroll
                for (int nt = 0; nt < 4; nt++)
                    mma_tf32(acc[mt][nt], af[mt], bf[nt]);
        }
        __syncthreads();
    }

    float* st = (float*)smem;
    #pragma unroll
    for (int mt = 0; mt < 2; mt++) {
        #pragma unroll
        for (int nt = 0; nt < 4; nt++) {
            int rr = wr + mt * 16 + g4;
            int cc = wc + nt * 8 + 2 * q4;
            st[rr * SPITCH + cc]           = acc[mt][nt][0];
            st[rr * SPITCH + cc + 1]       = acc[mt][nt][1];
            st[(rr + 8) * SPITCH + cc]     = acc[mt][nt][2];
            st[(rr + 8) * SPITCH + cc + 1] = acc[mt][nt][3];
        }
    }
    __syncthreads();

    #pragma unroll
    for (int rep = 0; rep < 32; rep++) {
        int idx = rep * 256 + tid;
        int r = idx >> 6, c = idx & 63;
        int m = row0 + r, n = col0 + c;
        if (n >= N) continue;
        float v = st[r * SPITCH + c];
        if (MODE == 0) {
            if (bias) v += bias[n];
            C[(long)batch * sC + (long)m * ldc + n] = v;
        } else if (MODE == 1) {
            float tg = aux1[(long)m * CA + n];
            C[(long)m * ldc + n] = sigmoidf_(tg) * g_lna[(long)m * CA + n] + v;
        } else if (MODE == 2) {
            v += bias[n];
            int b = m / SS, si = m % SS, h = n / HD, d = n % HD;
            C[(((long)(b * HH + h) * SS) + si) * HD + d] = v;
        } else if (MODE == 3 || MODE == 4) {
            int b = m / SS, si = m % SS, h = n / HD, d = n % HD;
            C[(((long)(b * HH + h) * SS) + si) * HD + d] = v;
        } else if (MODE == 8) {
            long off = (long)m * ldc + n;
            C[off] = C[off] * sigmoidf_(v + bias[n]);
        }
    }
}

// ---------------- pair bias v2: LN(z)*gz+bz @ Wb + beta via mma.sync --------
// Block: 256 thr handles (b, q, 64 p-rows). Writes g_bias[b,h,q,p].
#define ZP 132
__global__ void __launch_bounds__(256, 1)
pairbias2_kernel(const float* __restrict__ z, const float* __restrict__ beta,
                 const float* __restrict__ Wb, const float* __restrict__ gz,
                 const float* __restrict__ bz) {
    __shared__ uint32_t Zs[64 * ZP];        // 64 p-rows x 128 k (tf32)
    __shared__ uint32_t Wbs[16 * ZP];       // 16 h x 128 k (tf32)
    __shared__ float res[64 * 17];
    __shared__ float gzs[CZ], bzs[CZ];

    int tid = threadIdx.x, wid = tid >> 5, lane = tid & 31;
    int g4 = lane >> 2, q4 = lane & 3;
    int b = blockIdx.z, q = blockIdx.y, p0 = blockIdx.x * 64;

    // stage Wb (transposed) + gz/bz
    for (int idx = tid; idx < CZ * HH; idx += 256) {
        int k = idx >> 4, n = idx & 15;
        Wbs[n * ZP + k] = f2tf32(Wb[idx]);
    }
    for (int idx = tid; idx < CZ; idx += 256) { gzs[idx] = gz[idx]; bzs[idx] = bz[idx]; }
    __syncthreads();

    // LN of 64 z-rows -> Zs (tf32). Warp w handles rows 8w..8w+7.
    #pragma unroll
    for (int rr = 0; rr < 8; rr++) {
        int pl = wid * 8 + rr;
        const float* zr = z + (((long)(b * SS + p0 + pl) * SS) + q) * CZ;
        float v[4];
        float sum = 0.f, sq = 0.f;
        #pragma unroll
        for (int t = 0; t < 4; t++) {
            v[t] = zr[lane + 32 * t];
            sum += v[t]; sq += v[t] * v[t];
        }
        #pragma unroll
        for (int o = 16; o; o >>= 1) {
            sum += __shfl_xor_sync(0xffffffffu, sum, o);
            sq  += __shfl_xor_sync(0xffffffffu, sq,  o);
        }
        float mean = sum * (1.0f / CZ);
        float var  = sq * (1.0f / CZ) - mean * mean;
        float rstd = rsqrtf(var + EPS);
        #pragma unroll
        for (int t = 0; t < 4; t++) {
            int c = lane + 32 * t;
            Zs[pl * ZP + c] = f2tf32((v[t] - mean) * rstd * gzs[c] + bzs[c]);
        }
    }
    __syncthreads();

    // mma: [64 x 128] @ [128 x 16] by warps 0..3 (16 rows each)
    if (wid < 4) {
        int wr = wid * 16;
        float acc[2][4];
        #pragma unroll
        for (int nt = 0; nt < 2; nt++)
            #pragma unroll
            for (int t = 0; t < 4; t++) acc[nt][t] = 0.f;
        #pragma unroll
        for (int kc = 0; kc < 16; kc++) {
            int kb = kc * 8 + q4;
            uint32_t af[4];
            af[0] = Zs[(wr + g4) * ZP + kb];
            af[1] = Zs[(wr + g4 + 8) * ZP + kb];
            af[2] = Zs[(wr + g4) * ZP + kb + 4];
            af[3] = Zs[(wr + g4 + 8) * ZP + kb + 4];
            #pragma unroll
            for (int nt = 0; nt < 2; nt++) {
                uint32_t bf[2];
                bf[0] = Wbs[(nt * 8 + g4) * ZP + kb];
                bf[1] = Wbs[(nt * 8 + g4) * ZP + kb + 4];
                mma_tf32(acc[nt], af, bf);
            }
        }
        // add beta, stage to res
        #pragma unroll
        for (int nt = 0; nt < 2; nt++) {
            #pragma unroll
            for (int t = 0; t < 4; t++) {
                int row = wr + g4 + ((t >= 2) ? 8 : 0);
                int h = nt * 8 + 2 * q4 + (t & 1);
                float bet = beta[(((long)(b * SS + p0 + row) * SS) + q) * HH + h];
                res[row * 17 + h] = acc[nt][t] + bet;
            }
        }
    }
    __syncthreads();

    // coalesced store: g_bias[b,h,q,p]
    #pragma unroll
    for (int rep = 0; rep < 4; rep++) {
        int idx = rep * 256 + tid;
        int h = idx >> 6, p = idx & 63;
        g_bias[(((long)(b * HH + h) * SS) + q) * SS + p0 + p] = res[p * 17 + h];
    }
}

// ---------------- fused attention: softmax(scale*QK^T + bias) @ V, gated ----
// grid (SS/128, BB*HH), 256 thr. Q-tile 128, j-tiles 64.
#define QP 52
#define KP 52
#define VP 68
#define PP 68
#define AT_Q 0
#define AT_K (128 * QP)
#define AT_V (AT_K + 64 * KP)
#define AT_P (AT_V + 48 * VP)
#define AT_WORDS (AT_P + 128 * PP)
#define ATT_SMEM (AT_WORDS * 4)

__global__ void __launch_bounds__(256, 1)
attn_kernel(const float* __restrict__ qg, const float* __restrict__ kg,
            const float* __restrict__ vg, const float* __restrict__ biasg,
            const float* __restrict__ gateg, float* __restrict__ outg) {
    extern __shared__ char smem[];
    uint32_t* Qs = (uint32_t*)smem;
    uint32_t* Ks = Qs + AT_K;
    uint32_t* Vs = Qs + AT_V;
    float*    Bf = (float*)(Qs + AT_P);     // bias staging, then P (tf32)
    uint32_t* Ps = (uint32_t*)Bf;

    int tid = threadIdx.x, wid = tid >> 5, lane = tid & 31;
    int g4 = lane >> 2, q4 = lane & 3;
    int bh = blockIdx.y;
    int b = bh >> 4, h = bh & 15;
    int i0 = blockIdx.x * 128;
    const float* qb = qg + ((long)bh * SS + i0) * HD;
    const float* kb_ = kg + (long)bh * SS * HD;
    const float* vb = vg + (long)bh * SS * HD;
    const float* biasb = biasg + ((long)bh * SS + i0) * SS;

    // load Q tile (128 x 48) as tf32
    #pragma unroll
    for (int rep = 0; rep < 6; rep++) {
        int idx = rep * 256 + tid;
        int r = idx / 12, c4 = (idx % 12) * 4;
        float4 v = *(const float4*)&qb[(long)r * HD + c4];
        uint32_t* d = &Qs[r * QP + c4];
        d[0] = f2tf32(v.x); d[1] = f2tf32(v.y); d[2] = f2tf32(v.z); d[3] = f2tf32(v.w);
    }

    int wr = wid * 16;
    float accO[6][4];
    #pragma unroll
    for (int n = 0; n < 6; n++)
        #pragma unroll
        for (int t = 0; t < 4; t++) accO[n][t] = 0.f;
    float mrow[2] = {-1e30f, -1e30f};
    float lrow[2] = {0.f, 0.f};

    for (int j = 0; j < 12; j++) {
        __syncthreads();
        // K tile 64x48
        #pragma unroll
        for (int rep = 0; rep < 3; rep++) {
            int idx = rep * 256 + tid;
            int r = idx / 12, c4 = (idx % 12) * 4;
            float4 v = *(const float4*)&kb_[(long)(j * 64 + r) * HD + c4];
            uint32_t* d = &Ks[r * KP + c4];
            d[0] = f2tf32(v.x); d[1] = f2tf32(v.y); d[2] = f2tf32(v.z); d[3] = f2tf32(v.w);
        }
        // V tile transposed: Vs[d][r]
        #pragma unroll
        for (int rep = 0; rep < 12; rep++) {
            int idx = rep * 256 + tid;
            int r = idx / 48, d = idx % 48;
            Vs[d * VP + r] = f2tf32(vb[(long)(j * 64 + r) * HD + d]);
        }
        // bias tile 128x64 (fp32)
        #pragma unroll
        for (int rep = 0; rep < 32; rep++) {
            int idx = rep * 256 + tid;
            int r = idx >> 6, c = idx & 63;
            Bf[r * PP + c] = biasb[(long)r * SS + j * 64 + c];
        }
        __syncthreads();

        // S = Q @ K^T
        float S[8][4];
        #pragma unroll
        for (int nt = 0; nt < 8; nt++)
            #pragma unroll
            for (int t = 0; t < 4; t++) S[nt][t] = 0.f;
        #pragma unroll
        for (int kc = 0; kc < 6; kc++) {
            int kbx = kc * 8 + q4;
            uint32_t af[4];
            af[0] = Qs[(wr + g4) * QP + kbx];
            af[1] = Qs[(wr + g4 + 8) * QP + kbx];
            af[2] = Qs[(wr + g4) * QP + kbx + 4];
            af[3] = Qs[(wr + g4 + 8) * QP + kbx + 4];
            #pragma unroll
            for (int nt = 0; nt < 8; nt++) {
                uint32_t bf2[2];
                bf2[0] = Ks[(nt * 8 + g4) * KP + kbx];
                bf2[1] = Ks[(nt * 8 + g4) * KP + kbx + 4];
                mma_tf32(S[nt], af, bf2);
            }
        }
        // scale + bias, rowmax
        int r0 = wr + g4, r1 = r0 + 8;
        float mn0 = mrow[0], mn1 = mrow[1];
        #pragma unroll
        for (int nt = 0; nt < 8; nt++) {
            #pragma unroll
            for (int t = 0; t < 4; t++) {
                int rr = (t >= 2) ? r1 : r0;
                int cc = nt * 8 + 2 * q4 + (t & 1);
                float val = S[nt][t] * SCALE + Bf[rr * PP + cc];
                S[nt][t] = val;
                if (t < 2) mn0 = fmaxf(mn0, val); else mn1 = fmaxf(mn1, val);
            }
        }
        mn0 = fmaxf(mn0, __shfl_xor_sync(0xffffffffu, mn0, 1));
        mn0 = fmaxf(mn0, __shfl_xor_sync(0xffffffffu, mn0, 2));
        mn1 = fmaxf(mn1, __shfl_xor_sync(0xffffffffu, mn1, 1));
        mn1 = fmaxf(mn1, __shfl_xor_sync(0xffffffffu, mn1, 2));
        float al0 = __expf(mrow[0] - mn0);
        float al1 = __expf(mrow[1] - mn1);
        mrow[0] = mn0; mrow[1] = mn1;
        float s0 = 0.f, s1 = 0.f;
        #pragma unroll
        for (int nt = 0; nt < 8; nt++) {
            #pragma unroll
            for (int t = 0; t < 4; t++) {
                float p = __expf(S[nt][t] - ((t >= 2) ? mn1 : mn0));
                S[nt][t] = p;
                if (t < 2) s0 += p; else s1 += p;
                int rr = (t >= 2) ? r1 : r0;
                int cc = nt * 8 + 2 * q4 + (t & 1);
                Ps[rr * PP + cc] = f2tf32(p);
            }
        }
        s0 += __shfl_xor_sync(0xffffffffu, s0, 1);
        s0 += __shfl_xor_sync(0xffffffffu, s0, 2);
        s1 += __shfl_xor_sync(0xffffffffu, s1, 1);
        s1 += __shfl_xor_sync(0xffffffffu, s1, 2);
        lrow[0] = lrow[0] * al0 + s0;
        lrow[1] = lrow[1] * al1 + s1;
        #pragma unroll
        for (int n = 0; n < 6; n++) {
            accO[n][0] *= al0; accO[n][1] *= al0;
            accO[n][2] *= al1; accO[n][3] *= al1;
        }
        __syncwarp();
        // O += P @ V
        #pragma unroll
        for (int kc = 0; kc < 8; kc++) {
            int kbx = kc * 8 + q4;
            uint32_t af[4];
            af[0] = Ps[(wr + g4) * PP + kbx];
            af[1] = Ps[(wr + g4 + 8) * PP + kbx];
            af[2] = Ps[(wr + g4) * PP + kbx + 4];
            af[3] = Ps[(wr + g4 + 8) * PP + kbx + 4];
            #pragma unroll
            for (int n = 0; n < 6; n++) {
                uint32_t bf2[2];
                bf2[0] = Vs[(n * 8 + g4) * VP + kbx];
                bf2[1] = Vs[(n * 8 + g4) * VP + kbx + 4];
                mma_tf32(accO[n], af, bf2);
            }
        }
    }

    // epilogue: O/l * sigmoid(gate) -> g_go (natural layout)
    float inv0 = 1.0f / lrow[0], inv1 = 1.0f / lrow[1];
    #pragma unroll
    for (int n = 0; n < 6; n++) {
        #pragma unroll
        for (int t = 0; t < 4; t++) {
            int r = wr + g4 + ((t >= 2) ? 8 : 0);
            int c = n * 8 + 2 * q4 + (t & 1);
            long gi = ((long)(b * SS + i0 + r)) * CA + h * HD + c;
            float o = accO[n][t] * ((t >= 2) ? inv1 : inv0);
            outg[gi] = o * sigmoidf_(gateg[gi]);
        }
    }
}

// ---------------- host side --------------------------------------------------
static float* sym(const void* symbol) {
    void* p = nullptr;
    cudaGetSymbolAddress(&p, symbol);
    return (float*)p;
}

extern "C" void kernel_launch(void* const* d_in, const int* in_sizes, int n_in,
                              void* d_out, int out_size) {
    const float* a        = (const float*)d_in[0];
    const float* s        = (const float*)d_in[1];
    const float* z        = (const float*)d_in[2];
    const float* beta     = (const float*)d_in[3];
    const float* gamma_s  = (const float*)d_in[4];
    const float* W_ada_g  = (const float*)d_in[5];
    const float* b_ada_g  = (const float*)d_in[6];
    const float* W_ada_o  = (const float*)d_in[7];
    const float* Wq       = (const float*)d_in[8];
    const float* bq       = (const float*)d_in[9];
    const float* Wk       = (const float*)d_in[10];
    const float* Wv       = (const float*)d_in[11];
    const float* Wb       = (const float*)d_in[12];
    const float* gz       = (const float*)d_in[13];
    const float* bz       = (const float*)d_in[14];
    const float* Wg       = (const float*)d_in[15];
    const float* Wout     = (const float*)d_in[16];
    const float* Ws_gate  = (const float*)d_in[17];
    const float* bs_gate  = (const float*)d_in[18];
    float* out = (float*)d_out;

    float* p_sn   = sym(g_sn);
    float* p_tg   = sym(g_tg);
    float* p_an   = sym(g_an);
    float* p_q    = sym(g_q);
    float* p_k    = sym(g_k);
    float* p_v    = sym(g_v);
    float* p_gate = sym(g_gate);
    float* p_bias = sym(g_bias);
    float* p_go   = sym(g_go);

    cudaFuncSetAttribute(gemm_mma<0, true>, cudaFuncAttributeMaxDynamicSharedMemorySize, SMEM_BYTES);
    cudaFuncSetAttribute(gemm_mma<1, true>, cudaFuncAttributeMaxDynamicSharedMemorySize, SMEM_BYTES);
    cudaFuncSetAttribute(gemm_mma<2, true>, cudaFuncAttributeMaxDynamicSharedMemorySize, SMEM_BYTES);
    cudaFuncSetAttribute(gemm_mma<3, true>, cudaFuncAttributeMaxDynamicSharedMemorySize, SMEM_BYTES);
    cudaFuncSetAttribute(gemm_mma<4, true>, cudaFuncAttributeMaxDynamicSharedMemorySize, SMEM_BYTES);
    cudaFuncSetAttribute(gemm_mma<8, true>, cudaFuncAttributeMaxDynamicSharedMemorySize, SMEM_BYTES);
    cudaFuncSetAttribute(attn_kernel, cudaFuncAttributeMaxDynamicSharedMemorySize, ATT_SMEM);

    // 1. layer norms
    ln_kernel<<<MM, 256>>>(s, a, gamma_s);

    dim3 gP(CA / 64, MM / 128, 1);
    // 2. t_g
    gemm_mma<0, true><<<gP, 256, SMEM_BYTES>>>(p_sn, CS, 0, W_ada_g, CA, 0, p_tg, CA, 0,
                                               MM, CA, CS, b_ada_g, nullptr);
    // 3. a_n
    gemm_mma<1, true><<<gP, 256, SMEM_BYTES>>>(p_sn, CS, 0, W_ada_o, CA, 0, p_an, CA, 0,
                                               MM, CA, CS, nullptr, p_tg);
    // 4-7. projections
    gemm_mma<2, true><<<gP, 256, SMEM_BYTES>>>(p_an, CA, 0, Wq, CA, 0, p_q, 0, 0,
                                               MM, CA, CA, bq, nullptr);
    gemm_mma<3, true><<<gP, 256, SMEM_BYTES>>>(p_an, CA, 0, Wk, CA, 0, p_k, 0, 0,
                                               MM, CA, CA, nullptr, nullptr);
    gemm_mma<4, true><<<gP, 256, SMEM_BYTES>>>(p_an, CA, 0, Wv, CA, 0, p_v, 0, 0,
                                               MM, CA, CA, nullptr, nullptr);
    gemm_mma<0, true><<<gP, 256, SMEM_BYTES>>>(p_an, CA, 0, Wg, CA, 0, p_gate, CA, 0,
                                               MM, CA, CA, nullptr, nullptr);
    // 8. pair bias
    pairbias2_kernel<<<dim3(SS / 64, SS, BB), 256>>>(z, beta, Wb, gz, bz);
    // 9. fused attention
    attn_kernel<<<dim3(SS / 128, BB * HH), 256, ATT_SMEM>>>(p_q, p_k, p_v, p_bias, p_gate, p_go);
    // 10. out = g_go @ Wout
    gemm_mma<0, true><<<gP, 256, SMEM_BYTES>>>(p_go, CA, 0, Wout, CA, 0, out, CA, 0,
                                               MM, CA, CA, nullptr, nullptr);
    // 11. out *= sigmoid(s @ Ws_gate + bs_gate)
    gemm_mma<8, true><<<gP, 256, SMEM_BYTES>>>(s, CS, 0, Ws_gate, CA, 0, out, CA, 0,
                                               MM, CA, CS, bs_gate, nullptr);
}

// round 5
// speedup vs baseline: 2.1268x; 1.1763x over previous
#include <cuda_runtime.h>
#include <cuda_bf16.h>
#include <math.h>
#include <cstdint>

// Problem constants
#define BB   2
#define SS   768
#define CA   768
#define CS   384
#define CZ   128
#define HH   16
#define HD   48
#define MM   (BB*SS)          // 1536
#define EPS  1e-5f
#define SCALE (0.14433756729740643f)  // 1/sqrt(48)

// ---------------- scratch (device globals) ----------------------------------
__device__ float g_sn   [MM*CS];
__device__ float g_lna  [MM*CA];
__device__ float g_an   [MM*CA];
__device__ float g_q    [BB*HH*SS*HD];      // [b,h,s,d]
__device__ float g_k    [BB*HH*SS*HD];      // [b,h,s,d]
__device__ float g_v    [BB*HH*SS*HD];      // [b,h,s,d]
__device__ float g_gate [MM*CA];
__device__ float g_bias [BB*HH*SS*SS];      // pair bias, [b,h,i,j]
__device__ float g_go   [MM*CA];

// ---------------- helpers ----------------------------------------------------
__device__ __forceinline__ float sigmoidf_(float x) { return 1.0f / (1.0f + expf(-x)); }

__device__ __forceinline__ uint32_t f2tf32(float f) {
    uint32_t r;
    asm("cvt.rna.tf32.f32 %0, %1;" : "=r"(r) : "f"(f));
    return r;
}

__device__ __forceinline__ void mma_tf32(float* d, const uint32_t* a, const uint32_t* b) {
    asm volatile("mma.sync.aligned.m16n8k8.row.col.f32.tf32.tf32.f32 "
        "{%0,%1,%2,%3}, {%4,%5,%6,%7}, {%8,%9}, {%0,%1,%2,%3};"
        : "+f"(d[0]), "+f"(d[1]), "+f"(d[2]), "+f"(d[3])
        : "r"(a[0]), "r"(a[1]), "r"(a[2]), "r"(a[3]), "r"(b[0]), "r"(b[1]));
}

__device__ float2 blockReduceSum2(float a, float b) {
    __shared__ float sa[32], sb[32];
    int lane = threadIdx.x & 31, wid = threadIdx.x >> 5;
    #pragma unroll
    for (int o = 16; o; o >>= 1) {
        a += __shfl_xor_sync(0xffffffffu, a, o);
        b += __shfl_xor_sync(0xffffffffu, b, o);
    }
    if (lane == 0) { sa[wid] = a; sb[wid] = b; }
    __syncthreads();
    if (wid == 0) {
        int nw = (blockDim.x + 31) >> 5;
        a = (lane < nw) ? sa[lane] : 0.0f;
        b = (lane < nw) ? sb[lane] : 0.0f;
        #pragma unroll
        for (int o = 16; o; o >>= 1) {
            a += __shfl_xor_sync(0xffffffffu, a, o);
            b += __shfl_xor_sync(0xffffffffu, b, o);
        }
        if (lane == 0) { sa[0] = a; sb[0] = b; }
    }
    __syncthreads();
    float2 r = make_float2(sa[0], sb[0]);
    __syncthreads();
    return r;
}

// ---------------- LN kernel --------------------------------------------------
__global__ void ln_kernel(const float* __restrict__ s, const float* __restrict__ a,
                          const float* __restrict__ gamma_s) {
    int r = blockIdx.x;
    int tid = threadIdx.x;
    const float* srow = s + (long)r * CS;
    float sum = 0.f, sq = 0.f;
    for (int c = tid; c < CS; c += blockDim.x) { float v = srow[c]; sum += v; sq += v * v; }
    float2 t = blockReduceSum2(sum, sq);
    float mean = t.x / CS, var = t.y / CS - mean * mean;
    float rstd = rsqrtf(var + EPS);
    for (int c = tid; c < CS; c += blockDim.x)
        g_sn[(long)r * CS + c] = (srow[c] - mean) * rstd * gamma_s[c];

    const float* arow = a + (long)r * CA;
    sum = 0.f; sq = 0.f;
    for (int c = tid; c < CA; c += blockDim.x) { float v = arow[c]; sum += v; sq += v * v; }
    t = blockReduceSum2(sum, sq);
    mean = t.x / CA; var = t.y / CA - mean * mean;
    rstd = rsqrtf(var + EPS);
    for (int c = tid; c < CA; c += blockDim.x)
        g_lna[(long)r * CA + c] = (arow[c] - mean) * rstd;
}

// ---------------- common GEMM machinery (128x64 tile, BK=32) ----------------
#define APITCH 36
#define BPITCH 36
#define A_WORDS (128 * APITCH)               // 4608
#define B_WORDS (64 * BPITCH)                // 2304
#define SPITCH 68
#define STAGE_WORDS (128 * SPITCH)           // 8704

// fragment compute for 128x64 tile
__device__ __forceinline__ void frag_compute(const uint32_t* As, const uint32_t* Bs,
        float (&acc)[2][4][4], int wr, int wc, int g4, int q4) {
    #pragma unroll
    for (int kc = 0; kc < 4; kc++) {
        int kb = kc * 8 + q4;
        uint32_t af[2][4];
        #pragma unroll
        for (int mt = 0; mt < 2; mt++) {
            int r = wr + mt * 16 + g4;
            af[mt][0] = As[r * APITCH + kb];
            af[mt][1] = As[(r + 8) * APITCH + kb];
            af[mt][2] = As[r * APITCH + kb + 4];
            af[mt][3] = As[(r + 8) * APITCH + kb + 4];
        }
        #pragma unroll
        for (int nt = 0; nt < 4; nt++) {
            int c = wc + nt * 8 + g4;
            uint32_t bf[2] = {Bs[c * BPITCH + kb], Bs[c * BPITCH + kb + 4]};
            #pragma unroll
            for (int mt = 0; mt < 2; mt++)
                mma_tf32(acc[mt][nt], af[mt], bf);
        }
    }
}

// dual-B compute (shared A fragments)
__device__ __forceinline__ void frag_compute2(const uint32_t* As, const uint32_t* Bs1,
        const uint32_t* Bs2, float (&acc1)[2][4][4], float (&acc2)[2][4][4],
        int wr, int wc, int g4, int q4) {
    #pragma unroll
    for (int kc = 0; kc < 4; kc++) {
        int kb = kc * 8 + q4;
        uint32_t af[2][4];
        #pragma unroll
        for (int mt = 0; mt < 2; mt++) {
            int r = wr + mt * 16 + g4;
            af[mt][0] = As[r * APITCH + kb];
            af[mt][1] = As[(r + 8) * APITCH + kb];
            af[mt][2] = As[r * APITCH + kb + 4];
            af[mt][3] = As[(r + 8) * APITCH + kb + 4];
        }
        #pragma unroll
        for (int nt = 0; nt < 4; nt++) {
            int c = wc + nt * 8 + g4;
            uint32_t b1[2] = {Bs1[c * BPITCH + kb], Bs1[c * BPITCH + kb + 4]};
            uint32_t b2[2] = {Bs2[c * BPITCH + kb], Bs2[c * BPITCH + kb + 4]};
            #pragma unroll
            for (int mt = 0; mt < 2; mt++) {
                mma_tf32(acc1[mt][nt], af[mt], b1);
                mma_tf32(acc2[mt][nt], af[mt], b2);
            }
        }
    }
}

__device__ __forceinline__ void stage_acc(float* st, const float (&acc)[2][4][4],
        int wr, int wc, int g4, int q4) {
    #pragma unroll
    for (int mt = 0; mt < 2; mt++) {
        #pragma unroll
        for (int nt = 0; nt < 4; nt++) {
            int rr = wr + mt * 16 + g4;
            int cc = wc + nt * 8 + 2 * q4;
            st[rr * SPITCH + cc]           = acc[mt][nt][0];
            st[rr * SPITCH + cc + 1]       = acc[mt][nt][1];
            st[(rr + 8) * SPITCH + cc]     = acc[mt][nt][2];
            st[(rr + 8) * SPITCH + cc + 1] = acc[mt][nt][3];
        }
    }
}

#define ZERO_ACC(acc) { \
    _Pragma("unroll") for (int i = 0; i < 2; i++) \
    _Pragma("unroll") for (int j = 0; j < 4; j++) \
    _Pragma("unroll") for (int t = 0; t < 4; t++) acc[i][j][t] = 0.f; }

// A tile: 128 x 32 fp32, each thread 4 float4
#define LDGA(pa, Abase, lda, k0) { \
    _Pragma("unroll") for (int rep = 0; rep < 4; rep++) { \
        int lin = rep * 256 + tid; int r = lin >> 3, c4 = (lin & 7) * 4; \
        pa[rep] = *(const float4*)&(Abase)[(long)(row0 + r) * (lda) + (k0) + c4]; } }
#define STSA(As, pa) { \
    _Pragma("unroll") for (int rep = 0; rep < 4; rep++) { \
        int lin = rep * 256 + tid; int r = lin >> 3, c4 = (lin & 7) * 4; \
        uint32_t* dst = &(As)[r * APITCH + c4]; \
        dst[0] = f2tf32(pa[rep].x); dst[1] = f2tf32(pa[rep].y); \
        dst[2] = f2tf32(pa[rep].z); dst[3] = f2tf32(pa[rep].w); } }
// B tile (B is [K, N] row-major): 32k x 64n, each thread 8 floats, coalesced
#define LDGB(pb, Bbase, ldb, k0, c0) { \
    _Pragma("unroll") for (int rep = 0; rep < 8; rep++) { \
        int lin = rep * 256 + tid; int kk = lin >> 6, n = lin & 63; \
        pb[rep] = (Bbase)[(long)((k0) + kk) * (ldb) + (c0) + n]; } }
#define STSB(Bs, pb) { \
    _Pragma("unroll") for (int rep = 0; rep < 8; rep++) { \
        int lin = rep * 256 + tid; int kk = lin >> 6, n = lin & 63; \
        (Bs)[n * BPITCH + kk] = f2tf32(pb[rep]); } }

// ---------------- adaLN fused dual GEMM --------------------------------------
// acc1 = sn @ W_ada_g ; acc2 = sn @ W_ada_o ; a_n = sigmoid(acc1+b)*lna + acc2
#define ADA_SMEM (2 * STAGE_WORDS * 4)   // 69632 B
__global__ void __launch_bounds__(256)
gemm_ada(const float* __restrict__ Wg_, const float* __restrict__ Wo_,
         const float* __restrict__ badag) {
    extern __shared__ float sm[];
    uint32_t* As  = (uint32_t*)sm;
    uint32_t* Bs1 = As + A_WORDS;
    uint32_t* Bs2 = Bs1 + B_WORDS;

    int tid = threadIdx.x, wid = tid >> 5;
    int g4 = (tid & 31) >> 2, q4 = tid & 3;
    int wr = (wid & 3) * 32, wc = (wid >> 2) * 32;
    int row0 = blockIdx.y * 128, col0 = blockIdx.x * 64;
    const float* A = g_sn;

    float acc1[2][4][4], acc2[2][4][4];
    ZERO_ACC(acc1); ZERO_ACC(acc2);
    float4 pa[4]; float pb1[8], pb2[8];

    LDGA(pa, A, CS, 0);
    LDGB(pb1, Wg_, CA, 0, col0);
    LDGB(pb2, Wo_, CA, 0, col0);
    const int KT = CS / 32;       // 12
    for (int kt = 0; kt < KT; kt++) {
        STSA(As, pa); STSB(Bs1, pb1); STSB(Bs2, pb2);
        __syncthreads();
        if (kt + 1 < KT) {
            int k0 = (kt + 1) * 32;
            LDGA(pa, A, CS, k0);
            LDGB(pb1, Wg_, CA, k0, col0);
            LDGB(pb2, Wo_, CA, k0, col0);
        }
        frag_compute2(As, Bs1, Bs2, acc1, acc2, wr, wc, g4, q4);
        __syncthreads();
    }

    float* st1 = sm;
    float* st2 = sm + STAGE_WORDS;
    stage_acc(st1, acc1, wr, wc, g4, q4);
    stage_acc(st2, acc2, wr, wc, g4, q4);
    __syncthreads();
    #pragma unroll
    for (int rep = 0; rep < 32; rep++) {
        int idx = rep * 256 + tid;
        int r = idx >> 6, c = idx & 63;
        int m = row0 + r, n = col0 + c;
        float v1 = st1[r * SPITCH + c], v2 = st2[r * SPITCH + c];
        g_an[(long)m * CA + n] = sigmoidf_(v1 + badag[n]) * g_lna[(long)m * CA + n] + v2;
    }
}

// ---------------- fused 4-way projection GEMM --------------------------------
// N = 4*768; weight & epilogue selected per 64-col tile.
#define PROJ_SMEM (STAGE_WORDS * 4)      // 34816 B  (tiles = 27648 fit inside)
__global__ void __launch_bounds__(256)
gemm_proj4(const float* __restrict__ Wq, const float* __restrict__ Wk,
           const float* __restrict__ Wv, const float* __restrict__ Wg_,
           const float* __restrict__ bq) {
    extern __shared__ float sm[];
    uint32_t* As = (uint32_t*)sm;
    uint32_t* Bs = As + A_WORDS;

    int tid = threadIdx.x, wid = tid >> 5;
    int g4 = (tid & 31) >> 2, q4 = tid & 3;
    int wr = (wid & 3) * 32, wc = (wid >> 2) * 32;
    int row0 = blockIdx.y * 128;
    int cg = blockIdx.x * 64;
    int w = cg / CA, coln = cg % CA;
    const float* B = (w == 0) ? Wq : (w == 1) ? Wk : (w == 2) ? Wv : Wg_;
    const float* A = g_an;

    float acc[2][4][4];
    ZERO_ACC(acc);
    float4 pa[4]; float pb[8];

    LDGA(pa, A, CA, 0);
    LDGB(pb, B, CA, 0, coln);
    const int KT = CA / 32;      // 24
    for (int kt = 0; kt < KT; kt++) {
        STSA(As, pa); STSB(Bs, pb);
        __syncthreads();
        if (kt + 1 < KT) {
            int k0 = (kt + 1) * 32;
            LDGA(pa, A, CA, k0);
            LDGB(pb, B, CA, k0, coln);
        }
        frag_compute(As, Bs, acc, wr, wc, g4, q4);
        __syncthreads();
    }

    float* st = sm;
    stage_acc(st, acc, wr, wc, g4, q4);
    __syncthreads();
    float* dst = (w == 0) ? g_q : (w == 1) ? g_k : g_v;
    #pragma unroll
    for (int rep = 0; rep < 32; rep++) {
        int idx = rep * 256 + tid;
        int r = idx >> 6, c = idx & 63;
        int m = row0 + r, n = coln + c;
        float v = st[r * SPITCH + c];
        if (w == 3) {
            g_gate[(long)m * CA + n] = v;
        } else {
            if (w == 0) v += bq[n];
            int b = m / SS, si = m % SS, h = n / HD, d = n % HD;
            dst[(((long)(b * HH + h) * SS) + si) * HD + d] = v;
        }
    }
}

// ---------------- fused output GEMM ------------------------------------------
// out = (go @ Wout) * sigmoid(s @ Ws_gate + bs_gate)
__global__ void __launch_bounds__(256)
gemm_final(const float* __restrict__ Wout, const float* __restrict__ s_,
           const float* __restrict__ Wsg, const float* __restrict__ bsg,
           float* __restrict__ out) {
    extern __shared__ float sm[];
    uint32_t* As = (uint32_t*)sm;
    uint32_t* Bs = As + A_WORDS;

    int tid = threadIdx.x, wid = tid >> 5;
    int g4 = (tid & 31) >> 2, q4 = tid & 3;
    int wr = (wid & 3) * 32, wc = (wid >> 2) * 32;
    int row0 = blockIdx.y * 128, col0 = blockIdx.x * 64;

    float acc1[2][4][4], acc2[2][4][4];
    ZERO_ACC(acc1); ZERO_ACC(acc2);
    float4 pa[4]; float pb[8];

    // loop 1: go @ Wout, K = 768
    {
        const float* A = g_go;
        LDGA(pa, A, CA, 0);
        LDGB(pb, Wout, CA, 0, col0);
        const int KT = CA / 32;
        for (int kt = 0; kt < KT; kt++) {
            STSA(As, pa); STSB(Bs, pb);
            __syncthreads();
            if (kt + 1 < KT) {
                int k0 = (kt + 1) * 32;
                LDGA(pa, A, CA, k0);
                LDGB(pb, Wout, CA, k0, col0);
            }
            frag_compute(As, Bs, acc1, wr, wc, g4, q4);
            __syncthreads();
        }
    }
    // loop 2: s @ Ws_gate, K = 384
    {
        LDGA(pa, s_, CS, 0);
        LDGB(pb, Wsg, CA, 0, col0);
        const int KT = CS / 32;
        for (int kt = 0; kt < KT; kt++) {
            STSA(As, pa); STSB(Bs, pb);
            __syncthreads();
            if (kt + 1 < KT) {
                int k0 = (kt + 1) * 32;
                LDGA(pa, s_, CS, k0);
                LDGB(pb, Wsg, CA, k0, col0);
            }
            frag_compute(As, Bs, acc2, wr, wc, g4, q4);
            __syncthreads();
        }
    }

    // combine in registers: acc1 * sigmoid(acc2 + bsg[n])
    #pragma unroll
    for (int mt = 0; mt < 2; mt++)
        #pragma unroll
        for (int nt = 0; nt < 4; nt++)
            #pragma unroll
            for (int t = 0; t < 4; t++) {
                int n = col0 + wc + nt * 8 + 2 * q4 + (t & 1);
                acc1[mt][nt][t] *= sigmoidf_(acc2[mt][nt][t] + __ldg(&bsg[n]));
            }

    float* st = sm;
    stage_acc(st, acc1, wr, wc, g4, q4);
    __syncthreads();
    #pragma unroll
    for (int rep = 0; rep < 32; rep++) {
        int idx = rep * 256 + tid;
        int r = idx >> 6, c = idx & 63;
        out[(long)(row0 + r) * CA + col0 + c] = st[r * SPITCH + c];
    }
}

// ---------------- pair bias: LN(z)*gz+bz @ Wb + beta via mma (128 rows) -----
#define ZP 132
#define PB_ZS_WORDS (128 * ZP)                       // 16896
#define PB_WB_OFF   PB_ZS_WORDS                      // 16896
#define PB_RES_OFF  (PB_ZS_WORDS + 16 * ZP)          // 19008
#define PB_SMEM ((PB_RES_OFF + 128 * 17) * 4)        // 84736 B
__global__ void __launch_bounds__(256)
pairbias2_kernel(const float* __restrict__ z, const float* __restrict__ beta,
                 const float* __restrict__ Wb, const float* __restrict__ gz,
                 const float* __restrict__ bz) {
    extern __shared__ float smf[];
    uint32_t* Zs  = (uint32_t*)smf;
    uint32_t* Wbs = Zs + PB_WB_OFF;
    float*    res = smf + PB_RES_OFF;
    __shared__ float gzs[CZ], bzs[CZ];

    int tid = threadIdx.x, wid = tid >> 5, lane = tid & 31;
    int g4 = lane >> 2, q4 = lane & 3;
    int b = blockIdx.z, q = blockIdx.y, p0 = blockIdx.x * 128;

    for (int idx = tid; idx < CZ * HH; idx += 256) {
        int k = idx >> 4, n = idx & 15;
        Wbs[n * ZP + k] = f2tf32(Wb[idx]);
    }
    for (int idx = tid; idx < CZ; idx += 256) { gzs[idx] = gz[idx]; bzs[idx] = bz[idx]; }
    __syncthreads();

    // LN of 128 z-rows -> Zs (tf32). Warp w: rows 16w..16w+15.
    #pragma unroll
    for (int rr = 0; rr < 16; rr++) {
        int pl = wid * 16 + rr;
        const float* zr = z + (((long)(b * SS + p0 + pl) * SS) + q) * CZ;
        float v[4];
        float sum = 0.f, sq = 0.f;
        #pragma unroll
        for (int t = 0; t < 4; t++) {
            v[t] = zr[lane + 32 * t];
            sum += v[t]; sq += v[t] * v[t];
        }
        #pragma unroll
        for (int o = 16; o; o >>= 1) {
            sum += __shfl_xor_sync(0xffffffffu, sum, o);
            sq  += __shfl_xor_sync(0xffffffffu, sq,  o);
        }
        float mean = sum * (1.0f / CZ);
        float var  = sq * (1.0f / CZ) - mean * mean;
        float rstd = rsqrtf(var + EPS);
        #pragma unroll
        for (int t = 0; t < 4; t++) {
            int c = lane + 32 * t;
            Zs[pl * ZP + c] = f2tf32((v[t] - mean) * rstd * gzs[c] + bzs[c]);
        }
    }
    __syncthreads();

    // mma: [128 x 128] @ [128 x 16], 8 warps x 16 rows
    {
        int wr = wid * 16;
        float acc[2][4];
        #pragma unroll
        for (int nt = 0; nt < 2; nt++)
            #pragma unroll
            for (int t = 0; t < 4; t++) acc[nt][t] = 0.f;
        #pragma unroll
        for (int kc = 0; kc < 16; kc++) {
            int kb = kc * 8 + q4;
            uint32_t af[4];
            af[0] = Zs[(wr + g4) * ZP + kb];
            af[1] = Zs[(wr + g4 + 8) * ZP + kb];
            af[2] = Zs[(wr + g4) * ZP + kb + 4];
            af[3] = Zs[(wr + g4 + 8) * ZP + kb + 4];
            #pragma unroll
            for (int nt = 0; nt < 2; nt++) {
                uint32_t bf[2];
                bf[0] = Wbs[(nt * 8 + g4) * ZP + kb];
                bf[1] = Wbs[(nt * 8 + g4) * ZP + kb + 4];
                mma_tf32(acc[nt], af, bf);
            }
        }
        #pragma unroll
        for (int nt = 0; nt < 2; nt++) {
            #pragma unroll
            for (int t = 0; t < 4; t++) {
                int row = wr + g4 + ((t >= 2) ? 8 : 0);
                int h = nt * 8 + 2 * q4 + (t & 1);
                float bet = beta[(((long)(b * SS + p0 + row) * SS) + q) * HH + h];
                res[row * 17 + h] = acc[nt][t] + bet;
            }
        }
    }
    __syncthreads();

    // coalesced store: g_bias[b,h,q,p]
    #pragma unroll
    for (int rep = 0; rep < 8; rep++) {
        int idx = rep * 256 + tid;
        int h = idx >> 7, p = idx & 127;
        g_bias[(((long)(b * HH + h) * SS) + q) * SS + p0 + p] = res[p * 17 + h];
    }
}

// ---------------- fused attention: softmax(scale*QK^T + bias) @ V, gated ----
#define QP 52
#define KP 52
#define VP 68
#define PP 68
#define AT_K (128 * QP)
#define AT_V (AT_K + 64 * KP)
#define AT_P (AT_V + 48 * VP)
#define AT_WORDS (AT_P + 128 * PP)
#define ATT_SMEM (AT_WORDS * 4)

__global__ void __launch_bounds__(256, 1)
attn_kernel(const float* __restrict__ qg, const float* __restrict__ kg,
            const float* __restrict__ vg, const float* __restrict__ biasg,
            const float* __restrict__ gateg, float* __restrict__ outg) {
    extern __shared__ char smem[];
    uint32_t* Qs = (uint32_t*)smem;
    uint32_t* Ks = Qs + AT_K;
    uint32_t* Vs = Qs + AT_V;
    float*    Bf = (float*)(Qs + AT_P);
    uint32_t* Ps = (uint32_t*)Bf;

    int tid = threadIdx.x, wid = tid >> 5, lane = tid & 31;
    int g4 = lane >> 2, q4 = lane & 3;
    int bh = blockIdx.y;
    int b = bh >> 4, h = bh & 15;
    int i0 = blockIdx.x * 128;
    const float* qb = qg + ((long)bh * SS + i0) * HD;
    const float* kb_ = kg + (long)bh * SS * HD;
    const float* vb = vg + (long)bh * SS * HD;
    const float* biasb = biasg + ((long)bh * SS + i0) * SS;

    #pragma unroll
    for (int rep = 0; rep < 6; rep++) {
        int idx = rep * 256 + tid;
        int r = idx / 12, c4 = (idx % 12) * 4;
        float4 v = *(const float4*)&qb[(long)r * HD + c4];
        uint32_t* d = &Qs[r * QP + c4];
        d[0] = f2tf32(v.x); d[1] = f2tf32(v.y); d[2] = f2tf32(v.z); d[3] = f2tf32(v.w);
    }

    int wr = wid * 16;
    float accO[6][4];
    #pragma unroll
    for (int n = 0; n < 6; n++)
        #pragma unroll
        for (int t = 0; t < 4; t++) accO[n][t] = 0.f;
    float mrow[2] = {-1e30f, -1e30f};
    float lrow[2] = {0.f, 0.f};

    for (int j = 0; j < 12; j++) {
        __syncthreads();
        #pragma unroll
        for (int rep = 0; rep < 3; rep++) {
            int idx = rep * 256 + tid;
            int r = idx / 12, c4 = (idx % 12) * 4;
            float4 v = *(const float4*)&kb_[(long)(j * 64 + r) * HD + c4];
            uint32_t* d = &Ks[r * KP + c4];
            d[0] = f2tf32(v.x); d[1] = f2tf32(v.y); d[2] = f2tf32(v.z); d[3] = f2tf32(v.w);
        }
        #pragma unroll
        for (int rep = 0; rep < 12; rep++) {
            int idx = rep * 256 + tid;
            int r = idx / 48, d = idx % 48;
            Vs[d * VP + r] = f2tf32(vb[(long)(j * 64 + r) * HD + d]);
        }
        #pragma unroll
        for (int rep = 0; rep < 32; rep++) {
            int idx = rep * 256 + tid;
            int r = idx >> 6, c = idx & 63;
            Bf[r * PP + c] = biasb[(long)r * SS + j * 64 + c];
        }
        __syncthreads();

        float S[8][4];
        #pragma unroll
        for (int nt = 0; nt < 8; nt++)
            #pragma unroll
            for (int t = 0; t < 4; t++) S[nt][t] = 0.f;
        #pragma unroll
        for (int kc = 0; kc < 6; kc++) {
            int kbx = kc * 8 + q4;
            uint32_t af[4];
            af[0] = Qs[(wr + g4) * QP + kbx];
            af[1] = Qs[(wr + g4 + 8) * QP + kbx];
            af[2] = Qs[(wr + g4) * QP + kbx + 4];
            af[3] = Qs[(wr + g4 + 8) * QP + kbx + 4];
            #pragma unroll
            for (int nt = 0; nt < 8; nt++) {
                uint32_t bf2[2];
                bf2[0] = Ks[(nt * 8 + g4) * KP + kbx];
                bf2[1] = Ks[(nt * 8 + g4) * KP + kbx + 4];
                mma_tf32(S[nt], af, bf2);
            }
        }
        int r0 = wr + g4, r1 = r0 + 8;
        float mn0 = mrow[0], mn1 = mrow[1];
        #pragma unroll
        for (int nt = 0; nt < 8; nt++) {
            #pragma unroll
            for (int t = 0; t < 4; t++) {
                int rr = (t >= 2) ? r1 : r0;
                int cc = nt * 8 + 2 * q4 + (t & 1);
                float val = S[nt][t] * SCALE + Bf[rr * PP + cc];
                S[nt][t] = val;
                if (t < 2) mn0 = fmaxf(mn0, val); else mn1 = fmaxf(mn1, val);
            }
        }
        mn0 = fmaxf(mn0, __shfl_xor_sync(0xffffffffu, mn0, 1));
        mn0 = fmaxf(mn0, __shfl_xor_sync(0xffffffffu, mn0, 2));
        mn1 = fmaxf(mn1, __shfl_xor_sync(0xffffffffu, mn1, 1));
        mn1 = fmaxf(mn1, __shfl_xor_sync(0xffffffffu, mn1, 2));
        float al0 = __expf(mrow[0] - mn0);
        float al1 = __expf(mrow[1] - mn1);
        mrow[0] = mn0; mrow[1] = mn1;
        float s0 = 0.f, s1 = 0.f;
        #pragma unroll
        for (int nt = 0; nt < 8; nt++) {
            #pragma unroll
            for (int t = 0; t < 4; t++) {
                float p = __expf(S[nt][t] - ((t >= 2) ? mn1 : mn0));
                S[nt][t] = p;
                if (t < 2) s0 += p; else s1 += p;
                int rr = (t >= 2) ? r1 : r0;
                int cc = nt * 8 + 2 * q4 + (t & 1);
                Ps[rr * PP + cc] = f2tf32(p);
            }
        }
        s0 += __shfl_xor_sync(0xffffffffu, s0, 1);
        s0 += __shfl_xor_sync(0xffffffffu, s0, 2);
        s1 += __shfl_xor_sync(0xffffffffu, s1, 1);
        s1 += __shfl_xor_sync(0xffffffffu, s1, 2);
        lrow[0] = lrow[0] * al0 + s0;
        lrow[1] = lrow[1] * al1 + s1;
        #pragma unroll
        for (int n = 0; n < 6; n++) {
            accO[n][0] *= al0; accO[n][1] *= al0;
            accO[n][2] *= al1; accO[n][3] *= al1;
        }
        __syncwarp();
        #pragma unroll
        for (int kc = 0; kc < 8; kc++) {
            int kbx = kc * 8 + q4;
            uint32_t af[4];
            af[0] = Ps[(wr + g4) * PP + kbx];
            af[1] = Ps[(wr + g4 + 8) * PP + kbx];
            af[2] = Ps[(wr + g4) * PP + kbx + 4];
            af[3] = Ps[(wr + g4 + 8) * PP + kbx + 4];
            #pragma unroll
            for (int n = 0; n < 6; n++) {
                uint32_t bf2[2];
                bf2[0] = Vs[(n * 8 + g4) * VP + kbx];
                bf2[1] = Vs[(n * 8 + g4) * VP + kbx + 4];
                mma_tf32(accO[n], af, bf2);
            }
        }
    }

    float inv0 = 1.0f / lrow[0], inv1 = 1.0f / lrow[1];
    #pragma unroll
    for (int n = 0; n < 6; n++) {
        #pragma unroll
        for (int t = 0; t < 4; t++) {
            int r = wr + g4 + ((t >= 2) ? 8 : 0);
            int c = n * 8 + 2 * q4 + (t & 1);
            long gi = ((long)(b * SS + i0 + r)) * CA + h * HD + c;
            float o = accO[n][t] * ((t >= 2) ? inv1 : inv0);
            outg[gi] = o * sigmoidf_(gateg[gi]);
        }
    }
}

// ---------------- host side --------------------------------------------------
static float* sym(const void* symbol) {
    void* p = nullptr;
    cudaGetSymbolAddress(&p, symbol);
    return (float*)p;
}

extern "C" void kernel_launch(void* const* d_in, const int* in_sizes, int n_in,
                              void* d_out, int out_size) {
    const float* a        = (const float*)d_in[0];
    const float* s        = (const float*)d_in[1];
    const float* z        = (const float*)d_in[2];
    const float* beta     = (const float*)d_in[3];
    const float* gamma_s  = (const float*)d_in[4];
    const float* W_ada_g  = (const float*)d_in[5];
    const float* b_ada_g  = (const float*)d_in[6];
    const float* W_ada_o  = (const float*)d_in[7];
    const float* Wq       = (const float*)d_in[8];
    const float* bq       = (const float*)d_in[9];
    const float* Wk       = (const float*)d_in[10];
    const float* Wv       = (const float*)d_in[11];
    const float* Wb       = (const float*)d_in[12];
    const float* gz       = (const float*)d_in[13];
    const float* bz       = (const float*)d_in[14];
    const float* Wg       = (const float*)d_in[15];
    const float* Wout     = (const float*)d_in[16];
    const float* Ws_gate  = (const float*)d_in[17];
    const float* bs_gate  = (const float*)d_in[18];
    float* out = (float*)d_out;

    float* p_q    = sym(g_q);
    float* p_k    = sym(g_k);
    float* p_v    = sym(g_v);
    float* p_gate = sym(g_gate);
    float* p_bias = sym(g_bias);
    float* p_go   = sym(g_go);

    cudaFuncSetAttribute(gemm_ada,        cudaFuncAttributeMaxDynamicSharedMemorySize, ADA_SMEM);
    cudaFuncSetAttribute(gemm_proj4,      cudaFuncAttributeMaxDynamicSharedMemorySize, PROJ_SMEM);
    cudaFuncSetAttribute(gemm_final,      cudaFuncAttributeMaxDynamicSharedMemorySize, PROJ_SMEM);
    cudaFuncSetAttribute(pairbias2_kernel,cudaFuncAttributeMaxDynamicSharedMemorySize, PB_SMEM);
    cudaFuncSetAttribute(attn_kernel,     cudaFuncAttributeMaxDynamicSharedMemorySize, ATT_SMEM);

    // 1. layer norms
    ln_kernel<<<MM, 256>>>(s, a, gamma_s);
    // 2. adaLN (fused dual GEMM)
    gemm_ada<<<dim3(CA / 64, MM / 128), 256, ADA_SMEM>>>(W_ada_g, W_ada_o, b_ada_g);
    // 3. 4-way projections
    gemm_proj4<<<dim3(4 * CA / 64, MM / 128), 256, PROJ_SMEM>>>(Wq, Wk, Wv, Wg, bq);
    // 4. pair bias
    pairbias2_kernel<<<dim3(SS / 128, SS, BB), 256, PB_SMEM>>>(z, beta, Wb, gz, bz);
    // 5. fused attention
    attn_kernel<<<dim3(SS / 128, BB * HH), 256, ATT_SMEM>>>(p_q, p_k, p_v, p_bias, p_gate, p_go);
    // 6. fused output GEMM + s-gate
    gemm_final<<<dim3(CA / 64, MM / 128), 256, PROJ_SMEM>>>(Wout, s, Ws_gate, bs_gate, out);
}

// round 6
// speedup vs baseline: 2.6103x; 1.2273x over previous
#include <cuda_runtime.h>
#include <cuda_bf16.h>
#include <math.h>
#include <cstdint>

// Problem constants
#define BB   2
#define SS   768
#define CA   768
#define CS   384
#define CZ   128
#define HH   16
#define HD   48
#define MM   (BB*SS)          // 1536
#define EPS  1e-5f
#define SCALE (0.14433756729740643f)  // 1/sqrt(48)

// ---------------- scratch (device globals) ----------------------------------
__device__ float g_sn   [MM*CS];
__device__ float g_lna  [MM*CA];
__device__ float g_an   [MM*CA];
__device__ float g_q    [BB*HH*SS*HD];      // [b,h,s,d]
__device__ float g_k    [BB*HH*SS*HD];      // [b,h,s,d]
__device__ float g_v    [BB*HH*SS*HD];      // [b,h,s,d]
__device__ float g_gate [MM*CA];
__device__ float g_bias [BB*HH*SS*SS];      // pair bias, layout [b,h,j,i] (i contiguous)
__device__ float g_go   [MM*CA];

// ---------------- helpers ----------------------------------------------------
__device__ __forceinline__ float sigmoidf_(float x) { return 1.0f / (1.0f + expf(-x)); }

__device__ __forceinline__ uint32_t f2tf32(float f) {
    uint32_t r;
    asm("cvt.rna.tf32.f32 %0, %1;" : "=r"(r) : "f"(f));
    return r;
}

__device__ __forceinline__ void mma_tf32(float* d, const uint32_t* a, const uint32_t* b) {
    asm volatile("mma.sync.aligned.m16n8k8.row.col.f32.tf32.tf32.f32 "
        "{%0,%1,%2,%3}, {%4,%5,%6,%7}, {%8,%9}, {%0,%1,%2,%3};"
        : "+f"(d[0]), "+f"(d[1]), "+f"(d[2]), "+f"(d[3])
        : "r"(a[0]), "r"(a[1]), "r"(a[2]), "r"(a[3]), "r"(b[0]), "r"(b[1]));
}

__device__ float2 blockReduceSum2(float a, float b) {
    __shared__ float sa[32], sb[32];
    int lane = threadIdx.x & 31, wid = threadIdx.x >> 5;
    #pragma unroll
    for (int o = 16; o; o >>= 1) {
        a += __shfl_xor_sync(0xffffffffu, a, o);
        b += __shfl_xor_sync(0xffffffffu, b, o);
    }
    if (lane == 0) { sa[wid] = a; sb[wid] = b; }
    __syncthreads();
    if (wid == 0) {
        int nw = (blockDim.x + 31) >> 5;
        a = (lane < nw) ? sa[lane] : 0.0f;
        b = (lane < nw) ? sb[lane] : 0.0f;
        #pragma unroll
        for (int o = 16; o; o >>= 1) {
            a += __shfl_xor_sync(0xffffffffu, a, o);
            b += __shfl_xor_sync(0xffffffffu, b, o);
        }
        if (lane == 0) { sa[0] = a; sb[0] = b; }
    }
    __syncthreads();
    float2 r = make_float2(sa[0], sb[0]);
    __syncthreads();
    return r;
}

// ---------------- LN kernel --------------------------------------------------
__global__ void ln_kernel(const float* __restrict__ s, const float* __restrict__ a,
                          const float* __restrict__ gamma_s) {
    int r = blockIdx.x;
    int tid = threadIdx.x;
    const float* srow = s + (long)r * CS;
    float sum = 0.f, sq = 0.f;
    for (int c = tid; c < CS; c += blockDim.x) { float v = srow[c]; sum += v; sq += v * v; }
    float2 t = blockReduceSum2(sum, sq);
    float mean = t.x / CS, var = t.y / CS - mean * mean;
    float rstd = rsqrtf(var + EPS);
    for (int c = tid; c < CS; c += blockDim.x)
        g_sn[(long)r * CS + c] = (srow[c] - mean) * rstd * gamma_s[c];

    const float* arow = a + (long)r * CA;
    sum = 0.f; sq = 0.f;
    for (int c = tid; c < CA; c += blockDim.x) { float v = arow[c]; sum += v; sq += v * v; }
    t = blockReduceSum2(sum, sq);
    mean = t.x / CA; var = t.y / CA - mean * mean;
    rstd = rsqrtf(var + EPS);
    for (int c = tid; c < CA; c += blockDim.x)
        g_lna[(long)r * CA + c] = (arow[c] - mean) * rstd;
}

// ---------------- common GEMM machinery (128x64 tile, BK=32) ----------------
#define APITCH 36
#define BPITCH 36
#define A_WORDS (128 * APITCH)               // 4608
#define B_WORDS (64 * BPITCH)                // 2304
#define SPITCH 68
#define STAGE_WORDS (128 * SPITCH)           // 8704

__device__ __forceinline__ void frag_compute(const uint32_t* As, const uint32_t* Bs,
        float (&acc)[2][4][4], int wr, int wc, int g4, int q4) {
    #pragma unroll
    for (int kc = 0; kc < 4; kc++) {
        int kb = kc * 8 + q4;
        uint32_t af[2][4];
        #pragma unroll
        for (int mt = 0; mt < 2; mt++) {
            int r = wr + mt * 16 + g4;
            af[mt][0] = As[r * APITCH + kb];
            af[mt][1] = As[(r + 8) * APITCH + kb];
            af[mt][2] = As[r * APITCH + kb + 4];
            af[mt][3] = As[(r + 8) * APITCH + kb + 4];
        }
        #pragma unroll
        for (int nt = 0; nt < 4; nt++) {
            int c = wc + nt * 8 + g4;
            uint32_t bf[2] = {Bs[c * BPITCH + kb], Bs[c * BPITCH + kb + 4]};
            #pragma unroll
            for (int mt = 0; mt < 2; mt++)
                mma_tf32(acc[mt][nt], af[mt], bf);
        }
    }
}

__device__ __forceinline__ void frag_compute2(const uint32_t* As, const uint32_t* Bs1,
        const uint32_t* Bs2, float (&acc1)[2][4][4], float (&acc2)[2][4][4],
        int wr, int wc, int g4, int q4) {
    #pragma unroll
    for (int kc = 0; kc < 4; kc++) {
        int kb = kc * 8 + q4;
        uint32_t af[2][4];
        #pragma unroll
        for (int mt = 0; mt < 2; mt++) {
            int r = wr + mt * 16 + g4;
            af[mt][0] = As[r * APITCH + kb];
            af[mt][1] = As[(r + 8) * APITCH + kb];
            af[mt][2] = As[r * APITCH + kb + 4];
            af[mt][3] = As[(r + 8) * APITCH + kb + 4];
        }
        #pragma unroll
        for (int nt = 0; nt < 4; nt++) {
            int c = wc + nt * 8 + g4;
            uint32_t b1[2] = {Bs1[c * BPITCH + kb], Bs1[c * BPITCH + kb + 4]};
            uint32_t b2[2] = {Bs2[c * BPITCH + kb], Bs2[c * BPITCH + kb + 4]};
            #pragma unroll
            for (int mt = 0; mt < 2; mt++) {
                mma_tf32(acc1[mt][nt], af[mt], b1);
                mma_tf32(acc2[mt][nt], af[mt], b2);
            }
        }
    }
}

__device__ __forceinline__ void stage_acc(float* st, const float (&acc)[2][4][4],
        int wr, int wc, int g4, int q4) {
    #pragma unroll
    for (int mt = 0; mt < 2; mt++) {
        #pragma unroll
        for (int nt = 0; nt < 4; nt++) {
            int rr = wr + mt * 16 + g4;
            int cc = wc + nt * 8 + 2 * q4;
            st[rr * SPITCH + cc]           = acc[mt][nt][0];
            st[rr * SPITCH + cc + 1]       = acc[mt][nt][1];
            st[(rr + 8) * SPITCH + cc]     = acc[mt][nt][2];
            st[(rr + 8) * SPITCH + cc + 1] = acc[mt][nt][3];
        }
    }
}

#define ZERO_ACC(acc) { \
    _Pragma("unroll") for (int i = 0; i < 2; i++) \
    _Pragma("unroll") for (int j = 0; j < 4; j++) \
    _Pragma("unroll") for (int t = 0; t < 4; t++) acc[i][j][t] = 0.f; }

#define LDGA(pa, Abase, lda, k0) { \
    _Pragma("unroll") for (int rep = 0; rep < 4; rep++) { \
        int lin = rep * 256 + tid; int r = lin >> 3, c4 = (lin & 7) * 4; \
        pa[rep] = *(const float4*)&(Abase)[(long)(row0 + r) * (lda) + (k0) + c4]; } }
#define STSA(As, pa) { \
    _Pragma("unroll") for (int rep = 0; rep < 4; rep++) { \
        int lin = rep * 256 + tid; int r = lin >> 3, c4 = (lin & 7) * 4; \
        uint32_t* dst = &(As)[r * APITCH + c4]; \
        dst[0] = f2tf32(pa[rep].x); dst[1] = f2tf32(pa[rep].y); \
        dst[2] = f2tf32(pa[rep].z); dst[3] = f2tf32(pa[rep].w); } }
#define LDGB(pb, Bbase, ldb, k0, c0) { \
    _Pragma("unroll") for (int rep = 0; rep < 8; rep++) { \
        int lin = rep * 256 + tid; int kk = lin >> 6, n = lin & 63; \
        pb[rep] = (Bbase)[(long)((k0) + kk) * (ldb) + (c0) + n]; } }
#define STSB(Bs, pb) { \
    _Pragma("unroll") for (int rep = 0; rep < 8; rep++) { \
        int lin = rep * 256 + tid; int kk = lin >> 6, n = lin & 63; \
        (Bs)[n * BPITCH + kk] = f2tf32(pb[rep]); } }

// ---------------- adaLN fused dual GEMM --------------------------------------
#define ADA_SMEM (2 * STAGE_WORDS * 4)   // 69632 B
__global__ void __launch_bounds__(256)
gemm_ada(const float* __restrict__ Wg_, const float* __restrict__ Wo_,
         const float* __restrict__ badag) {
    extern __shared__ float sm[];
    uint32_t* As  = (uint32_t*)sm;
    uint32_t* Bs1 = As + A_WORDS;
    uint32_t* Bs2 = Bs1 + B_WORDS;

    int tid = threadIdx.x, wid = tid >> 5;
    int g4 = (tid & 31) >> 2, q4 = tid & 3;
    int wr = (wid & 3) * 32, wc = (wid >> 2) * 32;
    int row0 = blockIdx.y * 128, col0 = blockIdx.x * 64;
    const float* A = g_sn;

    float acc1[2][4][4], acc2[2][4][4];
    ZERO_ACC(acc1); ZERO_ACC(acc2);
    float4 pa[4]; float pb1[8], pb2[8];

    LDGA(pa, A, CS, 0);
    LDGB(pb1, Wg_, CA, 0, col0);
    LDGB(pb2, Wo_, CA, 0, col0);
    const int KT = CS / 32;
    for (int kt = 0; kt < KT; kt++) {
        STSA(As, pa); STSB(Bs1, pb1); STSB(Bs2, pb2);
        __syncthreads();
        if (kt + 1 < KT) {
            int k0 = (kt + 1) * 32;
            LDGA(pa, A, CS, k0);
            LDGB(pb1, Wg_, CA, k0, col0);
            LDGB(pb2, Wo_, CA, k0, col0);
        }
        frag_compute2(As, Bs1, Bs2, acc1, acc2, wr, wc, g4, q4);
        __syncthreads();
    }

    float* st1 = sm;
    float* st2 = sm + STAGE_WORDS;
    stage_acc(st1, acc1, wr, wc, g4, q4);
    stage_acc(st2, acc2, wr, wc, g4, q4);
    __syncthreads();
    #pragma unroll
    for (int rep = 0; rep < 32; rep++) {
        int idx = rep * 256 + tid;
        int r = idx >> 6, c = idx & 63;
        int m = row0 + r, n = col0 + c;
        float v1 = st1[r * SPITCH + c], v2 = st2[r * SPITCH + c];
        g_an[(long)m * CA + n] = sigmoidf_(v1 + badag[n]) * g_lna[(long)m * CA + n] + v2;
    }
}

// ---------------- fused 4-way projection GEMM --------------------------------
#define PROJ_SMEM (STAGE_WORDS * 4)      // 34816 B
__global__ void __launch_bounds__(256)
gemm_proj4(const float* __restrict__ Wq, const float* __restrict__ Wk,
           const float* __restrict__ Wv, const float* __restrict__ Wg_,
           const float* __restrict__ bq) {
    extern __shared__ float sm[];
    uint32_t* As = (uint32_t*)sm;
    uint32_t* Bs = As + A_WORDS;

    int tid = threadIdx.x, wid = tid >> 5;
    int g4 = (tid & 31) >> 2, q4 = tid & 3;
    int wr = (wid & 3) * 32, wc = (wid >> 2) * 32;
    int row0 = blockIdx.y * 128;
    int cg = blockIdx.x * 64;
    int w = cg / CA, coln = cg % CA;
    const float* B = (w == 0) ? Wq : (w == 1) ? Wk : (w == 2) ? Wv : Wg_;
    const float* A = g_an;

    float acc[2][4][4];
    ZERO_ACC(acc);
    float4 pa[4]; float pb[8];

    LDGA(pa, A, CA, 0);
    LDGB(pb, B, CA, 0, coln);
    const int KT = CA / 32;
    for (int kt = 0; kt < KT; kt++) {
        STSA(As, pa); STSB(Bs, pb);
        __syncthreads();
        if (kt + 1 < KT) {
            int k0 = (kt + 1) * 32;
            LDGA(pa, A, CA, k0);
            LDGB(pb, B, CA, k0, coln);
        }
        frag_compute(As, Bs, acc, wr, wc, g4, q4);
        __syncthreads();
    }

    float* st = sm;
    stage_acc(st, acc, wr, wc, g4, q4);
    __syncthreads();
    float* dst = (w == 0) ? g_q : (w == 1) ? g_k : g_v;
    #pragma unroll
    for (int rep = 0; rep < 32; rep++) {
        int idx = rep * 256 + tid;
        int r = idx >> 6, c = idx & 63;
        int m = row0 + r, n = coln + c;
        float v = st[r * SPITCH + c];
        if (w == 3) {
            g_gate[(long)m * CA + n] = v;
        } else {
            if (w == 0) v += bq[n];
            int b = m / SS, si = m % SS, h = n / HD, d = n % HD;
            dst[(((long)(b * HH + h) * SS) + si) * HD + d] = v;
        }
    }
}

// ---------------- fused output GEMM ------------------------------------------
__global__ void __launch_bounds__(256)
gemm_final(const float* __restrict__ Wout, const float* __restrict__ s_,
           const float* __restrict__ Wsg, const float* __restrict__ bsg,
           float* __restrict__ out) {
    extern __shared__ float sm[];
    uint32_t* As = (uint32_t*)sm;
    uint32_t* Bs = As + A_WORDS;

    int tid = threadIdx.x, wid = tid >> 5;
    int g4 = (tid & 31) >> 2, q4 = tid & 3;
    int wr = (wid & 3) * 32, wc = (wid >> 2) * 32;
    int row0 = blockIdx.y * 128, col0 = blockIdx.x * 64;

    float acc1[2][4][4], acc2[2][4][4];
    ZERO_ACC(acc1); ZERO_ACC(acc2);
    float4 pa[4]; float pb[8];

    {
        const float* A = g_go;
        LDGA(pa, A, CA, 0);
        LDGB(pb, Wout, CA, 0, col0);
        const int KT = CA / 32;
        for (int kt = 0; kt < KT; kt++) {
            STSA(As, pa); STSB(Bs, pb);
            __syncthreads();
            if (kt + 1 < KT) {
                int k0 = (kt + 1) * 32;
                LDGA(pa, A, CA, k0);
                LDGB(pb, Wout, CA, k0, col0);
            }
            frag_compute(As, Bs, acc1, wr, wc, g4, q4);
            __syncthreads();
        }
    }
    {
        LDGA(pa, s_, CS, 0);
        LDGB(pb, Wsg, CA, 0, col0);
        const int KT = CS / 32;
        for (int kt = 0; kt < KT; kt++) {
            STSA(As, pa); STSB(Bs, pb);
            __syncthreads();
            if (kt + 1 < KT) {
                int k0 = (kt + 1) * 32;
                LDGA(pa, s_, CS, k0);
                LDGB(pb, Wsg, CA, k0, col0);
            }
            frag_compute(As, Bs, acc2, wr, wc, g4, q4);
            __syncthreads();
        }
    }

    #pragma unroll
    for (int mt = 0; mt < 2; mt++)
        #pragma unroll
        for (int nt = 0; nt < 4; nt++)
            #pragma unroll
            for (int t = 0; t < 4; t++) {
                int n = col0 + wc + nt * 8 + 2 * q4 + (t & 1);
                acc1[mt][nt][t] *= sigmoidf_(acc2[mt][nt][t] + __ldg(&bsg[n]));
            }

    float* st = sm;
    stage_acc(st, acc1, wr, wc, g4, q4);
    __syncthreads();
    #pragma unroll
    for (int rep = 0; rep < 32; rep++) {
        int idx = rep * 256 + tid;
        int r = idx >> 6, c = idx & 63;
        out[(long)(row0 + r) * CA + col0 + c] = st[r * SPITCH + c];
    }
}

// ---------------- pair bias v3: streaming layout -----------------------------
// Block handles (b, p=j, q-tile of 128 i values). z slab contiguous (64KB).
// Output: g_bias[b][h][p][q0..q0+127] (contiguous per h).
#define ZP 132
#define PB_ZS_WORDS (128 * ZP)                       // 16896
#define PB_WB_OFF   PB_ZS_WORDS
#define PB_BETA_OFF (PB_WB_OFF + 16 * ZP)            // +2112 = 19008
#define PB_RES_OFF  (PB_BETA_OFF + 128 * 16)         // +2048 = 21056
#define PB_SMEM ((PB_RES_OFF + 128 * 17) * 4)        // 93 KB
__global__ void __launch_bounds__(256)
pairbias3_kernel(const float* __restrict__ z, const float* __restrict__ beta,
                 const float* __restrict__ Wb, const float* __restrict__ gz,
                 const float* __restrict__ bz) {
    extern __shared__ float smf[];
    uint32_t* Zs    = (uint32_t*)smf;
    uint32_t* Wbs   = Zs + PB_WB_OFF;
    float*    betas = smf + PB_BETA_OFF;
    float*    res   = smf + PB_RES_OFF;
    __shared__ float gzs[CZ], bzs[CZ];

    int tid = threadIdx.x, wid = tid >> 5, lane = tid & 31;
    int g4 = lane >> 2, q4 = lane & 3;
    int b = blockIdx.z, p = blockIdx.y, q0 = blockIdx.x * 128;

    const float* zb = z + ((long)(b * SS + p) * SS + q0) * CZ;
    const float* betab = beta + ((long)(b * SS + p) * SS + q0) * HH;

    // stage Wb (transposed) + gz/bz + beta slab (all contiguous loads)
    for (int idx = tid; idx < CZ * HH; idx += 256) {
        int k = idx >> 4, n = idx & 15;
        Wbs[n * ZP + k] = f2tf32(Wb[idx]);
    }
    for (int idx = tid; idx < CZ; idx += 256) { gzs[idx] = gz[idx]; bzs[idx] = bz[idx]; }
    #pragma unroll
    for (int rep = 0; rep < 8; rep++)
        betas[rep * 256 + tid] = betab[rep * 256 + tid];
    __syncthreads();

    // LN of 128 contiguous z-rows. Warp w: rows 16w..16w+15, two batches of 8
    // (batched loads for MLP, interleaved shfl chains).
    #pragma unroll
    for (int batch = 0; batch < 2; batch++) {
        float4 vr[8];
        #pragma unroll
        for (int rr = 0; rr < 8; rr++) {
            int pl = wid * 16 + batch * 8 + rr;
            vr[rr] = *(const float4*)&zb[(long)pl * CZ + lane * 4];
        }
        float sums[8], sqs[8];
        #pragma unroll
        for (int rr = 0; rr < 8; rr++) {
            float4 v = vr[rr];
            sums[rr] = v.x + v.y + v.z + v.w;
            sqs[rr]  = v.x * v.x + v.y * v.y + v.z * v.z + v.w * v.w;
        }
        #pragma unroll
        for (int o = 16; o; o >>= 1) {
            #pragma unroll
            for (int rr = 0; rr < 8; rr++) {
                sums[rr] += __shfl_xor_sync(0xffffffffu, sums[rr], o);
                sqs[rr]  += __shfl_xor_sync(0xffffffffu, sqs[rr],  o);
            }
        }
        #pragma unroll
        for (int rr = 0; rr < 8; rr++) {
            int pl = wid * 16 + batch * 8 + rr;
            float mean = sums[rr] * (1.0f / CZ);
            float var  = sqs[rr] * (1.0f / CZ) - mean * mean;
            float rstd = rsqrtf(var + EPS);
            float4 v = vr[rr];
            int c = lane * 4;
            uint4 o4;
            o4.x = f2tf32((v.x - mean) * rstd * gzs[c + 0] + bzs[c + 0]);
            o4.y = f2tf32((v.y - mean) * rstd * gzs[c + 1] + bzs[c + 1]);
            o4.z = f2tf32((v.z - mean) * rstd * gzs[c + 2] + bzs[c + 2]);
            o4.w = f2tf32((v.w - mean) * rstd * gzs[c + 3] + bzs[c + 3]);
            *(uint4*)&Zs[pl * ZP + c] = o4;
        }
    }
    __syncthreads();

    // mma: [128 x 128] @ [128 x 16], 8 warps x 16 rows
    {
        int wr = wid * 16;
        float acc[2][4];
        #pragma unroll
        for (int nt = 0; nt < 2; nt++)
            #pragma unroll
            for (int t = 0; t < 4; t++) acc[nt][t] = 0.f;
        #pragma unroll
        for (int kc = 0; kc < 16; kc++) {
            int kb = kc * 8 + q4;
            uint32_t af[4];
            af[0] = Zs[(wr + g4) * ZP + kb];
            af[1] = Zs[(wr + g4 + 8) * ZP + kb];
            af[2] = Zs[(wr + g4) * ZP + kb + 4];
            af[3] = Zs[(wr + g4 + 8) * ZP + kb + 4];
            #pragma unroll
            for (int nt = 0; nt < 2; nt++) {
                uint32_t bf[2];
                bf[0] = Wbs[(nt * 8 + g4) * ZP + kb];
                bf[1] = Wbs[(nt * 8 + g4) * ZP + kb + 4];
                mma_tf32(acc[nt], af, bf);
            }
        }
        #pragma unroll
        for (int nt = 0; nt < 2; nt++) {
            #pragma unroll
            for (int t = 0; t < 4; t++) {
                int row = wr + g4 + ((t >= 2) ? 8 : 0);
                int h = nt * 8 + 2 * q4 + (t & 1);
                res[row * 17 + h] = acc[nt][t] + betas[row * 16 + h];
            }
        }
    }
    __syncthreads();

    // coalesced store: g_bias[b][h][p][q0+ql] (contiguous runs of 128 per h)
    #pragma unroll
    for (int rep = 0; rep < 8; rep++) {
        int idx = rep * 256 + tid;
        int h = idx >> 7, ql = idx & 127;
        g_bias[(((long)(b * HH + h) * SS) + p) * SS + q0 + ql] = res[ql * 17 + h];
    }
}

// ---------------- fused attention: softmax(scale*QK^T + bias) @ V, gated ----
// bias layout is [b,h,j,i] -> staged column-major Bfc[c(=j-local)][r(=i-local)]
#define QP 52
#define KP 52
#define VP 68
#define PP 68
#define BFP 132
#define AT_K (128 * QP)
#define AT_V (AT_K + 64 * KP)
#define AT_P (AT_V + 48 * VP)
#define AT_BF (AT_P + 128 * PP)
#define AT_WORDS (AT_BF + 64 * BFP)
#define ATT_SMEM (AT_WORDS * 4)

__global__ void __launch_bounds__(256, 1)
attn_kernel(const float* __restrict__ qg, const float* __restrict__ kg,
            const float* __restrict__ vg, const float* __restrict__ biasg,
            const float* __restrict__ gateg, float* __restrict__ outg) {
    extern __shared__ char smem[];
    uint32_t* Qs = (uint32_t*)smem;
    uint32_t* Ks = Qs + AT_K;
    uint32_t* Vs = Qs + AT_V;
    uint32_t* Ps = Qs + AT_P;
    float*    Bfc = (float*)(Qs + AT_BF);

    int tid = threadIdx.x, wid = tid >> 5, lane = tid & 31;
    int g4 = lane >> 2, q4 = lane & 3;
    int bh = blockIdx.y;
    int b = bh >> 4, h = bh & 15;
    int i0 = blockIdx.x * 128;
    const float* qb = qg + ((long)bh * SS + i0) * HD;
    const float* kb_ = kg + (long)bh * SS * HD;
    const float* vb = vg + (long)bh * SS * HD;
    const float* biasb = biasg + (long)bh * SS * SS;   // [j][i]

    #pragma unroll
    for (int rep = 0; rep < 6; rep++) {
        int idx = rep * 256 + tid;
        int r = idx / 12, c4 = (idx % 12) * 4;
        float4 v = *(const float4*)&qb[(long)r * HD + c4];
        uint32_t* d = &Qs[r * QP + c4];
        d[0] = f2tf32(v.x); d[1] = f2tf32(v.y); d[2] = f2tf32(v.z); d[3] = f2tf32(v.w);
    }

    int wr = wid * 16;
    float accO[6][4];
    #pragma unroll
    for (int n = 0; n < 6; n++)
        #pragma unroll
        for (int t = 0; t < 4; t++) accO[n][t] = 0.f;
    float mrow[2] = {-1e30f, -1e30f};
    float lrow[2] = {0.f, 0.f};

    for (int j = 0; j < 12; j++) {
        __syncthreads();
        #pragma unroll
        for (int rep = 0; rep < 3; rep++) {
            int idx = rep * 256 + tid;
            int r = idx / 12, c4 = (idx % 12) * 4;
            float4 v = *(const float4*)&kb_[(long)(j * 64 + r) * HD + c4];
            uint32_t* d = &Ks[r * KP + c4];
            d[0] = f2tf32(v.x); d[1] = f2tf32(v.y); d[2] = f2tf32(v.z); d[3] = f2tf32(v.w);
        }
        #pragma unroll
        for (int rep = 0; rep < 12; rep++) {
            int idx = rep * 256 + tid;
            int r = idx / 48, d = idx % 48;
            Vs[d * VP + r] = f2tf32(vb[(long)(j * 64 + r) * HD + d]);
        }
        // bias tile: [b,h,j0+c, i0+r], r contiguous in gmem -> column-major smem
        #pragma unroll
        for (int rep = 0; rep < 32; rep++) {
            int idx = rep * 256 + tid;
            int c = idx >> 7, r = idx & 127;
            Bfc[c * BFP + r] = biasb[(long)(j * 64 + c) * SS + i0 + r];
        }
        __syncthreads();

        float S[8][4];
        #pragma unroll
        for (int nt = 0; nt < 8; nt++)
            #pragma unroll
            for (int t = 0; t < 4; t++) S[nt][t] = 0.f;
        #pragma unroll
        for (int kc = 0; kc < 6; kc++) {
            int kbx = kc * 8 + q4;
            uint32_t af[4];
            af[0] = Qs[(wr + g4) * QP + kbx];
            af[1] = Qs[(wr + g4 + 8) * QP + kbx];
            af[2] = Qs[(wr + g4) * QP + kbx + 4];
            af[3] = Qs[(wr + g4 + 8) * QP + kbx + 4];
            #pragma unroll
            for (int nt = 0; nt < 8; nt++) {
                uint32_t bf2[2];
                bf2[0] = Ks[(nt * 8 + g4) * KP + kbx];
                bf2[1] = Ks[(nt * 8 + g4) * KP + kbx + 4];
                mma_tf32(S[nt], af, bf2);
            }
        }
        int r0 = wr + g4, r1 = r0 + 8;
        float mn0 = mrow[0], mn1 = mrow[1];
        #pragma unroll
        for (int nt = 0; nt < 8; nt++) {
            #pragma unroll
            for (int t = 0; t < 4; t++) {
                int rr = (t >= 2) ? r1 : r0;
                int cc = nt * 8 + 2 * q4 + (t & 1);
                float val = S[nt][t] * SCALE + Bfc[cc * BFP + rr];
                S[nt][t] = val;
                if (t < 2) mn0 = fmaxf(mn0, val); else mn1 = fmaxf(mn1, val);
            }
        }
        mn0 = fmaxf(mn0, __shfl_xor_sync(0xffffffffu, mn0, 1));
        mn0 = fmaxf(mn0, __shfl_xor_sync(0xffffffffu, mn0, 2));
        mn1 = fmaxf(mn1, __shfl_xor_sync(0xffffffffu, mn1, 1));
        mn1 = fmaxf(mn1, __shfl_xor_sync(0xffffffffu, mn1, 2));
        float al0 = __expf(mrow[0] - mn0);
        float al1 = __expf(mrow[1] - mn1);
        mrow[0] = mn0; mrow[1] = mn1;
        float s0 = 0.f, s1 = 0.f;
        #pragma unroll
        for (int nt = 0; nt < 8; nt++) {
            #pragma unroll
            for (int t = 0; t < 4; t++) {
                float p = __expf(S[nt][t] - ((t >= 2) ? mn1 : mn0));
                S[nt][t] = p;
                if (t < 2) s0 += p; else s1 += p;
                int rr = (t >= 2) ? r1 : r0;
                int cc = nt * 8 + 2 * q4 + (t & 1);
                Ps[rr * PP + cc] = f2tf32(p);
            }
        }
        s0 += __shfl_xor_sync(0xffffffffu, s0, 1);
        s0 += __shfl_xor_sync(0xffffffffu, s0, 2);
        s1 += __shfl_xor_sync(0xffffffffu, s1, 1);
        s1 += __shfl_xor_sync(0xffffffffu, s1, 2);
        lrow[0] = lrow[0] * al0 + s0;
        lrow[1] = lrow[1] * al1 + s1;
        #pragma unroll
        for (int n = 0; n < 6; n++) {
            accO[n][0] *= al0; accO[n][1] *= al0;
            accO[n][2] *= al1; accO[n][3] *= al1;
        }
        __syncwarp();
        #pragma unroll
        for (int kc = 0; kc < 8; kc++) {
            int kbx = kc * 8 + q4;
            uint32_t af[4];
            af[0] = Ps[(wr + g4) * PP + kbx];
            af[1] = Ps[(wr + g4 + 8) * PP + kbx];
            af[2] = Ps[(wr + g4) * PP + kbx + 4];
            af[3] = Ps[(wr + g4 + 8) * PP + kbx + 4];
            #pragma unroll
            for (int n = 0; n < 6; n++) {
                uint32_t bf2[2];
                bf2[0] = Vs[(n * 8 + g4) * VP + kbx];
                bf2[1] = Vs[(n * 8 + g4) * VP + kbx + 4];
                mma_tf32(accO[n], af, bf2);
            }
        }
    }

    float inv0 = 1.0f / lrow[0], inv1 = 1.0f / lrow[1];
    #pragma unroll
    for (int n = 0; n < 6; n++) {
        #pragma unroll
        for (int t = 0; t < 4; t++) {
            int r = wr + g4 + ((t >= 2) ? 8 : 0);
            int c = n * 8 + 2 * q4 + (t & 1);
            long gi = ((long)(b * SS + i0 + r)) * CA + h * HD + c;
            float o = accO[n][t] * ((t >= 2) ? inv1 : inv0);
            outg[gi] = o * sigmoidf_(gateg[gi]);
        }
    }
}

// ---------------- host side --------------------------------------------------
static float* sym(const void* symbol) {
    void* p = nullptr;
    cudaGetSymbolAddress(&p, symbol);
    return (float*)p;
}

extern "C" void kernel_launch(void* const* d_in, const int* in_sizes, int n_in,
                              void* d_out, int out_size) {
    const float* a        = (const float*)d_in[0];
    const float* s        = (const float*)d_in[1];
    const float* z        = (const float*)d_in[2];
    const float* beta     = (const float*)d_in[3];
    const float* gamma_s  = (const float*)d_in[4];
    const float* W_ada_g  = (const float*)d_in[5];
    const float* b_ada_g  = (const float*)d_in[6];
    const float* W_ada_o  = (const float*)d_in[7];
    const float* Wq       = (const float*)d_in[8];
    const float* bq       = (const float*)d_in[9];
    const float* Wk       = (const float*)d_in[10];
    const float* Wv       = (const float*)d_in[11];
    const float* Wb       = (const float*)d_in[12];
    const float* gz       = (const float*)d_in[13];
    const float* bz       = (const float*)d_in[14];
    const float* Wg       = (const float*)d_in[15];
    const float* Wout     = (const float*)d_in[16];
    const float* Ws_gate  = (const float*)d_in[17];
    const float* bs_gate  = (const float*)d_in[18];
    float* out = (float*)d_out;

    float* p_q    = sym(g_q);
    float* p_k    = sym(g_k);
    float* p_v    = sym(g_v);
    float* p_gate = sym(g_gate);
    float* p_bias = sym(g_bias);
    float* p_go   = sym(g_go);

    cudaFuncSetAttribute(gemm_ada,        cudaFuncAttributeMaxDynamicSharedMemorySize, ADA_SMEM);
    cudaFuncSetAttribute(gemm_proj4,      cudaFuncAttributeMaxDynamicSharedMemorySize, PROJ_SMEM);
    cudaFuncSetAttribute(gemm_final,      cudaFuncAttributeMaxDynamicSharedMemorySize, PROJ_SMEM);
    cudaFuncSetAttribute(pairbias3_kernel,cudaFuncAttributeMaxDynamicSharedMemorySize, PB_SMEM);
    cudaFuncSetAttribute(attn_kernel,     cudaFuncAttributeMaxDynamicSharedMemorySize, ATT_SMEM);

    // 1. layer norms
    ln_kernel<<<MM, 256>>>(s, a, gamma_s);
    // 2. adaLN (fused dual GEMM)
    gemm_ada<<<dim3(CA / 64, MM / 128), 256, ADA_SMEM>>>(W_ada_g, W_ada_o, b_ada_g);
    // 3. 4-way projections
    gemm_proj4<<<dim3(4 * CA / 64, MM / 128), 256, PROJ_SMEM>>>(Wq, Wk, Wv, Wg, bq);
    // 4. pair bias (streaming layout)
    pairbias3_kernel<<<dim3(SS / 128, SS, BB), 256, PB_SMEM>>>(z, beta, Wb, gz, bz);
    // 5. fused attention
    attn_kernel<<<dim3(SS / 128, BB * HH), 256, ATT_SMEM>>>(p_q, p_k, p_v, p_bias, p_gate, p_go);
    // 6. fused output GEMM + s-gate
    gemm_final<<<dim3(CA / 64, MM / 128), 256, PROJ_SMEM>>>(Wout, s, Ws_gate, bs_gate, out);
}

// round 8
// speedup vs baseline: 2.9623x; 1.1349x over previous
#include <cuda_runtime.h>
#include <cuda_bf16.h>
#include <math.h>
#include <cstdint>

// Problem constants
#define BB   2
#define SS   768
#define CA   768
#define CS   384
#define CZ   128
#define HH   16
#define HD   48
#define MM   (BB*SS)          // 1536
#define EPS  1e-5f
#define SCALE (0.14433756729740643f)  // 1/sqrt(48)

// ---------------- scratch (device globals) ----------------------------------
__device__ float g_sn   [MM*CS];
__device__ float g_lna  [MM*CA];
__device__ float g_an   [MM*CA];
__device__ float g_q    [BB*HH*SS*HD];      // [b,h,s,d]
__device__ float g_k    [BB*HH*SS*HD];      // [b,h,s,d]
__device__ float g_v    [BB*HH*SS*HD];      // [b,h,s,d]
__device__ float g_gate [MM*CA];
__device__ float g_bias [BB*HH*SS*SS];      // pair bias, layout [b,h,j,i] (i contiguous)
__device__ float g_go   [MM*CA];

// ---------------- helpers ----------------------------------------------------
__device__ __forceinline__ float sigmoidf_(float x) { return 1.0f / (1.0f + expf(-x)); }

__device__ __forceinline__ uint32_t f2tf32(float f) {
    uint32_t r;
    asm("cvt.rna.tf32.f32 %0, %1;" : "=r"(r) : "f"(f));
    return r;
}

__device__ __forceinline__ void mma_tf32(float* d, const uint32_t* a, const uint32_t* b) {
    asm volatile("mma.sync.aligned.m16n8k8.row.col.f32.tf32.tf32.f32 "
        "{%0,%1,%2,%3}, {%4,%5,%6,%7}, {%8,%9}, {%0,%1,%2,%3};"
        : "+f"(d[0]), "+f"(d[1]), "+f"(d[2]), "+f"(d[3])
        : "r"(a[0]), "r"(a[1]), "r"(a[2]), "r"(a[3]), "r"(b[0]), "r"(b[1]));
}

__device__ float2 blockReduceSum2(float a, float b) {
    __shared__ float sa[32], sb[32];
    int lane = threadIdx.x & 31, wid = threadIdx.x >> 5;
    #pragma unroll
    for (int o = 16; o; o >>= 1) {
        a += __shfl_xor_sync(0xffffffffu, a, o);
        b += __shfl_xor_sync(0xffffffffu, b, o);
    }
    if (lane == 0) { sa[wid] = a; sb[wid] = b; }
    __syncthreads();
    if (wid == 0) {
        int nw = (blockDim.x + 31) >> 5;
        a = (lane < nw) ? sa[lane] : 0.0f;
        b = (lane < nw) ? sb[lane] : 0.0f;
        #pragma unroll
        for (int o = 16; o; o >>= 1) {
            a += __shfl_xor_sync(0xffffffffu, a, o);
            b += __shfl_xor_sync(0xffffffffu, b, o);
        }
        if (lane == 0) { sa[0] = a; sb[0] = b; }
    }
    __syncthreads();
    float2 r = make_float2(sa[0], sb[0]);
    __syncthreads();
    return r;
}

// ---------------- LN kernel --------------------------------------------------
__global__ void ln_kernel(const float* __restrict__ s, const float* __restrict__ a,
                          const float* __restrict__ gamma_s) {
    int r = blockIdx.x;
    int tid = threadIdx.x;
    const float* srow = s + (long)r * CS;
    float sum = 0.f, sq = 0.f;
    for (int c = tid; c < CS; c += blockDim.x) { float v = srow[c]; sum += v; sq += v * v; }
    float2 t = blockReduceSum2(sum, sq);
    float mean = t.x / CS, var = t.y / CS - mean * mean;
    float rstd = rsqrtf(var + EPS);
    for (int c = tid; c < CS; c += blockDim.x)
        g_sn[(long)r * CS + c] = (srow[c] - mean) * rstd * gamma_s[c];

    const float* arow = a + (long)r * CA;
    sum = 0.f; sq = 0.f;
    for (int c = tid; c < CA; c += blockDim.x) { float v = arow[c]; sum += v; sq += v * v; }
    t = blockReduceSum2(sum, sq);
    mean = t.x / CA; var = t.y / CA - mean * mean;
    rstd = rsqrtf(var + EPS);
    for (int c = tid; c < CA; c += blockDim.x)
        g_lna[(long)r * CA + c] = (arow[c] - mean) * rstd;
}

// ---------------- common GEMM machinery (128x64 tile, BK=32) ----------------
#define APITCH 36
#define BPITCH 36
#define A_WORDS (128 * APITCH)               // 4608
#define B_WORDS (64 * BPITCH)                // 2304
#define SPITCH 68
#define STAGE_WORDS (128 * SPITCH)           // 8704

__device__ __forceinline__ void frag_compute(const uint32_t* As, const uint32_t* Bs,
        float (&acc)[2][4][4], int wr, int wc, int g4, int q4) {
    #pragma unroll
    for (int kc = 0; kc < 4; kc++) {
        int kb = kc * 8 + q4;
        uint32_t af[2][4];
        #pragma unroll
        for (int mt = 0; mt < 2; mt++) {
            int r = wr + mt * 16 + g4;
            af[mt][0] = As[r * APITCH + kb];
            af[mt][1] = As[(r + 8) * APITCH + kb];
            af[mt][2] = As[r * APITCH + kb + 4];
            af[mt][3] = As[(r + 8) * APITCH + kb + 4];
        }
        #pragma unroll
        for (int nt = 0; nt < 4; nt++) {
            int c = wc + nt * 8 + g4;
            uint32_t bf[2] = {Bs[c * BPITCH + kb], Bs[c * BPITCH + kb + 4]};
            #pragma unroll
            for (int mt = 0; mt < 2; mt++)
                mma_tf32(acc[mt][nt], af[mt], bf);
        }
    }
}

__device__ __forceinline__ void frag_compute2(const uint32_t* As, const uint32_t* Bs1,
        const uint32_t* Bs2, float (&acc1)[2][4][4], float (&acc2)[2][4][4],
        int wr, int wc, int g4, int q4) {
    #pragma unroll
    for (int kc = 0; kc < 4; kc++) {
        int kb = kc * 8 + q4;
        uint32_t af[2][4];
        #pragma unroll
        for (int mt = 0; mt < 2; mt++) {
            int r = wr + mt * 16 + g4;
            af[mt][0] = As[r * APITCH + kb];
            af[mt][1] = As[(r + 8) * APITCH + kb];
            af[mt][2] = As[r * APITCH + kb + 4];
            af[mt][3] = As[(r + 8) * APITCH + kb + 4];
        }
        #pragma unroll
        for (int nt = 0; nt < 4; nt++) {
            int c = wc + nt * 8 + g4;
            uint32_t b1[2] = {Bs1[c * BPITCH + kb], Bs1[c * BPITCH + kb + 4]};
            uint32_t b2[2] = {Bs2[c * BPITCH + kb], Bs2[c * BPITCH + kb + 4]};
            #pragma unroll
            for (int mt = 0; mt < 2; mt++) {
                mma_tf32(acc1[mt][nt], af[mt], b1);
                mma_tf32(acc2[mt][nt], af[mt], b2);
            }
        }
    }
}

__device__ __forceinline__ void stage_acc(float* st, const float (&acc)[2][4][4],
        int wr, int wc, int g4, int q4) {
    #pragma unroll
    for (int mt = 0; mt < 2; mt++) {
        #pragma unroll
        for (int nt = 0; nt < 4; nt++) {
            int rr = wr + mt * 16 + g4;
            int cc = wc + nt * 8 + 2 * q4;
            st[rr * SPITCH + cc]           = acc[mt][nt][0];
            st[rr * SPITCH + cc + 1]       = acc[mt][nt][1];
            st[(rr + 8) * SPITCH + cc]     = acc[mt][nt][2];
            st[(rr + 8) * SPITCH + cc + 1] = acc[mt][nt][3];
        }
    }
}

#define ZERO_ACC(acc) { \
    _Pragma("unroll") for (int i = 0; i < 2; i++) \
    _Pragma("unroll") for (int j = 0; j < 4; j++) \
    _Pragma("unroll") for (int t = 0; t < 4; t++) acc[i][j][t] = 0.f; }

#define LDGA(pa, Abase, lda, k0) { \
    _Pragma("unroll") for (int rep = 0; rep < 4; rep++) { \
        int lin = rep * 256 + tid; int r = lin >> 3, c4 = (lin & 7) * 4; \
        pa[rep] = *(const float4*)&(Abase)[(long)(row0 + r) * (lda) + (k0) + c4]; } }
#define STSA(As, pa) { \
    _Pragma("unroll") for (int rep = 0; rep < 4; rep++) { \
        int lin = rep * 256 + tid; int r = lin >> 3, c4 = (lin & 7) * 4; \
        uint32_t* dst = &(As)[r * APITCH + c4]; \
        dst[0] = f2tf32(pa[rep].x); dst[1] = f2tf32(pa[rep].y); \
        dst[2] = f2tf32(pa[rep].z); dst[3] = f2tf32(pa[rep].w); } }
#define LDGB(pb, Bbase, ldb, k0, c0) { \
    _Pragma("unroll") for (int rep = 0; rep < 8; rep++) { \
        int lin = rep * 256 + tid; int kk = lin >> 6, n = lin & 63; \
        pb[rep] = (Bbase)[(long)((k0) + kk) * (ldb) + (c0) + n]; } }
#define STSB(Bs, pb) { \
    _Pragma("unroll") for (int rep = 0; rep < 8; rep++) { \
        int lin = rep * 256 + tid; int kk = lin >> 6, n = lin & 63; \
        (Bs)[n * BPITCH + kk] = f2tf32(pb[rep]); } }

// ---------------- adaLN fused dual GEMM --------------------------------------
#define ADA_SMEM (2 * STAGE_WORDS * 4)   // 69632 B
__global__ void __launch_bounds__(256)
gemm_ada(const float* __restrict__ Wg_, const float* __restrict__ Wo_,
         const float* __restrict__ badag) {
    extern __shared__ float sm[];
    uint32_t* As  = (uint32_t*)sm;
    uint32_t* Bs1 = As + A_WORDS;
    uint32_t* Bs2 = Bs1 + B_WORDS;

    int tid = threadIdx.x, wid = tid >> 5;
    int g4 = (tid & 31) >> 2, q4 = tid & 3;
    int wr = (wid & 3) * 32, wc = (wid >> 2) * 32;
    int row0 = blockIdx.y * 128, col0 = blockIdx.x * 64;
    const float* A = g_sn;

    float acc1[2][4][4], acc2[2][4][4];
    ZERO_ACC(acc1); ZERO_ACC(acc2);
    float4 pa[4]; float pb1[8], pb2[8];

    LDGA(pa, A, CS, 0);
    LDGB(pb1, Wg_, CA, 0, col0);
    LDGB(pb2, Wo_, CA, 0, col0);
    const int KT = CS / 32;
    for (int kt = 0; kt < KT; kt++) {
        STSA(As, pa); STSB(Bs1, pb1); STSB(Bs2, pb2);
        __syncthreads();
        if (kt + 1 < KT) {
            int k0 = (kt + 1) * 32;
            LDGA(pa, A, CS, k0);
            LDGB(pb1, Wg_, CA, k0, col0);
            LDGB(pb2, Wo_, CA, k0, col0);
        }
        frag_compute2(As, Bs1, Bs2, acc1, acc2, wr, wc, g4, q4);
        __syncthreads();
    }

    float* st1 = sm;
    float* st2 = sm + STAGE_WORDS;
    stage_acc(st1, acc1, wr, wc, g4, q4);
    stage_acc(st2, acc2, wr, wc, g4, q4);
    __syncthreads();
    #pragma unroll
    for (int rep = 0; rep < 32; rep++) {
        int idx = rep * 256 + tid;
        int r = idx >> 6, c = idx & 63;
        int m = row0 + r, n = col0 + c;
        float v1 = st1[r * SPITCH + c], v2 = st2[r * SPITCH + c];
        g_an[(long)m * CA + n] = sigmoidf_(v1 + badag[n]) * g_lna[(long)m * CA + n] + v2;
    }
}

// ---------------- fused 4-way projection GEMM --------------------------------
#define PROJ_SMEM (STAGE_WORDS * 4)      // 34816 B
__global__ void __launch_bounds__(256)
gemm_proj4(const float* __restrict__ Wq, const float* __restrict__ Wk,
           const float* __restrict__ Wv, const float* __restrict__ Wg_,
           const float* __restrict__ bq) {
    extern __shared__ float sm[];
    uint32_t* As = (uint32_t*)sm;
    uint32_t* Bs = As + A_WORDS;

    int tid = threadIdx.x, wid = tid >> 5;
    int g4 = (tid & 31) >> 2, q4 = tid & 3;
    int wr = (wid & 3) * 32, wc = (wid >> 2) * 32;
    int row0 = blockIdx.y * 128;
    int cg = blockIdx.x * 64;
    int w = cg / CA, coln = cg % CA;
    const float* B = (w == 0) ? Wq : (w == 1) ? Wk : (w == 2) ? Wv : Wg_;
    const float* A = g_an;

    float acc[2][4][4];
    ZERO_ACC(acc);
    float4 pa[4]; float pb[8];

    LDGA(pa, A, CA, 0);
    LDGB(pb, B, CA, 0, coln);
    const int KT = CA / 32;
    for (int kt = 0; kt < KT; kt++) {
        STSA(As, pa); STSB(Bs, pb);
        __syncthreads();
        if (kt + 1 < KT) {
            int k0 = (kt + 1) * 32;
            LDGA(pa, A, CA, k0);
            LDGB(pb, B, CA, k0, coln);
        }
        frag_compute(As, Bs, acc, wr, wc, g4, q4);
        __syncthreads();
    }

    float* st = sm;
    stage_acc(st, acc, wr, wc, g4, q4);
    __syncthreads();
    float* dst = (w == 0) ? g_q : (w == 1) ? g_k : g_v;
    #pragma unroll
    for (int rep = 0; rep < 32; rep++) {
        int idx = rep * 256 + tid;
        int r = idx >> 6, c = idx & 63;
        int m = row0 + r, n = coln + c;
        float v = st[r * SPITCH + c];
        if (w == 3) {
            g_gate[(long)m * CA + n] = v;
        } else {
            if (w == 0) v += bq[n];
            int b = m / SS, si = m % SS, h = n / HD, d = n % HD;
            dst[(((long)(b * HH + h) * SS) + si) * HD + d] = v;
        }
    }
}

// ---------------- fused output GEMM ------------------------------------------
__global__ void __launch_bounds__(256)
gemm_final(const float* __restrict__ Wout, const float* __restrict__ s_,
           const float* __restrict__ Wsg, const float* __restrict__ bsg,
           float* __restrict__ out) {
    extern __shared__ float sm[];
    uint32_t* As = (uint32_t*)sm;
    uint32_t* Bs = As + A_WORDS;

    int tid = threadIdx.x, wid = tid >> 5;
    int g4 = (tid & 31) >> 2, q4 = tid & 3;
    int wr = (wid & 3) * 32, wc = (wid >> 2) * 32;
    int row0 = blockIdx.y * 128, col0 = blockIdx.x * 64;

    float acc1[2][4][4], acc2[2][4][4];
    ZERO_ACC(acc1); ZERO_ACC(acc2);
    float4 pa[4]; float pb[8];

    {
        const float* A = g_go;
        LDGA(pa, A, CA, 0);
        LDGB(pb, Wout, CA, 0, col0);
        const int KT = CA / 32;
        for (int kt = 0; kt < KT; kt++) {
            STSA(As, pa); STSB(Bs, pb);
            __syncthreads();
            if (kt + 1 < KT) {
                int k0 = (kt + 1) * 32;
                LDGA(pa, A, CA, k0);
                LDGB(pb, Wout, CA, k0, col0);
            }
            frag_compute(As, Bs, acc1, wr, wc, g4, q4);
            __syncthreads();
        }
    }
    {
        LDGA(pa, s_, CS, 0);
        LDGB(pb, Wsg, CA, 0, col0);
        const int KT = CS / 32;
        for (int kt = 0; kt < KT; kt++) {
            STSA(As, pa); STSB(Bs, pb);
            __syncthreads();
            if (kt + 1 < KT) {
                int k0 = (kt + 1) * 32;
                LDGA(pa, s_, CS, k0);
                LDGB(pb, Wsg, CA, k0, col0);
            }
            frag_compute(As, Bs, acc2, wr, wc, g4, q4);
            __syncthreads();
        }
    }

    #pragma unroll
    for (int mt = 0; mt < 2; mt++)
        #pragma unroll
        for (int nt = 0; nt < 4; nt++)
            #pragma unroll
            for (int t = 0; t < 4; t++) {
                int n = col0 + wc + nt * 8 + 2 * q4 + (t & 1);
                acc1[mt][nt][t] *= sigmoidf_(acc2[mt][nt][t] + __ldg(&bsg[n]));
            }

    float* st = sm;
    stage_acc(st, acc1, wr, wc, g4, q4);
    __syncthreads();
    #pragma unroll
    for (int rep = 0; rep < 32; rep++) {
        int idx = rep * 256 + tid;
        int r = idx >> 6, c = idx & 63;
        out[(long)(row0 + r) * CA + col0 + c] = st[r * SPITCH + c];
    }
}

// ---------------- pair bias v4: 64 rows/block for occupancy ------------------
// Block handles (b, p=j, q-tile of 64 i values). z slab contiguous (32KB).
// Output: g_bias[b][h][p][q0..q0+63] (contiguous per h).
#define ZP 132
#define PB_ZS_WORDS (64 * ZP)                        // 8448
#define PB_WB_OFF   PB_ZS_WORDS
#define PB_BETA_OFF (PB_WB_OFF + 16 * ZP)            // +2112 = 10560
#define PB_RES_OFF  (PB_BETA_OFF + 64 * 16)          // +1024 = 11584
#define PB_SMEM ((PB_RES_OFF + 64 * 17) * 4)         // 50688 B
__global__ void __launch_bounds__(256)
pairbias4_kernel(const float* __restrict__ z, const float* __restrict__ beta,
                 const float* __restrict__ Wb, const float* __restrict__ gz,
                 const float* __restrict__ bz) {
    extern __shared__ float smf[];
    uint32_t* Zs    = (uint32_t*)smf;
    uint32_t* Wbs   = Zs + PB_WB_OFF;
    float*    betas = smf + PB_BETA_OFF;
    float*    res   = smf + PB_RES_OFF;
    __shared__ float gzs[CZ], bzs[CZ];

    int tid = threadIdx.x, wid = tid >> 5, lane = tid & 31;
    int g4 = lane >> 2, q4 = lane & 3;
    int b = blockIdx.z, p = blockIdx.y, q0 = blockIdx.x * 64;

    const float* zb = z + ((long)(b * SS + p) * SS + q0) * CZ;
    const float* betab = beta + ((long)(b * SS + p) * SS + q0) * HH;

    // stage Wb (transposed) + gz/bz + beta slab (all contiguous loads)
    for (int idx = tid; idx < CZ * HH; idx += 256) {
        int k = idx >> 4, n = idx & 15;
        Wbs[n * ZP + k] = f2tf32(Wb[idx]);
    }
    for (int idx = tid; idx < CZ; idx += 256) { gzs[idx] = gz[idx]; bzs[idx] = bz[idx]; }
    #pragma unroll
    for (int rep = 0; rep < 4; rep++)
        betas[rep * 256 + tid] = betab[rep * 256 + tid];
    __syncthreads();   // gzs/bzs/Wbs visible to all threads before LN reads them

    // LN of 64 contiguous z-rows. Warp w: rows 8w..8w+7 (batched loads, MLP 8).
    {
        float4 vr[8];
        #pragma unroll
        for (int rr = 0; rr < 8; rr++) {
            int pl = wid * 8 + rr;
            vr[rr] = *(const float4*)&zb[(long)pl * CZ + lane * 4];
        }
        float sums[8], sqs[8];
        #pragma unroll
        for (int rr = 0; rr < 8; rr++) {
            float4 v = vr[rr];
            sums[rr] = v.x + v.y + v.z + v.w;
            sqs[rr]  = v.x * v.x + v.y * v.y + v.z * v.z + v.w * v.w;
        }
        #pragma unroll
        for (int o = 16; o; o >>= 1) {
            #pragma unroll
            for (int rr = 0; rr < 8; rr++) {
                sums[rr] += __shfl_xor_sync(0xffffffffu, sums[rr], o);
                sqs[rr]  += __shfl_xor_sync(0xffffffffu, sqs[rr],  o);
            }
        }
        #pragma unroll
        for (int rr = 0; rr < 8; rr++) {
            int pl = wid * 8 + rr;
            float mean = sums[rr] * (1.0f / CZ);
            float var  = sqs[rr] * (1.0f / CZ) - mean * mean;
            float rstd = rsqrtf(var + EPS);
            float4 v = vr[rr];
            int c = lane * 4;
            uint4 o4;
            o4.x = f2tf32((v.x - mean) * rstd * gzs[c + 0] + bzs[c + 0]);
            o4.y = f2tf32((v.y - mean) * rstd * gzs[c + 1] + bzs[c + 1]);
            o4.z = f2tf32((v.z - mean) * rstd * gzs[c + 2] + bzs[c + 2]);
            o4.w = f2tf32((v.w - mean) * rstd * gzs[c + 3] + bzs[c + 3]);
            *(uint4*)&Zs[pl * ZP + c] = o4;
        }
    }
    __syncthreads();

    // mma: [64 x 128] @ [128 x 16], warps 0..3, 16 rows each
    if (wid < 4) {
        int wr = wid * 16;
        float acc[2][4];
        #pragma unroll
        for (int nt = 0; nt < 2; nt++)
            #pragma unroll
            for (int t = 0; t < 4; t++) acc[nt][t] = 0.f;
        #pragma unroll
        for (int kc = 0; kc < 16; kc++) {
            int kb = kc * 8 + q4;
            uint32_t af[4];
            af[0] = Zs[(wr + g4) * ZP + kb];
            af[1] = Zs[(wr + g4 + 8) * ZP + kb];
            af[2] = Zs[(wr + g4) * ZP + kb + 4];
            af[3] = Zs[(wr + g4 + 8) * ZP + kb + 4];
            #pragma unroll
            for (int nt = 0; nt < 2; nt++) {
                uint32_t bf[2];
                bf[0] = Wbs[(nt * 8 + g4) * ZP + kb];
                bf[1] = Wbs[(nt * 8 + g4) * ZP + kb + 4];
                mma_tf32(acc[nt], af, bf);
            }
        }
        #pragma unroll
        for (int nt = 0; nt < 2; nt++) {
            #pragma unroll
            for (int t = 0; t < 4; t++) {
                int row = wr + g4 + ((t >= 2) ? 8 : 0);
                int h = nt * 8 + 2 * q4 + (t & 1);
                res[row * 17 + h] = acc[nt][t] + betas[row * 16 + h];
            }
        }
    }
    __syncthreads();

    // coalesced store: g_bias[b][h][p][q0+ql] (contiguous runs of 64 per h)
    #pragma unroll
    for (int rep = 0; rep < 4; rep++) {
        int idx = rep * 256 + tid;
        int h = idx >> 6, ql = idx & 63;
        g_bias[(((long)(b * HH + h) * SS) + p) * SS + q0 + ql] = res[ql * 17 + h];
    }
}

// ---------------- fused attention: softmax(scale*QK^T + bias) @ V, gated ----
// bias layout [b,h,j,i]; Ps and Bfc share one smem buffer (bias fully consumed
// into registers before Ps is written; one extra __syncthreads() in between).
#define QP 52
#define KP 52
#define VP 68
#define PP 68
#define BFP 132
#define AT_K (128 * QP)
#define AT_V (AT_K + 64 * KP)
#define AT_PB (AT_V + 48 * VP)
#define AT_WORDS (AT_PB + 128 * PP)          // Ps 8704 words >= Bfc 8448 words
#define ATT_SMEM (AT_WORDS * 4)              // 87808 B

__global__ void __launch_bounds__(256, 2)
attn_kernel(const float* __restrict__ qg, const float* __restrict__ kg,
            const float* __restrict__ vg, const float* __restrict__ biasg,
            const float* __restrict__ gateg, float* __restrict__ outg) {
    extern __shared__ char smem[];
    uint32_t* Qs = (uint32_t*)smem;
    uint32_t* Ks = Qs + AT_K;
    uint32_t* Vs = Qs + AT_V;
    uint32_t* Ps = Qs + AT_PB;
    float*    Bfc = (float*)(Qs + AT_PB);

    int tid = threadIdx.x, wid = tid >> 5, lane = tid & 31;
    int g4 = lane >> 2, q4 = lane & 3;
    int bh = blockIdx.y;
    int b = bh >> 4, h = bh & 15;
    int i0 = blockIdx.x * 128;
    const float* qb = qg + ((long)bh * SS + i0) * HD;
    const float* kb_ = kg + (long)bh * SS * HD;
    const float* vb = vg + (long)bh * SS * HD;
    const float* biasb = biasg + (long)bh * SS * SS;   // [j][i]

    #pragma unroll
    for (int rep = 0; rep < 6; rep++) {
        int idx = rep * 256 + tid;
        int r = idx / 12, c4 = (idx % 12) * 4;
        float4 v = *(const float4*)&qb[(long)r * HD + c4];
        uint32_t* d = &Qs[r * QP + c4];
        d[0] = f2tf32(v.x); d[1] = f2tf32(v.y); d[2] = f2tf32(v.z); d[3] = f2tf32(v.w);
    }

    int wr = wid * 16;
    float accO[6][4];
    #pragma unroll
    for (int n = 0; n < 6; n++)
        #pragma unroll
        for (int t = 0; t < 4; t++) accO[n][t] = 0.f;
    float mrow[2] = {-1e30f, -1e30f};
    float lrow[2] = {0.f, 0.f};

    for (int j = 0; j < 12; j++) {
        __syncthreads();
        #pragma unroll
        for (int rep = 0; rep < 3; rep++) {
            int idx = rep * 256 + tid;
            int r = idx / 12, c4 = (idx % 12) * 4;
            float4 v = *(const float4*)&kb_[(long)(j * 64 + r) * HD + c4];
            uint32_t* d = &Ks[r * KP + c4];
            d[0] = f2tf32(v.x); d[1] = f2tf32(v.y); d[2] = f2tf32(v.z); d[3] = f2tf32(v.w);
        }
        #pragma unroll
        for (int rep = 0; rep < 12; rep++) {
            int idx = rep * 256 + tid;
            int r = idx / 48, d = idx % 48;
            Vs[d * VP + r] = f2tf32(vb[(long)(j * 64 + r) * HD + d]);
        }
        // bias tile: [b,h,j0+c, i0+r], r contiguous in gmem -> column-major smem
        #pragma unroll
        for (int rep = 0; rep < 32; rep++) {
            int idx = rep * 256 + tid;
            int c = idx >> 7, r = idx & 127;
            Bfc[c * BFP + r] = biasb[(long)(j * 64 + c) * SS + i0 + r];
        }
        __syncthreads();

        float S[8][4];
        #pragma unroll
        for (int nt = 0; nt < 8; nt++)
            #pragma unroll
            for (int t = 0; t < 4; t++) S[nt][t] = 0.f;
        #pragma unroll
        for (int kc = 0; kc < 6; kc++) {
            int kbx = kc * 8 + q4;
            uint32_t af[4];
            af[0] = Qs[(wr + g4) * QP + kbx];
            af[1] = Qs[(wr + g4 + 8) * QP + kbx];
            af[2] = Qs[(wr + g4) * QP + kbx + 4];
            af[3] = Qs[(wr + g4 + 8) * QP + kbx + 4];
            #pragma unroll
            for (int nt = 0; nt < 8; nt++) {
                uint32_t bf2[2];
                bf2[0] = Ks[(nt * 8 + g4) * KP + kbx];
                bf2[1] = Ks[(nt * 8 + g4) * KP + kbx + 4];
                mma_tf32(S[nt], af, bf2);
            }
        }
        int r0 = wr + g4, r1 = r0 + 8;
        float mn0 = mrow[0], mn1 = mrow[1];
        #pragma unroll
        for (int nt = 0; nt < 8; nt++) {
            #pragma unroll
            for (int t = 0; t < 4; t++) {
                int rr = (t >= 2) ? r1 : r0;
                int cc = nt * 8 + 2 * q4 + (t & 1);
                float val = S[nt][t] * SCALE + Bfc[cc * BFP + rr];
                S[nt][t] = val;
                if (t < 2) mn0 = fmaxf(mn0, val); else mn1 = fmaxf(mn1, val);
            }
        }
        __syncthreads();   // bias fully consumed; Ps may now overwrite the buffer
        mn0 = fmaxf(mn0, __shfl_xor_sync(0xffffffffu, mn0, 1));
        mn0 = fmaxf(mn0, __shfl_xor_sync(0xffffffffu, mn0, 2));
        mn1 = fmaxf(mn1, __shfl_xor_sync(0xffffffffu, mn1, 1));
        mn1 = fmaxf(mn1, __shfl_xor_sync(0xffffffffu, mn1, 2));
        float al0 = __expf(mrow[0] - mn0);
        float al1 = __expf(mrow[1] - mn1);
        mrow[0] = mn0; mrow[1] = mn1;
        float s0 = 0.f, s1 = 0.f;
        #pragma unroll
        for (int nt = 0; nt < 8; nt++) {
            #pragma unroll
            for (int t = 0; t < 4; t++) {
                float p = __expf(S[nt][t] - ((t >= 2) ? mn1 : mn0));
                S[nt][t] = p;
                if (t < 2) s0 += p; else s1 += p;
                int rr = (t >= 2) ? r1 : r0;
                int cc = nt * 8 + 2 * q4 + (t & 1);
                Ps[rr * PP + cc] = f2tf32(p);
            }
        }
        s0 += __shfl_xor_sync(0xffffffffu, s0, 1);
        s0 += __shfl_xor_sync(0xffffffffu, s0, 2);
        s1 += __shfl_xor_sync(0xffffffffu, s1, 1);
        s1 += __shfl_xor_sync(0xffffffffu, s1, 2);
        lrow[0] = lrow[0] * al0 + s0;
        lrow[1] = lrow[1] * al1 + s1;
        #pragma unroll
        for (int n = 0; n < 6; n++) {
            accO[n][0] *= al0; accO[n][1] *= al0;
            accO[n][2] *= al1; accO[n][3] *= al1;
        }
        __syncwarp();
        #pragma unroll
        for (int kc = 0; kc < 8; kc++) {
            int kbx = kc * 8 + q4;
            uint32_t af[4];
            af[0] = Ps[(wr + g4) * PP + kbx];
            af[1] = Ps[(wr + g4 + 8) * PP + kbx];
            af[2] = Ps[(wr + g4) * PP + kbx + 4];
            af[3] = Ps[(wr + g4 + 8) * PP + kbx + 4];
            #pragma unroll
            for (int n = 0; n < 6; n++) {
                uint32_t bf2[2];
                bf2[0] = Vs[(n * 8 + g4) * VP + kbx];
                bf2[1] = Vs[(n * 8 + g4) * VP + kbx + 4];
                mma_tf32(accO[n], af, bf2);
            }
        }
    }

    float inv0 = 1.0f / lrow[0], inv1 = 1.0f / lrow[1];
    #pragma unroll
    for (int n = 0; n < 6; n++) {
        #pragma unroll
        for (int t = 0; t < 4; t++) {
            int r = wr + g4 + ((t >= 2) ? 8 : 0);
            int c = n * 8 + 2 * q4 + (t & 1);
            long gi = ((long)(b * SS + i0 + r)) * CA + h * HD + c;
            float o = accO[n][t] * ((t >= 2) ? inv1 : inv0);
            outg[gi] = o * sigmoidf_(gateg[gi]);
        }
    }
}

// ---------------- host side --------------------------------------------------
static float* sym(const void* symbol) {
    void* p = nullptr;
    cudaGetSymbolAddress(&p, symbol);
    return (float*)p;
}

extern "C" void kernel_launch(void* const* d_in, const int* in_sizes, int n_in,
                              void* d_out, int out_size) {
    const float* a        = (const float*)d_in[0];
    const float* s        = (const float*)d_in[1];
    const float* z        = (const float*)d_in[2];
    const float* beta     = (const float*)d_in[3];
    const float* gamma_s  = (const float*)d_in[4];
    const float* W_ada_g  = (const float*)d_in[5];
    const float* b_ada_g  = (const float*)d_in[6];
    const float* W_ada_o  = (const float*)d_in[7];
    const float* Wq       = (const float*)d_in[8];
    const float* bq       = (const float*)d_in[9];
    const float* Wk       = (const float*)d_in[10];
    const float* Wv       = (const float*)d_in[11];
    const float* Wb       = (const float*)d_in[12];
    const float* gz       = (const float*)d_in[13];
    const float* bz       = (const float*)d_in[14];
    const float* Wg       = (const float*)d_in[15];
    const float* Wout     = (const float*)d_in[16];
    const float* Ws_gate  = (const float*)d_in[17];
    const float* bs_gate  = (const float*)d_in[18];
    float* out = (float*)d_out;

    float* p_q    = sym(g_q);
    float* p_k    = sym(g_k);
    float* p_v    = sym(g_v);
    float* p_gate = sym(g_gate);
    float* p_bias = sym(g_bias);
    float* p_go   = sym(g_go);

    cudaFuncSetAttribute(gemm_ada,        cudaFuncAttributeMaxDynamicSharedMemorySize, ADA_SMEM);
    cudaFuncSetAttribute(gemm_proj4,      cudaFuncAttributeMaxDynamicSharedMemorySize, PROJ_SMEM);
    cudaFuncSetAttribute(gemm_final,      cudaFuncAttributeMaxDynamicSharedMemorySize, PROJ_SMEM);
    cudaFuncSetAttribute(pairbias4_kernel,cudaFuncAttributeMaxDynamicSharedMemorySize, PB_SMEM);
    cudaFuncSetAttribute(attn_kernel,     cudaFuncAttributeMaxDynamicSharedMemorySize, ATT_SMEM);

    // 1. layer norms
    ln_kernel<<<MM, 256>>>(s, a, gamma_s);
    // 2. adaLN (fused dual GEMM)
    gemm_ada<<<dim3(CA / 64, MM / 128), 256, ADA_SMEM>>>(W_ada_g, W_ada_o, b_ada_g);
    // 3. 4-way projections
    gemm_proj4<<<dim3(4 * CA / 64, MM / 128), 256, PROJ_SMEM>>>(Wq, Wk, Wv, Wg, bq);
    // 4. pair bias (64-row blocks, streaming layout)
    pairbias4_kernel<<<dim3(SS / 64, SS, BB), 256, PB_SMEM>>>(z, beta, Wb, gz, bz);
    // 5. fused attention
    attn_kernel<<<dim3(SS / 128, BB * HH), 256, ATT_SMEM>>>(p_q, p_k, p_v, p_bias, p_gate, p_go);
    // 6. fused output GEMM + s-gate
    gemm_final<<<dim3(CA / 64, MM / 128), 256, PROJ_SMEM>>>(Wout, s, Ws_gate, bs_gate, out);
}

// round 9
// speedup vs baseline: 3.1073x; 1.0490x over previous
#include <cuda_runtime.h>
#include <cuda_bf16.h>
#include <math.h>
#include <cstdint>

// Problem constants
#define BB   2
#define SS   768
#define CA   768
#define CS   384
#define CZ   128
#define HH   16
#define HD   48
#define MM   (BB*SS)          // 1536
#define EPS  1e-5f
#define SCALE (0.14433756729740643f)  // 1/sqrt(48)

// ---------------- scratch (device globals) ----------------------------------
__device__ float g_sn   [MM*CS];
__device__ float g_lna  [MM*CA];
__device__ float g_an   [MM*CA];
__device__ float g_q    [BB*HH*SS*HD];      // [b,h,s,d]
__device__ float g_k    [BB*HH*SS*HD];      // [b,h,s,d]
__device__ float g_v    [BB*HH*SS*HD];      // [b,h,s,d]
__device__ float g_gate [MM*CA];
__device__ float g_bias [BB*HH*SS*SS];      // pair bias, layout [b,h,j,i] (i contiguous)
__device__ float g_go   [MM*CA];

// ---------------- helpers ----------------------------------------------------
__device__ __forceinline__ float sigmoidf_(float x) { return 1.0f / (1.0f + expf(-x)); }

__device__ __forceinline__ uint32_t f2tf32(float f) {
    uint32_t r;
    asm("cvt.rna.tf32.f32 %0, %1;" : "=r"(r) : "f"(f));
    return r;
}

__device__ __forceinline__ void mma_tf32(float* d, const uint32_t* a, const uint32_t* b) {
    asm volatile("mma.sync.aligned.m16n8k8.row.col.f32.tf32.tf32.f32 "
        "{%0,%1,%2,%3}, {%4,%5,%6,%7}, {%8,%9}, {%0,%1,%2,%3};"
        : "+f"(d[0]), "+f"(d[1]), "+f"(d[2]), "+f"(d[3])
        : "r"(a[0]), "r"(a[1]), "r"(a[2]), "r"(a[3]), "r"(b[0]), "r"(b[1]));
}

__device__ float2 blockReduceSum2(float a, float b) {
    __shared__ float sa[32], sb[32];
    int lane = threadIdx.x & 31, wid = threadIdx.x >> 5;
    #pragma unroll
    for (int o = 16; o; o >>= 1) {
        a += __shfl_xor_sync(0xffffffffu, a, o);
        b += __shfl_xor_sync(0xffffffffu, b, o);
    }
    if (lane == 0) { sa[wid] = a; sb[wid] = b; }
    __syncthreads();
    if (wid == 0) {
        int nw = (blockDim.x + 31) >> 5;
        a = (lane < nw) ? sa[lane] : 0.0f;
        b = (lane < nw) ? sb[lane] : 0.0f;
        #pragma unroll
        for (int o = 16; o; o >>= 1) {
            a += __shfl_xor_sync(0xffffffffu, a, o);
            b += __shfl_xor_sync(0xffffffffu, b, o);
        }
        if (lane == 0) { sa[0] = a; sb[0] = b; }
    }
    __syncthreads();
    float2 r = make_float2(sa[0], sb[0]);
    __syncthreads();
    return r;
}

// ---------------- LN kernel --------------------------------------------------
__global__ void ln_kernel(const float* __restrict__ s, const float* __restrict__ a,
                          const float* __restrict__ gamma_s) {
    int r = blockIdx.x;
    int tid = threadIdx.x;
    const float* srow = s + (long)r * CS;
    float sum = 0.f, sq = 0.f;
    for (int c = tid; c < CS; c += blockDim.x) { float v = srow[c]; sum += v; sq += v * v; }
    float2 t = blockReduceSum2(sum, sq);
    float mean = t.x / CS, var = t.y / CS - mean * mean;
    float rstd = rsqrtf(var + EPS);
    for (int c = tid; c < CS; c += blockDim.x)
        g_sn[(long)r * CS + c] = (srow[c] - mean) * rstd * gamma_s[c];

    const float* arow = a + (long)r * CA;
    sum = 0.f; sq = 0.f;
    for (int c = tid; c < CA; c += blockDim.x) { float v = arow[c]; sum += v; sq += v * v; }
    t = blockReduceSum2(sum, sq);
    mean = t.x / CA; var = t.y / CA - mean * mean;
    rstd = rsqrtf(var + EPS);
    for (int c = tid; c < CA; c += blockDim.x)
        g_lna[(long)r * CA + c] = (arow[c] - mean) * rstd;
}

// ---------------- common GEMM machinery (128x64 tile, BK=32) ----------------
#define APITCH 36
#define BPITCH 36
#define A_WORDS (128 * APITCH)               // 4608
#define B_WORDS (64 * BPITCH)                // 2304
#define SPITCH 68
#define STAGE_WORDS (128 * SPITCH)           // 8704

__device__ __forceinline__ void frag_compute(const uint32_t* As, const uint32_t* Bs,
        float (&acc)[2][4][4], int wr, int wc, int g4, int q4) {
    #pragma unroll
    for (int kc = 0; kc < 4; kc++) {
        int kb = kc * 8 + q4;
        uint32_t af[2][4];
        #pragma unroll
        for (int mt = 0; mt < 2; mt++) {
            int r = wr + mt * 16 + g4;
            af[mt][0] = As[r * APITCH + kb];
            af[mt][1] = As[(r + 8) * APITCH + kb];
            af[mt][2] = As[r * APITCH + kb + 4];
            af[mt][3] = As[(r + 8) * APITCH + kb + 4];
        }
        #pragma unroll
        for (int nt = 0; nt < 4; nt++) {
            int c = wc + nt * 8 + g4;
            uint32_t bf[2] = {Bs[c * BPITCH + kb], Bs[c * BPITCH + kb + 4]};
            #pragma unroll
            for (int mt = 0; mt < 2; mt++)
                mma_tf32(acc[mt][nt], af[mt], bf);
        }
    }
}

__device__ __forceinline__ void frag_compute2(const uint32_t* As, const uint32_t* Bs1,
        const uint32_t* Bs2, float (&acc1)[2][4][4], float (&acc2)[2][4][4],
        int wr, int wc, int g4, int q4) {
    #pragma unroll
    for (int kc = 0; kc < 4; kc++) {
        int kb = kc * 8 + q4;
        uint32_t af[2][4];
        #pragma unroll
        for (int mt = 0; mt < 2; mt++) {
            int r = wr + mt * 16 + g4;
            af[mt][0] = As[r * APITCH + kb];
            af[mt][1] = As[(r + 8) * APITCH + kb];
            af[mt][2] = As[r * APITCH + kb + 4];
            af[mt][3] = As[(r + 8) * APITCH + kb + 4];
        }
        #pragma unroll
        for (int nt = 0; nt < 4; nt++) {
            int c = wc + nt * 8 + g4;
            uint32_t b1[2] = {Bs1[c * BPITCH + kb], Bs1[c * BPITCH + kb + 4]};
            uint32_t b2[2] = {Bs2[c * BPITCH + kb], Bs2[c * BPITCH + kb + 4]};
            #pragma unroll
            for (int mt = 0; mt < 2; mt++) {
                mma_tf32(acc1[mt][nt], af[mt], b1);
                mma_tf32(acc2[mt][nt], af[mt], b2);
            }
        }
    }
}

__device__ __forceinline__ void stage_acc(float* st, const float (&acc)[2][4][4],
        int wr, int wc, int g4, int q4) {
    #pragma unroll
    for (int mt = 0; mt < 2; mt++) {
        #pragma unroll
        for (int nt = 0; nt < 4; nt++) {
            int rr = wr + mt * 16 + g4;
            int cc = wc + nt * 8 + 2 * q4;
            st[rr * SPITCH + cc]           = acc[mt][nt][0];
            st[rr * SPITCH + cc + 1]       = acc[mt][nt][1];
            st[(rr + 8) * SPITCH + cc]     = acc[mt][nt][2];
            st[(rr + 8) * SPITCH + cc + 1] = acc[mt][nt][3];
        }
    }
}

#define ZERO_ACC(acc) { \
    _Pragma("unroll") for (int i = 0; i < 2; i++) \
    _Pragma("unroll") for (int j = 0; j < 4; j++) \
    _Pragma("unroll") for (int t = 0; t < 4; t++) acc[i][j][t] = 0.f; }

#define LDGA(pa, Abase, lda, k0) { \
    _Pragma("unroll") for (int rep = 0; rep < 4; rep++) { \
        int lin = rep * 256 + tid; int r = lin >> 3, c4 = (lin & 7) * 4; \
        pa[rep] = *(const float4*)&(Abase)[(long)(row0 + r) * (lda) + (k0) + c4]; } }
#define STSA(As, pa) { \
    _Pragma("unroll") for (int rep = 0; rep < 4; rep++) { \
        int lin = rep * 256 + tid; int r = lin >> 3, c4 = (lin & 7) * 4; \
        uint32_t* dst = &(As)[r * APITCH + c4]; \
        dst[0] = f2tf32(pa[rep].x); dst[1] = f2tf32(pa[rep].y); \
        dst[2] = f2tf32(pa[rep].z); dst[3] = f2tf32(pa[rep].w); } }
#define LDGB(pb, Bbase, ldb, k0, c0) { \
    _Pragma("unroll") for (int rep = 0; rep < 8; rep++) { \
        int lin = rep * 256 + tid; int kk = lin >> 6, n = lin & 63; \
        pb[rep] = (Bbase)[(long)((k0) + kk) * (ldb) + (c0) + n]; } }
#define STSB(Bs, pb) { \
    _Pragma("unroll") for (int rep = 0; rep < 8; rep++) { \
        int lin = rep * 256 + tid; int kk = lin >> 6, n = lin & 63; \
        (Bs)[n * BPITCH + kk] = f2tf32(pb[rep]); } }

// ---------------- adaLN fused dual GEMM --------------------------------------
#define ADA_SMEM (2 * STAGE_WORDS * 4)   // 69632 B
__global__ void __launch_bounds__(256)
gemm_ada(const float* __restrict__ Wg_, const float* __restrict__ Wo_,
         const float* __restrict__ badag) {
    extern __shared__ float sm[];
    uint32_t* As  = (uint32_t*)sm;
    uint32_t* Bs1 = As + A_WORDS;
    uint32_t* Bs2 = Bs1 + B_WORDS;

    int tid = threadIdx.x, wid = tid >> 5;
    int g4 = (tid & 31) >> 2, q4 = tid & 3;
    int wr = (wid & 3) * 32, wc = (wid >> 2) * 32;
    int row0 = blockIdx.y * 128, col0 = blockIdx.x * 64;
    const float* A = g_sn;

    float acc1[2][4][4], acc2[2][4][4];
    ZERO_ACC(acc1); ZERO_ACC(acc2);
    float4 pa[4]; float pb1[8], pb2[8];

    LDGA(pa, A, CS, 0);
    LDGB(pb1, Wg_, CA, 0, col0);
    LDGB(pb2, Wo_, CA, 0, col0);
    const int KT = CS / 32;
    for (int kt = 0; kt < KT; kt++) {
        STSA(As, pa); STSB(Bs1, pb1); STSB(Bs2, pb2);
        __syncthreads();
        if (kt + 1 < KT) {
            int k0 = (kt + 1) * 32;
            LDGA(pa, A, CS, k0);
            LDGB(pb1, Wg_, CA, k0, col0);
            LDGB(pb2, Wo_, CA, k0, col0);
        }
        frag_compute2(As, Bs1, Bs2, acc1, acc2, wr, wc, g4, q4);
        __syncthreads();
    }

    float* st1 = sm;
    float* st2 = sm + STAGE_WORDS;
    stage_acc(st1, acc1, wr, wc, g4, q4);
    stage_acc(st2, acc2, wr, wc, g4, q4);
    __syncthreads();
    #pragma unroll
    for (int rep = 0; rep < 32; rep++) {
        int idx = rep * 256 + tid;
        int r = idx >> 6, c = idx & 63;
        int m = row0 + r, n = col0 + c;
        float v1 = st1[r * SPITCH + c], v2 = st2[r * SPITCH + c];
        g_an[(long)m * CA + n] = sigmoidf_(v1 + badag[n]) * g_lna[(long)m * CA + n] + v2;
    }
}

// ---------------- fused 4-way projection GEMM --------------------------------
#define PROJ_SMEM (STAGE_WORDS * 4)      // 34816 B
__global__ void __launch_bounds__(256)
gemm_proj4(const float* __restrict__ Wq, const float* __restrict__ Wk,
           const float* __restrict__ Wv, const float* __restrict__ Wg_,
           const float* __restrict__ bq) {
    extern __shared__ float sm[];
    uint32_t* As = (uint32_t*)sm;
    uint32_t* Bs = As + A_WORDS;

    int tid = threadIdx.x, wid = tid >> 5;
    int g4 = (tid & 31) >> 2, q4 = tid & 3;
    int wr = (wid & 3) * 32, wc = (wid >> 2) * 32;
    int row0 = blockIdx.y * 128;
    int cg = blockIdx.x * 64;
    int w = cg / CA, coln = cg % CA;
    const float* B = (w == 0) ? Wq : (w == 1) ? Wk : (w == 2) ? Wv : Wg_;
    const float* A = g_an;

    float acc[2][4][4];
    ZERO_ACC(acc);
    float4 pa[4]; float pb[8];

    LDGA(pa, A, CA, 0);
    LDGB(pb, B, CA, 0, coln);
    const int KT = CA / 32;
    for (int kt = 0; kt < KT; kt++) {
        STSA(As, pa); STSB(Bs, pb);
        __syncthreads();
        if (kt + 1 < KT) {
            int k0 = (kt + 1) * 32;
            LDGA(pa, A, CA, k0);
            LDGB(pb, B, CA, k0, coln);
        }
        frag_compute(As, Bs, acc, wr, wc, g4, q4);
        __syncthreads();
    }

    float* st = sm;
    stage_acc(st, acc, wr, wc, g4, q4);
    __syncthreads();
    float* dst = (w == 0) ? g_q : (w == 1) ? g_k : g_v;
    #pragma unroll
    for (int rep = 0; rep < 32; rep++) {
        int idx = rep * 256 + tid;
        int r = idx >> 6, c = idx & 63;
        int m = row0 + r, n = coln + c;
        float v = st[r * SPITCH + c];
        if (w == 3) {
            g_gate[(long)m * CA + n] = v;
        } else {
            if (w == 0) v += bq[n];
            int b = m / SS, si = m % SS, h = n / HD, d = n % HD;
            dst[(((long)(b * HH + h) * SS) + si) * HD + d] = v;
        }
    }
}

// ---------------- fused output GEMM ------------------------------------------
__global__ void __launch_bounds__(256)
gemm_final(const float* __restrict__ Wout, const float* __restrict__ s_,
           const float* __restrict__ Wsg, const float* __restrict__ bsg,
           float* __restrict__ out) {
    extern __shared__ float sm[];
    uint32_t* As = (uint32_t*)sm;
    uint32_t* Bs = As + A_WORDS;

    int tid = threadIdx.x, wid = tid >> 5;
    int g4 = (tid & 31) >> 2, q4 = tid & 3;
    int wr = (wid & 3) * 32, wc = (wid >> 2) * 32;
    int row0 = blockIdx.y * 128, col0 = blockIdx.x * 64;

    float acc1[2][4][4], acc2[2][4][4];
    ZERO_ACC(acc1); ZERO_ACC(acc2);
    float4 pa[4]; float pb[8];

    {
        const float* A = g_go;
        LDGA(pa, A, CA, 0);
        LDGB(pb, Wout, CA, 0, col0);
        const int KT = CA / 32;
        for (int kt = 0; kt < KT; kt++) {
            STSA(As, pa); STSB(Bs, pb);
            __syncthreads();
            if (kt + 1 < KT) {
                int k0 = (kt + 1) * 32;
                LDGA(pa, A, CA, k0);
                LDGB(pb, Wout, CA, k0, col0);
            }
            frag_compute(As, Bs, acc1, wr, wc, g4, q4);
            __syncthreads();
        }
    }
    {
        LDGA(pa, s_, CS, 0);
        LDGB(pb, Wsg, CA, 0, col0);
        const int KT = CS / 32;
        for (int kt = 0; kt < KT; kt++) {
            STSA(As, pa); STSB(Bs, pb);
            __syncthreads();
            if (kt + 1 < KT) {
                int k0 = (kt + 1) * 32;
                LDGA(pa, s_, CS, k0);
                LDGB(pb, Wsg, CA, k0, col0);
            }
            frag_compute(As, Bs, acc2, wr, wc, g4, q4);
            __syncthreads();
        }
    }

    #pragma unroll
    for (int mt = 0; mt < 2; mt++)
        #pragma unroll
        for (int nt = 0; nt < 4; nt++)
            #pragma unroll
            for (int t = 0; t < 4; t++) {
                int n = col0 + wc + nt * 8 + 2 * q4 + (t & 1);
                acc1[mt][nt][t] *= sigmoidf_(acc2[mt][nt][t] + __ldg(&bsg[n]));
            }

    float* st = sm;
    stage_acc(st, acc1, wr, wc, g4, q4);
    __syncthreads();
    #pragma unroll
    for (int rep = 0; rep < 32; rep++) {
        int idx = rep * 256 + tid;
        int r = idx >> 6, c = idx & 63;
        out[(long)(row0 + r) * CA + col0 + c] = st[r * SPITCH + c];
    }
}

// ---------------- pair bias v5: 5 CTAs/SM + all-warp MMA ---------------------
// Block handles (b, p=j, q-tile of 64 i values). z slab contiguous (32KB).
// smem: Zs[64*ZP] (res[64*17] aliased on top after MMA) + Wbs[16*ZP] = 42240 B.
// beta preloaded into 4 regs/thread (linear coalesced), added after MMA.
// Output: g_bias[b][h][p][q0..q0+63] (contiguous per h).
#define ZP 132
#define PB_ZS_WORDS (64 * ZP)                        // 8448
#define PB_WB_OFF   PB_ZS_WORDS                      // 8448
#define PB_SMEM ((PB_ZS_WORDS + 16 * ZP) * 4)        // 42240 B
__global__ void __launch_bounds__(256)
pairbias5_kernel(const float* __restrict__ z, const float* __restrict__ beta,
                 const float* __restrict__ Wb, const float* __restrict__ gz,
                 const float* __restrict__ bz) {
    extern __shared__ float smf[];
    uint32_t* Zs  = (uint32_t*)smf;
    uint32_t* Wbs = Zs + PB_WB_OFF;
    float*    res = smf;                 // aliased over Zs after MMA reads finish
    __shared__ float gzs[CZ], bzs[CZ];

    int tid = threadIdx.x, wid = tid >> 5, lane = tid & 31;
    int g4 = lane >> 2, q4 = lane & 3;
    int b = blockIdx.z, p = blockIdx.y, q0 = blockIdx.x * 64;

    const float* zb = z + ((long)(b * SS + p) * SS + q0) * CZ;
    const float* betab = beta + ((long)(b * SS + p) * SS + q0) * HH;

    // preload beta slab (1024 consecutive floats) into regs, coalesced
    float betar[4];
    #pragma unroll
    for (int rep = 0; rep < 4; rep++)
        betar[rep] = betab[rep * 256 + tid];

    // stage Wb (transposed) + gz/bz
    for (int idx = tid; idx < CZ * HH; idx += 256) {
        int k = idx >> 4, n = idx & 15;
        Wbs[n * ZP + k] = f2tf32(Wb[idx]);
    }
    for (int idx = tid; idx < CZ; idx += 256) { gzs[idx] = gz[idx]; bzs[idx] = bz[idx]; }
    __syncthreads();

    // LN of 64 contiguous z-rows. Warp w: rows 8w..8w+7 (batched loads, MLP 8).
    {
        float4 vr[8];
        #pragma unroll
        for (int rr = 0; rr < 8; rr++) {
            int pl = wid * 8 + rr;
            vr[rr] = *(const float4*)&zb[(long)pl * CZ + lane * 4];
        }
        float sums[8], sqs[8];
        #pragma unroll
        for (int rr = 0; rr < 8; rr++) {
            float4 v = vr[rr];
            sums[rr] = v.x + v.y + v.z + v.w;
            sqs[rr]  = v.x * v.x + v.y * v.y + v.z * v.z + v.w * v.w;
        }
        #pragma unroll
        for (int o = 16; o; o >>= 1) {
            #pragma unroll
            for (int rr = 0; rr < 8; rr++) {
                sums[rr] += __shfl_xor_sync(0xffffffffu, sums[rr], o);
                sqs[rr]  += __shfl_xor_sync(0xffffffffu, sqs[rr],  o);
            }
        }
        #pragma unroll
        for (int rr = 0; rr < 8; rr++) {
            int pl = wid * 8 + rr;
            float mean = sums[rr] * (1.0f / CZ);
            float var  = sqs[rr] * (1.0f / CZ) - mean * mean;
            float rstd = rsqrtf(var + EPS);
            float4 v = vr[rr];
            int c = lane * 4;
            uint4 o4;
            o4.x = f2tf32((v.x - mean) * rstd * gzs[c + 0] + bzs[c + 0]);
            o4.y = f2tf32((v.y - mean) * rstd * gzs[c + 1] + bzs[c + 1]);
            o4.z = f2tf32((v.z - mean) * rstd * gzs[c + 2] + bzs[c + 2]);
            o4.w = f2tf32((v.w - mean) * rstd * gzs[c + 3] + bzs[c + 3]);
            *(uint4*)&Zs[pl * ZP + c] = o4;
        }
    }
    __syncthreads();

    // mma: [64 x 128] @ [128 x 16], ALL 8 warps.
    // warp w: row-group (w&3)*16, h-half (w>>2)*8. 16 kc x 1 n-tile each.
    float acc[4];
    #pragma unroll
    for (int t = 0; t < 4; t++) acc[t] = 0.f;
    {
        int wr = (wid & 3) * 16;
        int hb = (wid >> 2) * 8;
        #pragma unroll
        for (int kc = 0; kc < 16; kc++) {
            int kb = kc * 8 + q4;
            uint32_t af[4];
            af[0] = Zs[(wr + g4) * ZP + kb];
            af[1] = Zs[(wr + g4 + 8) * ZP + kb];
            af[2] = Zs[(wr + g4) * ZP + kb + 4];
            af[3] = Zs[(wr + g4 + 8) * ZP + kb + 4];
            uint32_t bf[2];
            bf[0] = Wbs[(hb + g4) * ZP + kb];
            bf[1] = Wbs[(hb + g4) * ZP + kb + 4];
            mma_tf32(acc, af, bf);
        }
    }
    __syncthreads();   // all Zs reads done; res may alias Zs now

    // write res[row*17 + h]
    {
        int wr = (wid & 3) * 16;
        int hb = (wid >> 2) * 8;
        #pragma unroll
        for (int t = 0; t < 4; t++) {
            int row = wr + g4 + ((t >= 2) ? 8 : 0);
            int h = hb + 2 * q4 + (t & 1);
            res[row * 17 + h] = acc[t];
        }
    }
    __syncthreads();

    // add beta (linear mapping: idx = ql*16 + h)
    #pragma unroll
    for (int rep = 0; rep < 4; rep++) {
        int idx = rep * 256 + tid;
        int ql = idx >> 4, hh = idx & 15;
        res[ql * 17 + hh] += betar[rep];
    }
    __syncthreads();

    // coalesced store: g_bias[b][h][p][q0+ql] (contiguous runs of 64 per h)
    #pragma unroll
    for (int rep = 0; rep < 4; rep++) {
        int idx = rep * 256 + tid;
        int h = idx >> 6, ql = idx & 63;
        g_bias[(((long)(b * HH + h) * SS) + p) * SS + q0 + ql] = res[ql * 17 + h];
    }
}

// ---------------- fused attention: softmax(scale*QK^T + bias) @ V, gated ----
// bias layout [b,h,j,i]; Ps and Bfc share one smem buffer (bias fully consumed
// into registers before Ps is written; one extra __syncthreads() in between).
#define QP 52
#define KP 52
#define VP 68
#define PP 68
#define BFP 132
#define AT_K (128 * QP)
#define AT_V (AT_K + 64 * KP)
#define AT_PB (AT_V + 48 * VP)
#define AT_WORDS (AT_PB + 128 * PP)          // Ps 8704 words >= Bfc 8448 words
#define ATT_SMEM (AT_WORDS * 4)              // 87808 B

__global__ void __launch_bounds__(256, 2)
attn_kernel(const float* __restrict__ qg, const float* __restrict__ kg,
            const float* __restrict__ vg, const float* __restrict__ biasg,
            const float* __restrict__ gateg, float* __restrict__ outg) {
    extern __shared__ char smem[];
    uint32_t* Qs = (uint32_t*)smem;
    uint32_t* Ks = Qs + AT_K;
    uint32_t* Vs = Qs + AT_V;
    uint32_t* Ps = Qs + AT_PB;
    float*    Bfc = (float*)(Qs + AT_PB);

    int tid = threadIdx.x, wid = tid >> 5, lane = tid & 31;
    int g4 = lane >> 2, q4 = lane & 3;
    int bh = blockIdx.y;
    int b = bh >> 4, h = bh & 15;
    int i0 = blockIdx.x * 128;
    const float* qb = qg + ((long)bh * SS + i0) * HD;
    const float* kb_ = kg + (long)bh * SS * HD;
    const float* vb = vg + (long)bh * SS * HD;
    const float* biasb = biasg + (long)bh * SS * SS;   // [j][i]

    #pragma unroll
    for (int rep = 0; rep < 6; rep++) {
        int idx = rep * 256 + tid;
        int r = idx / 12, c4 = (idx % 12) * 4;
        float4 v = *(const float4*)&qb[(long)r * HD + c4];
        uint32_t* d = &Qs[r * QP + c4];
        d[0] = f2tf32(v.x); d[1] = f2tf32(v.y); d[2] = f2tf32(v.z); d[3] = f2tf32(v.w);
    }

    int wr = wid * 16;
    float accO[6][4];
    #pragma unroll
    for (int n = 0; n < 6; n++)
        #pragma unroll
        for (int t = 0; t < 4; t++) accO[n][t] = 0.f;
    float mrow[2] = {-1e30f, -1e30f};
    float lrow[2] = {0.f, 0.f};

    for (int j = 0; j < 12; j++) {
        __syncthreads();
        #pragma unroll
        for (int rep = 0; rep < 3; rep++) {
            int idx = rep * 256 + tid;
            int r = idx / 12, c4 = (idx % 12) * 4;
            float4 v = *(const float4*)&kb_[(long)(j * 64 + r) * HD + c4];
            uint32_t* d = &Ks[r * KP + c4];
            d[0] = f2tf32(v.x); d[1] = f2tf32(v.y); d[2] = f2tf32(v.z); d[3] = f2tf32(v.w);
        }
        #pragma unroll
        for (int rep = 0; rep < 12; rep++) {
            int idx = rep * 256 + tid;
            int r = idx / 48, d = idx % 48;
            Vs[d * VP + r] = f2tf32(vb[(long)(j * 64 + r) * HD + d]);
        }
        // bias tile: [b,h,j0+c, i0+r], r contiguous in gmem -> column-major smem
        #pragma unroll
        for (int rep = 0; rep < 32; rep++) {
            int idx = rep * 256 + tid;
            int c = idx >> 7, r = idx & 127;
            Bfc[c * BFP + r] = biasb[(long)(j * 64 + c) * SS + i0 + r];
        }
        __syncthreads();

        float S[8][4];
        #pragma unroll
        for (int nt = 0; nt < 8; nt++)
            #pragma unroll
            for (int t = 0; t < 4; t++) S[nt][t] = 0.f;
        #pragma unroll
        for (int kc = 0; kc < 6; kc++) {
            int kbx = kc * 8 + q4;
            uint32_t af[4];
            af[0] = Qs[(wr + g4) * QP + kbx];
            af[1] = Qs[(wr + g4 + 8) * QP + kbx];
            af[2] = Qs[(wr + g4) * QP + kbx + 4];
            af[3] = Qs[(wr + g4 + 8) * QP + kbx + 4];
            #pragma unroll
            for (int nt = 0; nt < 8; nt++) {
                uint32_t bf2[2];
                bf2[0] = Ks[(nt * 8 + g4) * KP + kbx];
                bf2[1] = Ks[(nt * 8 + g4) * KP + kbx + 4];
                mma_tf32(S[nt], af, bf2);
            }
        }
        int r0 = wr + g4, r1 = r0 + 8;
        float mn0 = mrow[0], mn1 = mrow[1];
        #pragma unroll
        for (int nt = 0; nt < 8; nt++) {
            #pragma unroll
            for (int t = 0; t < 4; t++) {
                int rr = (t >= 2) ? r1 : r0;
                int cc = nt * 8 + 2 * q4 + (t & 1);
                float val = S[nt][t] * SCALE + Bfc[cc * BFP + rr];
                S[nt][t] = val;
                if (t < 2) mn0 = fmaxf(mn0, val); else mn1 = fmaxf(mn1, val);
            }
        }
        __syncthreads();   // bias fully consumed; Ps may now overwrite the buffer
        mn0 = fmaxf(mn0, __shfl_xor_sync(0xffffffffu, mn0, 1));
        mn0 = fmaxf(mn0, __shfl_xor_sync(0xffffffffu, mn0, 2));
        mn1 = fmaxf(mn1, __shfl_xor_sync(0xffffffffu, mn1, 1));
        mn1 = fmaxf(mn1, __shfl_xor_sync(0xffffffffu, mn1, 2));
        float al0 = __expf(mrow[0] - mn0);
        float al1 = __expf(mrow[1] - mn1);
        mrow[0] = mn0; mrow[1] = mn1;
        float s0 = 0.f, s1 = 0.f;
        #pragma unroll
        for (int nt = 0; nt < 8; nt++) {
            #pragma unroll
            for (int t = 0; t < 4; t++) {
                float p = __expf(S[nt][t] - ((t >= 2) ? mn1 : mn0));
                S[nt][t] = p;
                if (t < 2) s0 += p; else s1 += p;
                int rr = (t >= 2) ? r1 : r0;
                int cc = nt * 8 + 2 * q4 + (t & 1);
                Ps[rr * PP + cc] = f2tf32(p);
            }
        }
        s0 += __shfl_xor_sync(0xffffffffu, s0, 1);
        s0 += __shfl_xor_sync(0xffffffffu, s0, 2);
        s1 += __shfl_xor_sync(0xffffffffu, s1, 1);
        s1 += __shfl_xor_sync(0xffffffffu, s1, 2);
        lrow[0] = lrow[0] * al0 + s0;
        lrow[1] = lrow[1] * al1 + s1;
        #pragma unroll
        for (int n = 0; n < 6; n++) {
            accO[n][0] *= al0; accO[n][1] *= al0;
            accO[n][2] *= al1; accO[n][3] *= al1;
        }
        __syncwarp();
        #pragma unroll
        for (int kc = 0; kc < 8; kc++) {
            int kbx = kc * 8 + q4;
            uint32_t af[4];
            af[0] = Ps[(wr + g4) * PP + kbx];
            af[1] = Ps[(wr + g4 + 8) * PP + kbx];
            af[2] = Ps[(wr + g4) * PP + kbx + 4];
            af[3] = Ps[(wr + g4 + 8) * PP + kbx + 4];
            #pragma unroll
            for (int n = 0; n < 6; n++) {
                uint32_t bf2[2];
                bf2[0] = Vs[(n * 8 + g4) * VP + kbx];
                bf2[1] = Vs[(n * 8 + g4) * VP + kbx + 4];
                mma_tf32(accO[n], af, bf2);
            }
        }
    }

    float inv0 = 1.0f / lrow[0], inv1 = 1.0f / lrow[1];
    #pragma unroll
    for (int n = 0; n < 6; n++) {
        #pragma unroll
        for (int t = 0; t < 4; t++) {
            int r = wr + g4 + ((t >= 2) ? 8 : 0);
            int c = n * 8 + 2 * q4 + (t & 1);
            long gi = ((long)(b * SS + i0 + r)) * CA + h * HD + c;
            float o = accO[n][t] * ((t >= 2) ? inv1 : inv0);
            outg[gi] = o * sigmoidf_(gateg[gi]);
        }
    }
}

// ---------------- host side --------------------------------------------------
static float* sym(const void* symbol) {
    void* p = nullptr;
    cudaGetSymbolAddress(&p, symbol);
    return (float*)p;
}

extern "C" void kernel_launch(void* const* d_in, const int* in_sizes, int n_in,
                              void* d_out, int out_size) {
    const float* a        = (const float*)d_in[0];
    const float* s        = (const float*)d_in[1];
    const float* z        = (const float*)d_in[2];
    const float* beta     = (const float*)d_in[3];
    const float* gamma_s  = (const float*)d_in[4];
    const float* W_ada_g  = (const float*)d_in[5];
    const float* b_ada_g  = (const float*)d_in[6];
    const float* W_ada_o  = (const float*)d_in[7];
    const float* Wq       = (const float*)d_in[8];
    const float* bq       = (const float*)d_in[9];
    const float* Wk       = (const float*)d_in[10];
    const float* Wv       = (const float*)d_in[11];
    const float* Wb       = (const float*)d_in[12];
    const float* gz       = (const float*)d_in[13];
    const float* bz       = (const float*)d_in[14];
    const float* Wg       = (const float*)d_in[15];
    const float* Wout     = (const float*)d_in[16];
    const float* Ws_gate  = (const float*)d_in[17];
    const float* bs_gate  = (const float*)d_in[18];
    float* out = (float*)d_out;

    float* p_q    = sym(g_q);
    float* p_k    = sym(g_k);
    float* p_v    = sym(g_v);
    float* p_gate = sym(g_gate);
    float* p_bias = sym(g_bias);
    float* p_go   = sym(g_go);

    cudaFuncSetAttribute(gemm_ada,        cudaFuncAttributeMaxDynamicSharedMemorySize, ADA_SMEM);
    cudaFuncSetAttribute(gemm_proj4,      cudaFuncAttributeMaxDynamicSharedMemorySize, PROJ_SMEM);
    cudaFuncSetAttribute(gemm_final,      cudaFuncAttributeMaxDynamicSharedMemorySize, PROJ_SMEM);
    cudaFuncSetAttribute(pairbias5_kernel,cudaFuncAttributeMaxDynamicSharedMemorySize, PB_SMEM);
    cudaFuncSetAttribute(attn_kernel,     cudaFuncAttributeMaxDynamicSharedMemorySize, ATT_SMEM);

    // 1. layer norms
    ln_kernel<<<MM, 256>>>(s, a, gamma_s);
    // 2. adaLN (fused dual GEMM)
    gemm_ada<<<dim3(CA / 64, MM / 128), 256, ADA_SMEM>>>(W_ada_g, W_ada_o, b_ada_g);
    // 3. 4-way projections
    gemm_proj4<<<dim3(4 * CA / 64, MM / 128), 256, PROJ_SMEM>>>(Wq, Wk, Wv, Wg, bq);
    // 4. pair bias (5 CTA/SM, all-warp MMA)
    pairbias5_kernel<<<dim3(SS / 64, SS, BB), 256, PB_SMEM>>>(z, beta, Wb, gz, bz);
    // 5. fused attention
    attn_kernel<<<dim3(SS / 128, BB * HH), 256, ATT_SMEM>>>(p_q, p_k, p_v, p_bias, p_gate, p_go);
    // 6. fused output GEMM + s-gate
    gemm_final<<<dim3(CA / 64, MM / 128), 256, PROJ_SMEM>>>(Wout, s, Ws_gate, bs_gate, out);
}

// round 10
// speedup vs baseline: 3.5025x; 1.1272x over previous
#include <cuda_runtime.h>
#include <cuda_bf16.h>
#include <math.h>
#include <cstdint>

// Problem constants
#define BB   2
#define SS   768
#define CA   768
#define CS   384
#define CZ   128
#define HH   16
#define HD   48
#define MM   (BB*SS)          // 1536
#define EPS  1e-5f
#define SCALE (0.14433756729740643f)  // 1/sqrt(48)

// ---------------- scratch (device globals) ----------------------------------
__device__ float g_sn   [MM*CS];
__device__ float g_lna  [MM*CA];
__device__ float g_an   [MM*CA];
__device__ float g_q    [BB*HH*SS*HD];      // [b,h,s,d]
__device__ float g_k    [BB*HH*SS*HD];      // [b,h,s,d]
__device__ float g_v    [BB*HH*SS*HD];      // [b,h,s,d]
__device__ float g_gate [MM*CA];
__device__ float g_bias [BB*HH*SS*SS];      // pair bias, layout [b,h,j,i] (i contiguous)
__device__ float g_go   [MM*CA];

// ---------------- helpers ----------------------------------------------------
__device__ __forceinline__ float sigmoidf_(float x) { return 1.0f / (1.0f + expf(-x)); }

__device__ __forceinline__ uint32_t f2tf32(float f) {
    uint32_t r;
    asm("cvt.rna.tf32.f32 %0, %1;" : "=r"(r) : "f"(f));
    return r;
}
// pack two floats into bf16x2: lo = first k, hi = second k
__device__ __forceinline__ uint32_t pack_bf16x2(float lo, float hi) {
    uint32_t r;
    asm("cvt.rn.bf16x2.f32 %0, %1, %2;" : "=r"(r) : "f"(hi), "f"(lo));
    return r;
}

__device__ __forceinline__ void mma_tf32(float* d, const uint32_t* a, const uint32_t* b) {
    asm volatile("mma.sync.aligned.m16n8k8.row.col.f32.tf32.tf32.f32 "
        "{%0,%1,%2,%3}, {%4,%5,%6,%7}, {%8,%9}, {%0,%1,%2,%3};"
        : "+f"(d[0]), "+f"(d[1]), "+f"(d[2]), "+f"(d[3])
        : "r"(a[0]), "r"(a[1]), "r"(a[2]), "r"(a[3]), "r"(b[0]), "r"(b[1]));
}
__device__ __forceinline__ void mma_bf16(float* d, const uint32_t* a, const uint32_t* b) {
    asm volatile("mma.sync.aligned.m16n8k16.row.col.f32.bf16.bf16.f32 "
        "{%0,%1,%2,%3}, {%4,%5,%6,%7}, {%8,%9}, {%0,%1,%2,%3};"
        : "+f"(d[0]), "+f"(d[1]), "+f"(d[2]), "+f"(d[3])
        : "r"(a[0]), "r"(a[1]), "r"(a[2]), "r"(a[3]), "r"(b[0]), "r"(b[1]));
}

__device__ float2 blockReduceSum2(float a, float b) {
    __shared__ float sa[32], sb[32];
    int lane = threadIdx.x & 31, wid = threadIdx.x >> 5;
    #pragma unroll
    for (int o = 16; o; o >>= 1) {
        a += __shfl_xor_sync(0xffffffffu, a, o);
        b += __shfl_xor_sync(0xffffffffu, b, o);
    }
    if (lane == 0) { sa[wid] = a; sb[wid] = b; }
    __syncthreads();
    if (wid == 0) {
        int nw = (blockDim.x + 31) >> 5;
        a = (lane < nw) ? sa[lane] : 0.0f;
        b = (lane < nw) ? sb[lane] : 0.0f;
        #pragma unroll
        for (int o = 16; o; o >>= 1) {
            a += __shfl_xor_sync(0xffffffffu, a, o);
            b += __shfl_xor_sync(0xffffffffu, b, o);
        }
        if (lane == 0) { sa[0] = a; sb[0] = b; }
    }
    __syncthreads();
    float2 r = make_float2(sa[0], sb[0]);
    __syncthreads();
    return r;
}

// ---------------- LN kernel --------------------------------------------------
__global__ void ln_kernel(const float* __restrict__ s, const float* __restrict__ a,
                          const float* __restrict__ gamma_s) {
    int r = blockIdx.x;
    int tid = threadIdx.x;
    const float* srow = s + (long)r * CS;
    float sum = 0.f, sq = 0.f;
    for (int c = tid; c < CS; c += blockDim.x) { float v = srow[c]; sum += v; sq += v * v; }
    float2 t = blockReduceSum2(sum, sq);
    float mean = t.x / CS, var = t.y / CS - mean * mean;
    float rstd = rsqrtf(var + EPS);
    for (int c = tid; c < CS; c += blockDim.x)
        g_sn[(long)r * CS + c] = (srow[c] - mean) * rstd * gamma_s[c];

    const float* arow = a + (long)r * CA;
    sum = 0.f; sq = 0.f;
    for (int c = tid; c < CA; c += blockDim.x) { float v = arow[c]; sum += v; sq += v * v; }
    t = blockReduceSum2(sum, sq);
    mean = t.x / CA; var = t.y / CA - mean * mean;
    rstd = rsqrtf(var + EPS);
    for (int c = tid; c < CA; c += blockDim.x)
        g_lna[(long)r * CA + c] = (arow[c] - mean) * rstd;
}

// ---------------- common GEMM machinery (128x64 tile, BK=32) ----------------
#define APITCH 36
#define BPITCH 36
#define A_WORDS (128 * APITCH)               // 4608
#define B_WORDS (64 * BPITCH)                // 2304
#define SPITCH 68
#define STAGE_WORDS (128 * SPITCH)           // 8704

__device__ __forceinline__ void frag_compute(const uint32_t* As, const uint32_t* Bs,
        float (&acc)[2][4][4], int wr, int wc, int g4, int q4) {
    #pragma unroll
    for (int kc = 0; kc < 4; kc++) {
        int kb = kc * 8 + q4;
        uint32_t af[2][4];
        #pragma unroll
        for (int mt = 0; mt < 2; mt++) {
            int r = wr + mt * 16 + g4;
            af[mt][0] = As[r * APITCH + kb];
            af[mt][1] = As[(r + 8) * APITCH + kb];
            af[mt][2] = As[r * APITCH + kb + 4];
            af[mt][3] = As[(r + 8) * APITCH + kb + 4];
        }
        #pragma unroll
        for (int nt = 0; nt < 4; nt++) {
            int c = wc + nt * 8 + g4;
            uint32_t bf[2] = {Bs[c * BPITCH + kb], Bs[c * BPITCH + kb + 4]};
            #pragma unroll
            for (int mt = 0; mt < 2; mt++)
                mma_tf32(acc[mt][nt], af[mt], bf);
        }
    }
}

__device__ __forceinline__ void frag_compute2(const uint32_t* As, const uint32_t* Bs1,
        const uint32_t* Bs2, float (&acc1)[2][4][4], float (&acc2)[2][4][4],
        int wr, int wc, int g4, int q4) {
    #pragma unroll
    for (int kc = 0; kc < 4; kc++) {
        int kb = kc * 8 + q4;
        uint32_t af[2][4];
        #pragma unroll
        for (int mt = 0; mt < 2; mt++) {
            int r = wr + mt * 16 + g4;
            af[mt][0] = As[r * APITCH + kb];
            af[mt][1] = As[(r + 8) * APITCH + kb];
            af[mt][2] = As[r * APITCH + kb + 4];
            af[mt][3] = As[(r + 8) * APITCH + kb + 4];
        }
        #pragma unroll
        for (int nt = 0; nt < 4; nt++) {
            int c = wc + nt * 8 + g4;
            uint32_t b1[2] = {Bs1[c * BPITCH + kb], Bs1[c * BPITCH + kb + 4]};
            uint32_t b2[2] = {Bs2[c * BPITCH + kb], Bs2[c * BPITCH + kb + 4]};
            #pragma unroll
            for (int mt = 0; mt < 2; mt++) {
                mma_tf32(acc1[mt][nt], af[mt], b1);
                mma_tf32(acc2[mt][nt], af[mt], b2);
            }
        }
    }
}

__device__ __forceinline__ void stage_acc(float* st, const float (&acc)[2][4][4],
        int wr, int wc, int g4, int q4) {
    #pragma unroll
    for (int mt = 0; mt < 2; mt++) {
        #pragma unroll
        for (int nt = 0; nt < 4; nt++) {
            int rr = wr + mt * 16 + g4;
            int cc = wc + nt * 8 + 2 * q4;
            st[rr * SPITCH + cc]           = acc[mt][nt][0];
            st[rr * SPITCH + cc + 1]       = acc[mt][nt][1];
            st[(rr + 8) * SPITCH + cc]     = acc[mt][nt][2];
            st[(rr + 8) * SPITCH + cc + 1] = acc[mt][nt][3];
        }
    }
}

#define ZERO_ACC(acc) { \
    _Pragma("unroll") for (int i = 0; i < 2; i++) \
    _Pragma("unroll") for (int j = 0; j < 4; j++) \
    _Pragma("unroll") for (int t = 0; t < 4; t++) acc[i][j][t] = 0.f; }

#define LDGA(pa, Abase, lda, k0) { \
    _Pragma("unroll") for (int rep = 0; rep < 4; rep++) { \
        int lin = rep * 256 + tid; int r = lin >> 3, c4 = (lin & 7) * 4; \
        pa[rep] = *(const float4*)&(Abase)[(long)(row0 + r) * (lda) + (k0) + c4]; } }
#define STSA(As, pa) { \
    _Pragma("unroll") for (int rep = 0; rep < 4; rep++) { \
        int lin = rep * 256 + tid; int r = lin >> 3, c4 = (lin & 7) * 4; \
        uint32_t* dst = &(As)[r * APITCH + c4]; \
        dst[0] = f2tf32(pa[rep].x); dst[1] = f2tf32(pa[rep].y); \
        dst[2] = f2tf32(pa[rep].z); dst[3] = f2tf32(pa[rep].w); } }
#define LDGB(pb, Bbase, ldb, k0, c0) { \
    _Pragma("unroll") for (int rep = 0; rep < 8; rep++) { \
        int lin = rep * 256 + tid; int kk = lin >> 6, n = lin & 63; \
        pb[rep] = (Bbase)[(long)((k0) + kk) * (ldb) + (c0) + n]; } }
#define STSB(Bs, pb) { \
    _Pragma("unroll") for (int rep = 0; rep < 8; rep++) { \
        int lin = rep * 256 + tid; int kk = lin >> 6, n = lin & 63; \
        (Bs)[n * BPITCH + kk] = f2tf32(pb[rep]); } }

// ---------------- adaLN fused dual GEMM --------------------------------------
#define ADA_SMEM (2 * STAGE_WORDS * 4)   // 69632 B
__global__ void __launch_bounds__(256)
gemm_ada(const float* __restrict__ Wg_, const float* __restrict__ Wo_,
         const float* __restrict__ badag) {
    extern __shared__ float sm[];
    uint32_t* As  = (uint32_t*)sm;
    uint32_t* Bs1 = As + A_WORDS;
    uint32_t* Bs2 = Bs1 + B_WORDS;

    int tid = threadIdx.x, wid = tid >> 5;
    int g4 = (tid & 31) >> 2, q4 = tid & 3;
    int wr = (wid & 3) * 32, wc = (wid >> 2) * 32;
    int row0 = blockIdx.y * 128, col0 = blockIdx.x * 64;
    const float* A = g_sn;

    float acc1[2][4][4], acc2[2][4][4];
    ZERO_ACC(acc1); ZERO_ACC(acc2);
    float4 pa[4]; float pb1[8], pb2[8];

    LDGA(pa, A, CS, 0);
    LDGB(pb1, Wg_, CA, 0, col0);
    LDGB(pb2, Wo_, CA, 0, col0);
    const int KT = CS / 32;
    for (int kt = 0; kt < KT; kt++) {
        STSA(As, pa); STSB(Bs1, pb1); STSB(Bs2, pb2);
        __syncthreads();
        if (kt + 1 < KT) {
            int k0 = (kt + 1) * 32;
            LDGA(pa, A, CS, k0);
            LDGB(pb1, Wg_, CA, k0, col0);
            LDGB(pb2, Wo_, CA, k0, col0);
        }
        frag_compute2(As, Bs1, Bs2, acc1, acc2, wr, wc, g4, q4);
        __syncthreads();
    }

    float* st1 = sm;
    float* st2 = sm + STAGE_WORDS;
    stage_acc(st1, acc1, wr, wc, g4, q4);
    stage_acc(st2, acc2, wr, wc, g4, q4);
    __syncthreads();
    #pragma unroll
    for (int rep = 0; rep < 32; rep++) {
        int idx = rep * 256 + tid;
        int r = idx >> 6, c = idx & 63;
        int m = row0 + r, n = col0 + c;
        float v1 = st1[r * SPITCH + c], v2 = st2[r * SPITCH + c];
        g_an[(long)m * CA + n] = sigmoidf_(v1 + badag[n]) * g_lna[(long)m * CA + n] + v2;
    }
}

// ---------------- fused 4-way projection GEMM --------------------------------
#define PROJ_SMEM (STAGE_WORDS * 4)      // 34816 B
__global__ void __launch_bounds__(256)
gemm_proj4(const float* __restrict__ Wq, const float* __restrict__ Wk,
           const float* __restrict__ Wv, const float* __restrict__ Wg_,
           const float* __restrict__ bq) {
    extern __shared__ float sm[];
    uint32_t* As = (uint32_t*)sm;
    uint32_t* Bs = As + A_WORDS;

    int tid = threadIdx.x, wid = tid >> 5;
    int g4 = (tid & 31) >> 2, q4 = tid & 3;
    int wr = (wid & 3) * 32, wc = (wid >> 2) * 32;
    int row0 = blockIdx.y * 128;
    int cg = blockIdx.x * 64;
    int w = cg / CA, coln = cg % CA;
    const float* B = (w == 0) ? Wq : (w == 1) ? Wk : (w == 2) ? Wv : Wg_;
    const float* A = g_an;

    float acc[2][4][4];
    ZERO_ACC(acc);
    float4 pa[4]; float pb[8];

    LDGA(pa, A, CA, 0);
    LDGB(pb, B, CA, 0, coln);
    const int KT = CA / 32;
    for (int kt = 0; kt < KT; kt++) {
        STSA(As, pa); STSB(Bs, pb);
        __syncthreads();
        if (kt + 1 < KT) {
            int k0 = (kt + 1) * 32;
            LDGA(pa, A, CA, k0);
            LDGB(pb, B, CA, k0, coln);
        }
        frag_compute(As, Bs, acc, wr, wc, g4, q4);
        __syncthreads();
    }

    float* st = sm;
    stage_acc(st, acc, wr, wc, g4, q4);
    __syncthreads();
    float* dst = (w == 0) ? g_q : (w == 1) ? g_k : g_v;
    #pragma unroll
    for (int rep = 0; rep < 32; rep++) {
        int idx = rep * 256 + tid;
        int r = idx >> 6, c = idx & 63;
        int m = row0 + r, n = coln + c;
        float v = st[r * SPITCH + c];
        if (w == 3) {
            g_gate[(long)m * CA + n] = v;
        } else {
            if (w == 0) v += bq[n];
            int b = m / SS, si = m % SS, h = n / HD, d = n % HD;
            dst[(((long)(b * HH + h) * SS) + si) * HD + d] = v;
        }
    }
}

// ---------------- fused output GEMM ------------------------------------------
__global__ void __launch_bounds__(256)
gemm_final(const float* __restrict__ Wout, const float* __restrict__ s_,
           const float* __restrict__ Wsg, const float* __restrict__ bsg,
           float* __restrict__ out) {
    extern __shared__ float sm[];
    uint32_t* As = (uint32_t*)sm;
    uint32_t* Bs = As + A_WORDS;

    int tid = threadIdx.x, wid = tid >> 5;
    int g4 = (tid & 31) >> 2, q4 = tid & 3;
    int wr = (wid & 3) * 32, wc = (wid >> 2) * 32;
    int row0 = blockIdx.y * 128, col0 = blockIdx.x * 64;

    float acc1[2][4][4], acc2[2][4][4];
    ZERO_ACC(acc1); ZERO_ACC(acc2);
    float4 pa[4]; float pb[8];

    {
        const float* A = g_go;
        LDGA(pa, A, CA, 0);
        LDGB(pb, Wout, CA, 0, col0);
        const int KT = CA / 32;
        for (int kt = 0; kt < KT; kt++) {
            STSA(As, pa); STSB(Bs, pb);
            __syncthreads();
            if (kt + 1 < KT) {
                int k0 = (kt + 1) * 32;
                LDGA(pa, A, CA, k0);
                LDGB(pb, Wout, CA, k0, col0);
            }
            frag_compute(As, Bs, acc1, wr, wc, g4, q4);
            __syncthreads();
        }
    }
    {
        LDGA(pa, s_, CS, 0);
        LDGB(pb, Wsg, CA, 0, col0);
        const int KT = CS / 32;
        for (int kt = 0; kt < KT; kt++) {
            STSA(As, pa); STSB(Bs, pb);
            __syncthreads();
            if (kt + 1 < KT) {
                int k0 = (kt + 1) * 32;
                LDGA(pa, s_, CS, k0);
                LDGB(pb, Wsg, CA, k0, col0);
            }
            frag_compute(As, Bs, acc2, wr, wc, g4, q4);
            __syncthreads();
        }
    }

    #pragma unroll
    for (int mt = 0; mt < 2; mt++)
        #pragma unroll
        for (int nt = 0; nt < 4; nt++)
            #pragma unroll
            for (int t = 0; t < 4; t++) {
                int n = col0 + wc + nt * 8 + 2 * q4 + (t & 1);
                acc1[mt][nt][t] *= sigmoidf_(acc2[mt][nt][t] + __ldg(&bsg[n]));
            }

    float* st = sm;
    stage_acc(st, acc1, wr, wc, g4, q4);
    __syncthreads();
    #pragma unroll
    for (int rep = 0; rep < 32; rep++) {
        int idx = rep * 256 + tid;
        int r = idx >> 6, c = idx & 63;
        out[(long)(row0 + r) * CA + col0 + c] = st[r * SPITCH + c];
    }
}

// ---------------- pair bias v6: bf16 m16n8k16 MMA, half the smem traffic -----
// Block handles (b, p=j, q-tile of 64 i values). z slab contiguous (32KB).
// smem: Z16[64 x WP bf16x2 words] (res aliased on top) + Wb16[16 x WP] = 21760 B.
// beta preloaded into 4 regs/thread (linear coalesced), added after MMA.
// Output: g_bias[b][h][p][q0..q0+63] (contiguous per h).
#define WP 68
#define PB_Z_WORDS (64 * WP)                         // 4352
#define PB_WB_OFF  PB_Z_WORDS
#define PB_SMEM ((PB_Z_WORDS + 16 * WP) * 4)         // 21760 B
__global__ void __launch_bounds__(256)
pairbias6_kernel(const float* __restrict__ z, const float* __restrict__ beta,
                 const float* __restrict__ Wb, const float* __restrict__ gz,
                 const float* __restrict__ bz) {
    extern __shared__ float smf[];
    uint32_t* Z16  = (uint32_t*)smf;           // [64][WP] bf16x2
    uint32_t* Wb16 = Z16 + PB_WB_OFF;          // [16][WP] bf16x2
    float*    res  = smf;                      // aliased over Z16 after MMA
    __shared__ float gzs[CZ], bzs[CZ];

    int tid = threadIdx.x, wid = tid >> 5, lane = tid & 31;
    int g4 = lane >> 2, q4 = lane & 3;
    int b = blockIdx.z, p = blockIdx.y, q0 = blockIdx.x * 64;

    const float* zb = z + ((long)(b * SS + p) * SS + q0) * CZ;
    const float* betab = beta + ((long)(b * SS + p) * SS + q0) * HH;

    // preload beta slab (1024 consecutive floats) into regs, coalesced
    float betar[4];
    #pragma unroll
    for (int rep = 0; rep < 4; rep++)
        betar[rep] = betab[rep * 256 + tid];

    // stage Wb transposed as bf16x2: Wb16[h][j] = (Wb[2j][h], Wb[2j+1][h])
    for (int idx = tid; idx < (CZ / 2) * HH; idx += 256) {
        int j = idx >> 4, h = idx & 15;
        Wb16[h * WP + j] = pack_bf16x2(Wb[(2 * j) * HH + h], Wb[(2 * j + 1) * HH + h]);
    }
    for (int idx = tid; idx < CZ; idx += 256) { gzs[idx] = gz[idx]; bzs[idx] = bz[idx]; }
    __syncthreads();

    // LN of 64 contiguous z-rows -> bf16x2. Warp w: rows 8w..8w+7 (MLP 8).
    {
        float4 vr[8];
        #pragma unroll
        for (int rr = 0; rr < 8; rr++) {
            int pl = wid * 8 + rr;
            vr[rr] = *(const float4*)&zb[(long)pl * CZ + lane * 4];
        }
        float sums[8], sqs[8];
        #pragma unroll
        for (int rr = 0; rr < 8; rr++) {
            float4 v = vr[rr];
            sums[rr] = v.x + v.y + v.z + v.w;
            sqs[rr]  = v.x * v.x + v.y * v.y + v.z * v.z + v.w * v.w;
        }
        #pragma unroll
        for (int o = 16; o; o >>= 1) {
            #pragma unroll
            for (int rr = 0; rr < 8; rr++) {
                sums[rr] += __shfl_xor_sync(0xffffffffu, sums[rr], o);
                sqs[rr]  += __shfl_xor_sync(0xffffffffu, sqs[rr],  o);
            }
        }
        #pragma unroll
        for (int rr = 0; rr < 8; rr++) {
            int pl = wid * 8 + rr;
            float mean = sums[rr] * (1.0f / CZ);
            float var  = sqs[rr] * (1.0f / CZ) - mean * mean;
            float rstd = rsqrtf(var + EPS);
            float4 v = vr[rr];
            int c = lane * 4;
            float z0 = (v.x - mean) * rstd * gzs[c + 0] + bzs[c + 0];
            float z1 = (v.y - mean) * rstd * gzs[c + 1] + bzs[c + 1];
            float z2 = (v.z - mean) * rstd * gzs[c + 2] + bzs[c + 2];
            float z3 = (v.w - mean) * rstd * gzs[c + 3] + bzs[c + 3];
            uint2 o2;
            o2.x = pack_bf16x2(z0, z1);
            o2.y = pack_bf16x2(z2, z3);
            *(uint2*)&Z16[pl * WP + lane * 2] = o2;
        }
    }
    __syncthreads();

    // mma bf16 m16n8k16: [64 x 128] @ [128 x 16], ALL 8 warps.
    // warp w: row-group (w&3)*16, h-half (w>>2)*8. 8 kc (k=16 each) x 1 n-tile.
    float acc[4];
    #pragma unroll
    for (int t = 0; t < 4; t++) acc[t] = 0.f;
    {
        int wr = (wid & 3) * 16;
        int hb = (wid >> 2) * 8;
        #pragma unroll
        for (int kc = 0; kc < 8; kc++) {
            int kb = kc * 8 + q4;
            uint32_t af[4];
            af[0] = Z16[(wr + g4) * WP + kb];
            af[1] = Z16[(wr + g4 + 8) * WP + kb];
            af[2] = Z16[(wr + g4) * WP + kb + 4];
            af[3] = Z16[(wr + g4 + 8) * WP + kb + 4];
            uint32_t bf[2];
            bf[0] = Wb16[(hb + g4) * WP + kb];
            bf[1] = Wb16[(hb + g4) * WP + kb + 4];
            mma_bf16(acc, af, bf);
        }
    }
    __syncthreads();   // all Z16 reads done; res may alias Z16 now

    // write res[row*17 + h]
    {
        int wr = (wid & 3) * 16;
        int hb = (wid >> 2) * 8;
        #pragma unroll
        for (int t = 0; t < 4; t++) {
            int row = wr + g4 + ((t >= 2) ? 8 : 0);
            int h = hb + 2 * q4 + (t & 1);
            res[row * 17 + h] = acc[t];
        }
    }
    __syncthreads();

    // add beta (linear mapping: idx = ql*16 + h)
    #pragma unroll
    for (int rep = 0; rep < 4; rep++) {
        int idx = rep * 256 + tid;
        int ql = idx >> 4, hh = idx & 15;
        res[ql * 17 + hh] += betar[rep];
    }
    __syncthreads();

    // coalesced store: g_bias[b][h][p][q0+ql] (contiguous runs of 64 per h)
    #pragma unroll
    for (int rep = 0; rep < 4; rep++) {
        int idx = rep * 256 + tid;
        int h = idx >> 6, ql = idx & 63;
        g_bias[(((long)(b * HH + h) * SS) + p) * SS + q0 + ql] = res[ql * 17 + h];
    }
}

// ---------------- fused attention: softmax(scale*QK^T + bias) @ V, gated ----
// bias layout [b,h,j,i]; Ps and Bfc share one smem buffer (bias fully consumed
// into registers before Ps is written; one extra __syncthreads() in between).
#define QP 52
#define KP 52
#define VP 68
#define PP 68
#define BFP 132
#define AT_K (128 * QP)
#define AT_V (AT_K + 64 * KP)
#define AT_PB (AT_V + 48 * VP)
#define AT_WORDS (AT_PB + 128 * PP)          // Ps 8704 words >= Bfc 8448 words
#define ATT_SMEM (AT_WORDS * 4)              // 87808 B

__global__ void __launch_bounds__(256, 2)
attn_kernel(const float* __restrict__ qg, const float* __restrict__ kg,
            const float* __restrict__ vg, const float* __restrict__ biasg,
            const float* __restrict__ gateg, float* __restrict__ outg) {
    extern __shared__ char smem[];
    uint32_t* Qs = (uint32_t*)smem;
    uint32_t* Ks = Qs + AT_K;
    uint32_t* Vs = Qs + AT_V;
    uint32_t* Ps = Qs + AT_PB;
    float*    Bfc = (float*)(Qs + AT_PB);

    int tid = threadIdx.x, wid = tid >> 5, lane = tid & 31;
    int g4 = lane >> 2, q4 = lane & 3;
    int bh = blockIdx.y;
    int b = bh >> 4, h = bh & 15;
    int i0 = blockIdx.x * 128;
    const float* qb = qg + ((long)bh * SS + i0) * HD;
    const float* kb_ = kg + (long)bh * SS * HD;
    const float* vb = vg + (long)bh * SS * HD;
    const float* biasb = biasg + (long)bh * SS * SS;   // [j][i]

    #pragma unroll
    for (int rep = 0; rep < 6; rep++) {
        int idx = rep * 256 + tid;
        int r = idx / 12, c4 = (idx % 12) * 4;
        float4 v = *(const float4*)&qb[(long)r * HD + c4];
        uint32_t* d = &Qs[r * QP + c4];
        d[0] = f2tf32(v.x); d[1] = f2tf32(v.y); d[2] = f2tf32(v.z); d[3] = f2tf32(v.w);
    }

    int wr = wid * 16;
    float accO[6][4];
    #pragma unroll
    for (int n = 0; n < 6; n++)
        #pragma unroll
        for (int t = 0; t < 4; t++) accO[n][t] = 0.f;
    float mrow[2] = {-1e30f, -1e30f};
    float lrow[2] = {0.f, 0.f};

    for (int j = 0; j < 12; j++) {
        __syncthreads();
        #pragma unroll
        for (int rep = 0; rep < 3; rep++) {
            int idx = rep * 256 + tid;
            int r = idx / 12, c4 = (idx % 12) * 4;
            float4 v = *(const float4*)&kb_[(long)(j * 64 + r) * HD + c4];
            uint32_t* d = &Ks[r * KP + c4];
            d[0] = f2tf32(v.x); d[1] = f2tf32(v.y); d[2] = f2tf32(v.z); d[3] = f2tf32(v.w);
        }
        #pragma unroll
        for (int rep = 0; rep < 12; rep++) {
            int idx = rep * 256 + tid;
            int r = idx / 48, d = idx % 48;
            Vs[d * VP + r] = f2tf32(vb[(long)(j * 64 + r) * HD + d]);
        }
        // bias tile: [b,h,j0+c, i0+r], r contiguous in gmem -> column-major smem
        #pragma unroll
        for (int rep = 0; rep < 32; rep++) {
            int idx = rep * 256 + tid;
            int c = idx >> 7, r = idx & 127;
            Bfc[c * BFP + r] = biasb[(long)(j * 64 + c) * SS + i0 + r];
        }
        __syncthreads();

        float S[8][4];
        #pragma unroll
        for (int nt = 0; nt < 8; nt++)
            #pragma unroll
            for (int t = 0; t < 4; t++) S[nt][t] = 0.f;
        #pragma unroll
        for (int kc = 0; kc < 6; kc++) {
            int kbx = kc * 8 + q4;
            uint32_t af[4];
            af[0] = Qs[(wr + g4) * QP + kbx];
            af[1] = Qs[(wr + g4 + 8) * QP + kbx];
            af[2] = Qs[(wr + g4) * QP + kbx + 4];
            af[3] = Qs[(wr + g4 + 8) * QP + kbx + 4];
            #pragma unroll
            for (int nt = 0; nt < 8; nt++) {
                uint32_t bf2[2];
                bf2[0] = Ks[(nt * 8 + g4) * KP + kbx];
                bf2[1] = Ks[(nt * 8 + g4) * KP + kbx + 4];
                mma_tf32(S[nt], af, bf2);
            }
        }
        int r0 = wr + g4, r1 = r0 + 8;
        float mn0 = mrow[0], mn1 = mrow[1];
        #pragma unroll
        for (int nt = 0; nt < 8; nt++) {
            #pragma unroll
            for (int t = 0; t < 4; t++) {
                int rr = (t >= 2) ? r1 : r0;
                int cc = nt * 8 + 2 * q4 + (t & 1);
                float val = S[nt][t] * SCALE + Bfc[cc * BFP + rr];
                S[nt][t] = val;
                if (t < 2) mn0 = fmaxf(mn0, val); else mn1 = fmaxf(mn1, val);
            }
        }
        __syncthreads();   // bias fully consumed; Ps may now overwrite the buffer
        mn0 = fmaxf(mn0, __shfl_xor_sync(0xffffffffu, mn0, 1));
        mn0 = fmaxf(mn0, __shfl_xor_sync(0xffffffffu, mn0, 2));
        mn1 = fmaxf(mn1, __shfl_xor_sync(0xffffffffu, mn1, 1));
        mn1 = fmaxf(mn1, __shfl_xor_sync(0xffffffffu, mn1, 2));
        float al0 = __expf(mrow[0] - mn0);
        float al1 = __expf(mrow[1] - mn1);
        mrow[0] = mn0; mrow[1] = mn1;
        float s0 = 0.f, s1 = 0.f;
        #pragma unroll
        for (int nt = 0; nt < 8; nt++) {
            #pragma unroll
            for (int t = 0; t < 4; t++) {
                float p = __expf(S[nt][t] - ((t >= 2) ? mn1 : mn0));
                S[nt][t] = p;
                if (t < 2) s0 += p; else s1 += p;
                int rr = (t >= 2) ? r1 : r0;
                int cc = nt * 8 + 2 * q4 + (t & 1);
                Ps[rr * PP + cc] = f2tf32(p);
            }
        }
        s0 += __shfl_xor_sync(0xffffffffu, s0, 1);
        s0 += __shfl_xor_sync(0xffffffffu, s0, 2);
        s1 += __shfl_xor_sync(0xffffffffu, s1, 1);
        s1 += __shfl_xor_sync(0xffffffffu, s1, 2);
        lrow[0] = lrow[0] * al0 + s0;
        lrow[1] = lrow[1] * al1 + s1;
        #pragma unroll
        for (int n = 0; n < 6; n++) {
            accO[n][0] *= al0; accO[n][1] *= al0;
            accO[n][2] *= al1; accO[n][3] *= al1;
        }
        __syncwarp();
        #pragma unroll
        for (int kc = 0; kc < 8; kc++) {
            int kbx = kc * 8 + q4;
            uint32_t af[4];
            af[0] = Ps[(wr + g4) * PP + kbx];
            af[1] = Ps[(wr + g4 + 8) * PP + kbx];
            af[2] = Ps[(wr + g4) * PP + kbx + 4];
            af[3] = Ps[(wr + g4 + 8) * PP + kbx + 4];
            #pragma unroll
            for (int n = 0; n < 6; n++) {
                uint32_t bf2[2];
                bf2[0] = Vs[(n * 8 + g4) * VP + kbx];
                bf2[1] = Vs[(n * 8 + g4) * VP + kbx + 4];
                mma_tf32(accO[n], af, bf2);
            }
        }
    }

    float inv0 = 1.0f / lrow[0], inv1 = 1.0f / lrow[1];
    #pragma unroll
    for (int n = 0; n < 6; n++) {
        #pragma unroll
        for (int t = 0; t < 4; t++) {
            int r = wr + g4 + ((t >= 2) ? 8 : 0);
            int c = n * 8 + 2 * q4 + (t & 1);
            long gi = ((long)(b * SS + i0 + r)) * CA + h * HD + c;
            float o = accO[n][t] * ((t >= 2) ? inv1 : inv0);
            outg[gi] = o * sigmoidf_(gateg[gi]);
        }
    }
}

// ---------------- host side --------------------------------------------------
static float* sym(const void* symbol) {
    void* p = nullptr;
    cudaGetSymbolAddress(&p, symbol);
    return (float*)p;
}

extern "C" void kernel_launch(void* const* d_in, const int* in_sizes, int n_in,
                              void* d_out, int out_size) {
    const float* a        = (const float*)d_in[0];
    const float* s        = (const float*)d_in[1];
    const float* z        = (const float*)d_in[2];
    const float* beta     = (const float*)d_in[3];
    const float* gamma_s  = (const float*)d_in[4];
    const float* W_ada_g  = (const float*)d_in[5];
    const float* b_ada_g  = (const float*)d_in[6];
    const float* W_ada_o  = (const float*)d_in[7];
    const float* Wq       = (const float*)d_in[8];
    const float* bq       = (const float*)d_in[9];
    const float* Wk       = (const float*)d_in[10];
    const float* Wv       = (const float*)d_in[11];
    const float* Wb       = (const float*)d_in[12];
    const float* gz       = (const float*)d_in[13];
    const float* bz       = (const float*)d_in[14];
    const float* Wg       = (const float*)d_in[15];
    const float* Wout     = (const float*)d_in[16];
    const float* Ws_gate  = (const float*)d_in[17];
    const float* bs_gate  = (const float*)d_in[18];
    float* out = (float*)d_out;

    float* p_q    = sym(g_q);
    float* p_k    = sym(g_k);
    float* p_v    = sym(g_v);
    float* p_gate = sym(g_gate);
    float* p_bias = sym(g_bias);
    float* p_go   = sym(g_go);

    cudaFuncSetAttribute(gemm_ada,        cudaFuncAttributeMaxDynamicSharedMemorySize, ADA_SMEM);
    cudaFuncSetAttribute(gemm_proj4,      cudaFuncAttributeMaxDynamicSharedMemorySize, PROJ_SMEM);
    cudaFuncSetAttribute(gemm_final,      cudaFuncAttributeMaxDynamicSharedMemorySize, PROJ_SMEM);
    cudaFuncSetAttribute(pairbias6_kernel,cudaFuncAttributeMaxDynamicSharedMemorySize, PB_SMEM);
    cudaFuncSetAttribute(attn_kernel,     cudaFuncAttributeMaxDynamicSharedMemorySize, ATT_SMEM);

    // 1. layer norms
    ln_kernel<<<MM, 256>>>(s, a, gamma_s);
    // 2. adaLN (fused dual GEMM)
    gemm_ada<<<dim3(CA / 64, MM / 128), 256, ADA_SMEM>>>(W_ada_g, W_ada_o, b_ada_g);
    // 3. 4-way projections
    gemm_proj4<<<dim3(4 * CA / 64, MM / 128), 256, PROJ_SMEM>>>(Wq, Wk, Wv, Wg, bq);
    // 4. pair bias (bf16 MMA, 21.8KB smem)
    pairbias6_kernel<<<dim3(SS / 64, SS, BB), 256, PB_SMEM>>>(z, beta, Wb, gz, bz);
    // 5. fused attention
    attn_kernel<<<dim3(SS / 128, BB * HH), 256, ATT_SMEM>>>(p_q, p_k, p_v, p_bias, p_gate, p_go);
    // 6. fused output GEMM + s-gate
    gemm_final<<<dim3(CA / 64, MM / 128), 256, PROJ_SMEM>>>(Wout, s, Ws_gate, bs_gate, out);
}

// round 11
// speedup vs baseline: 3.5049x; 1.0007x over previous
#include <cuda_runtime.h>
#include <cuda_bf16.h>
#include <math.h>
#include <cstdint>

// Problem constants
#define BB   2
#define SS   768
#define CA   768
#define CS   384
#define CZ   128
#define HH   16
#define HD   48
#define MM   (BB*SS)          // 1536
#define EPS  1e-5f
#define SCALE (0.14433756729740643f)  // 1/sqrt(48)

// ---------------- scratch (device globals) ----------------------------------
__device__ float g_sn   [MM*CS];
__device__ float g_lna  [MM*CA];
__device__ float g_an   [MM*CA];
__device__ float g_q    [BB*HH*SS*HD];      // [b,h,s,d]
__device__ float g_k    [BB*HH*SS*HD];      // [b,h,s,d]
__device__ float g_v    [BB*HH*SS*HD];      // [b,h,s,d]
__device__ float g_gate [MM*CA];
__device__ float g_bias [BB*HH*SS*SS];      // pair bias, layout [b,h,j,i] (i contiguous)
__device__ float g_go   [MM*CA];

// ---------------- helpers ----------------------------------------------------
__device__ __forceinline__ float sigmoidf_(float x) { return 1.0f / (1.0f + expf(-x)); }

__device__ __forceinline__ uint32_t f2tf32(float f) {
    uint32_t r;
    asm("cvt.rna.tf32.f32 %0, %1;" : "=r"(r) : "f"(f));
    return r;
}
// pack two floats into bf16x2: lo = first k, hi = second k
__device__ __forceinline__ uint32_t pack_bf16x2(float lo, float hi) {
    uint32_t r;
    asm("cvt.rn.bf16x2.f32 %0, %1, %2;" : "=r"(r) : "f"(hi), "f"(lo));
    return r;
}
__device__ __forceinline__ uint32_t smem_u32(const void* p) {
    uint32_t a;
    asm("{ .reg .u64 t; cvta.to.shared.u64 t, %1; cvt.u32.u64 %0, t; }"
        : "=r"(a) : "l"(p));
    return a;
}

__device__ __forceinline__ void mma_tf32(float* d, const uint32_t* a, const uint32_t* b) {
    asm volatile("mma.sync.aligned.m16n8k8.row.col.f32.tf32.tf32.f32 "
        "{%0,%1,%2,%3}, {%4,%5,%6,%7}, {%8,%9}, {%0,%1,%2,%3};"
        : "+f"(d[0]), "+f"(d[1]), "+f"(d[2]), "+f"(d[3])
        : "r"(a[0]), "r"(a[1]), "r"(a[2]), "r"(a[3]), "r"(b[0]), "r"(b[1]));
}
__device__ __forceinline__ void mma_bf16(float* d, const uint32_t* a, const uint32_t* b) {
    asm volatile("mma.sync.aligned.m16n8k16.row.col.f32.bf16.bf16.f32 "
        "{%0,%1,%2,%3}, {%4,%5,%6,%7}, {%8,%9}, {%0,%1,%2,%3};"
        : "+f"(d[0]), "+f"(d[1]), "+f"(d[2]), "+f"(d[3])
        : "r"(a[0]), "r"(a[1]), "r"(a[2]), "r"(a[3]), "r"(b[0]), "r"(b[1]));
}

__device__ float2 blockReduceSum2(float a, float b) {
    __shared__ float sa[32], sb[32];
    int lane = threadIdx.x & 31, wid = threadIdx.x >> 5;
    #pragma unroll
    for (int o = 16; o; o >>= 1) {
        a += __shfl_xor_sync(0xffffffffu, a, o);
        b += __shfl_xor_sync(0xffffffffu, b, o);
    }
    if (lane == 0) { sa[wid] = a; sb[wid] = b; }
    __syncthreads();
    if (wid == 0) {
        int nw = (blockDim.x + 31) >> 5;
        a = (lane < nw) ? sa[lane] : 0.0f;
        b = (lane < nw) ? sb[lane] : 0.0f;
        #pragma unroll
        for (int o = 16; o; o >>= 1) {
            a += __shfl_xor_sync(0xffffffffu, a, o);
            b += __shfl_xor_sync(0xffffffffu, b, o);
        }
        if (lane == 0) { sa[0] = a; sb[0] = b; }
    }
    __syncthreads();
    float2 r = make_float2(sa[0], sb[0]);
    __syncthreads();
    return r;
}

// ---------------- LN kernel --------------------------------------------------
__global__ void ln_kernel(const float* __restrict__ s, const float* __restrict__ a,
                          const float* __restrict__ gamma_s) {
    int r = blockIdx.x;
    int tid = threadIdx.x;
    const float* srow = s + (long)r * CS;
    float sum = 0.f, sq = 0.f;
    for (int c = tid; c < CS; c += blockDim.x) { float v = srow[c]; sum += v; sq += v * v; }
    float2 t = blockReduceSum2(sum, sq);
    float mean = t.x / CS, var = t.y / CS - mean * mean;
    float rstd = rsqrtf(var + EPS);
    for (int c = tid; c < CS; c += blockDim.x)
        g_sn[(long)r * CS + c] = (srow[c] - mean) * rstd * gamma_s[c];

    const float* arow = a + (long)r * CA;
    sum = 0.f; sq = 0.f;
    for (int c = tid; c < CA; c += blockDim.x) { float v = arow[c]; sum += v; sq += v * v; }
    t = blockReduceSum2(sum, sq);
    mean = t.x / CA; var = t.y / CA - mean * mean;
    rstd = rsqrtf(var + EPS);
    for (int c = tid; c < CA; c += blockDim.x)
        g_lna[(long)r * CA + c] = (arow[c] - mean) * rstd;
}

// ---------------- common GEMM machinery (128x64 tile, BK=32) ----------------
#define APITCH 36
#define BPITCH 36
#define A_WORDS (128 * APITCH)               // 4608
#define B_WORDS (64 * BPITCH)                // 2304
#define SPITCH 68
#define STAGE_WORDS (128 * SPITCH)           // 8704

__device__ __forceinline__ void frag_compute(const uint32_t* As, const uint32_t* Bs,
        float (&acc)[2][4][4], int wr, int wc, int g4, int q4) {
    #pragma unroll
    for (int kc = 0; kc < 4; kc++) {
        int kb = kc * 8 + q4;
        uint32_t af[2][4];
        #pragma unroll
        for (int mt = 0; mt < 2; mt++) {
            int r = wr + mt * 16 + g4;
            af[mt][0] = As[r * APITCH + kb];
            af[mt][1] = As[(r + 8) * APITCH + kb];
            af[mt][2] = As[r * APITCH + kb + 4];
            af[mt][3] = As[(r + 8) * APITCH + kb + 4];
        }
        #pragma unroll
        for (int nt = 0; nt < 4; nt++) {
            int c = wc + nt * 8 + g4;
            uint32_t bf[2] = {Bs[c * BPITCH + kb], Bs[c * BPITCH + kb + 4]};
            #pragma unroll
            for (int mt = 0; mt < 2; mt++)
                mma_tf32(acc[mt][nt], af[mt], bf);
        }
    }
}

__device__ __forceinline__ void frag_compute2(const uint32_t* As, const uint32_t* Bs1,
        const uint32_t* Bs2, float (&acc1)[2][4][4], float (&acc2)[2][4][4],
        int wr, int wc, int g4, int q4) {
    #pragma unroll
    for (int kc = 0; kc < 4; kc++) {
        int kb = kc * 8 + q4;
        uint32_t af[2][4];
        #pragma unroll
        for (int mt = 0; mt < 2; mt++) {
            int r = wr + mt * 16 + g4;
            af[mt][0] = As[r * APITCH + kb];
            af[mt][1] = As[(r + 8) * APITCH + kb];
            af[mt][2] = As[r * APITCH + kb + 4];
            af[mt][3] = As[(r + 8) * APITCH + kb + 4];
        }
        #pragma unroll
        for (int nt = 0; nt < 4; nt++) {
            int c = wc + nt * 8 + g4;
            uint32_t b1[2] = {Bs1[c * BPITCH + kb], Bs1[c * BPITCH + kb + 4]};
            uint32_t b2[2] = {Bs2[c * BPITCH + kb], Bs2[c * BPITCH + kb + 4]};
            #pragma unroll
            for (int mt = 0; mt < 2; mt++) {
                mma_tf32(acc1[mt][nt], af[mt], b1);
                mma_tf32(acc2[mt][nt], af[mt], b2);
            }
        }
    }
}

__device__ __forceinline__ void stage_acc(float* st, const float (&acc)[2][4][4],
        int wr, int wc, int g4, int q4) {
    #pragma unroll
    for (int mt = 0; mt < 2; mt++) {
        #pragma unroll
        for (int nt = 0; nt < 4; nt++) {
            int rr = wr + mt * 16 + g4;
            int cc = wc + nt * 8 + 2 * q4;
            st[rr * SPITCH + cc]           = acc[mt][nt][0];
            st[rr * SPITCH + cc + 1]       = acc[mt][nt][1];
            st[(rr + 8) * SPITCH + cc]     = acc[mt][nt][2];
            st[(rr + 8) * SPITCH + cc + 1] = acc[mt][nt][3];
        }
    }
}

#define ZERO_ACC(acc) { \
    _Pragma("unroll") for (int i = 0; i < 2; i++) \
    _Pragma("unroll") for (int j = 0; j < 4; j++) \
    _Pragma("unroll") for (int t = 0; t < 4; t++) acc[i][j][t] = 0.f; }

#define LDGA(pa, Abase, lda, k0) { \
    _Pragma("unroll") for (int rep = 0; rep < 4; rep++) { \
        int lin = rep * 256 + tid; int r = lin >> 3, c4 = (lin & 7) * 4; \
        pa[rep] = *(const float4*)&(Abase)[(long)(row0 + r) * (lda) + (k0) + c4]; } }
#define STSA(As, pa) { \
    _Pragma("unroll") for (int rep = 0; rep < 4; rep++) { \
        int lin = rep * 256 + tid; int r = lin >> 3, c4 = (lin & 7) * 4; \
        uint32_t* dst = &(As)[r * APITCH + c4]; \
        dst[0] = f2tf32(pa[rep].x); dst[1] = f2tf32(pa[rep].y); \
        dst[2] = f2tf32(pa[rep].z); dst[3] = f2tf32(pa[rep].w); } }
#define LDGB(pb, Bbase, ldb, k0, c0) { \
    _Pragma("unroll") for (int rep = 0; rep < 8; rep++) { \
        int lin = rep * 256 + tid; int kk = lin >> 6, n = lin & 63; \
        pb[rep] = (Bbase)[(long)((k0) + kk) * (ldb) + (c0) + n]; } }
#define STSB(Bs, pb) { \
    _Pragma("unroll") for (int rep = 0; rep < 8; rep++) { \
        int lin = rep * 256 + tid; int kk = lin >> 6, n = lin & 63; \
        (Bs)[n * BPITCH + kk] = f2tf32(pb[rep]); } }

// ---------------- adaLN fused dual GEMM --------------------------------------
#define ADA_SMEM (2 * STAGE_WORDS * 4)   // 69632 B
__global__ void __launch_bounds__(256)
gemm_ada(const float* __restrict__ Wg_, const float* __restrict__ Wo_,
         const float* __restrict__ badag) {
    extern __shared__ float sm[];
    uint32_t* As  = (uint32_t*)sm;
    uint32_t* Bs1 = As + A_WORDS;
    uint32_t* Bs2 = Bs1 + B_WORDS;

    int tid = threadIdx.x, wid = tid >> 5;
    int g4 = (tid & 31) >> 2, q4 = tid & 3;
    int wr = (wid & 3) * 32, wc = (wid >> 2) * 32;
    int row0 = blockIdx.y * 128, col0 = blockIdx.x * 64;
    const float* A = g_sn;

    float acc1[2][4][4], acc2[2][4][4];
    ZERO_ACC(acc1); ZERO_ACC(acc2);
    float4 pa[4]; float pb1[8], pb2[8];

    LDGA(pa, A, CS, 0);
    LDGB(pb1, Wg_, CA, 0, col0);
    LDGB(pb2, Wo_, CA, 0, col0);
    const int KT = CS / 32;
    for (int kt = 0; kt < KT; kt++) {
        STSA(As, pa); STSB(Bs1, pb1); STSB(Bs2, pb2);
        __syncthreads();
        if (kt + 1 < KT) {
            int k0 = (kt + 1) * 32;
            LDGA(pa, A, CS, k0);
            LDGB(pb1, Wg_, CA, k0, col0);
            LDGB(pb2, Wo_, CA, k0, col0);
        }
        frag_compute2(As, Bs1, Bs2, acc1, acc2, wr, wc, g4, q4);
        __syncthreads();
    }

    float* st1 = sm;
    float* st2 = sm + STAGE_WORDS;
    stage_acc(st1, acc1, wr, wc, g4, q4);
    stage_acc(st2, acc2, wr, wc, g4, q4);
    __syncthreads();
    #pragma unroll
    for (int rep = 0; rep < 32; rep++) {
        int idx = rep * 256 + tid;
        int r = idx >> 6, c = idx & 63;
        int m = row0 + r, n = col0 + c;
        float v1 = st1[r * SPITCH + c], v2 = st2[r * SPITCH + c];
        g_an[(long)m * CA + n] = sigmoidf_(v1 + badag[n]) * g_lna[(long)m * CA + n] + v2;
    }
}

// ---------------- fused 4-way projection GEMM --------------------------------
#define PROJ_SMEM (STAGE_WORDS * 4)      // 34816 B
__global__ void __launch_bounds__(256, 2)
gemm_proj4(const float* __restrict__ Wq, const float* __restrict__ Wk,
           const float* __restrict__ Wv, const float* __restrict__ Wg_,
           const float* __restrict__ bq) {
    extern __shared__ float sm[];
    uint32_t* As = (uint32_t*)sm;
    uint32_t* Bs = As + A_WORDS;

    int tid = threadIdx.x, wid = tid >> 5;
    int g4 = (tid & 31) >> 2, q4 = tid & 3;
    int wr = (wid & 3) * 32, wc = (wid >> 2) * 32;
    int row0 = blockIdx.y * 128;
    int cg = blockIdx.x * 64;
    int w = cg / CA, coln = cg % CA;
    const float* B = (w == 0) ? Wq : (w == 1) ? Wk : (w == 2) ? Wv : Wg_;
    const float* A = g_an;

    float acc[2][4][4];
    ZERO_ACC(acc);
    float4 pa[4]; float pb[8];

    LDGA(pa, A, CA, 0);
    LDGB(pb, B, CA, 0, coln);
    const int KT = CA / 32;
    for (int kt = 0; kt < KT; kt++) {
        STSA(As, pa); STSB(Bs, pb);
        __syncthreads();
        if (kt + 1 < KT) {
            int k0 = (kt + 1) * 32;
            LDGA(pa, A, CA, k0);
            LDGB(pb, B, CA, k0, coln);
        }
        frag_compute(As, Bs, acc, wr, wc, g4, q4);
        __syncthreads();
    }

    float* st = sm;
    stage_acc(st, acc, wr, wc, g4, q4);
    __syncthreads();
    float* dst = (w == 0) ? g_q : (w == 1) ? g_k : g_v;
    #pragma unroll
    for (int rep = 0; rep < 32; rep++) {
        int idx = rep * 256 + tid;
        int r = idx >> 6, c = idx & 63;
        int m = row0 + r, n = coln + c;
        float v = st[r * SPITCH + c];
        if (w == 3) {
            g_gate[(long)m * CA + n] = v;
        } else {
            if (w == 0) v += bq[n];
            int b = m / SS, si = m % SS, h = n / HD, d = n % HD;
            dst[(((long)(b * HH + h) * SS) + si) * HD + d] = v;
        }
    }
}

// ---------------- fused output GEMM ------------------------------------------
__global__ void __launch_bounds__(256)
gemm_final(const float* __restrict__ Wout, const float* __restrict__ s_,
           const float* __restrict__ Wsg, const float* __restrict__ bsg,
           float* __restrict__ out) {
    extern __shared__ float sm[];
    uint32_t* As = (uint32_t*)sm;
    uint32_t* Bs = As + A_WORDS;

    int tid = threadIdx.x, wid = tid >> 5;
    int g4 = (tid & 31) >> 2, q4 = tid & 3;
    int wr = (wid & 3) * 32, wc = (wid >> 2) * 32;
    int row0 = blockIdx.y * 128, col0 = blockIdx.x * 64;

    float acc1[2][4][4], acc2[2][4][4];
    ZERO_ACC(acc1); ZERO_ACC(acc2);
    float4 pa[4]; float pb[8];

    {
        const float* A = g_go;
        LDGA(pa, A, CA, 0);
        LDGB(pb, Wout, CA, 0, col0);
        const int KT = CA / 32;
        for (int kt = 0; kt < KT; kt++) {
            STSA(As, pa); STSB(Bs, pb);
            __syncthreads();
            if (kt + 1 < KT) {
                int k0 = (kt + 1) * 32;
                LDGA(pa, A, CA, k0);
                LDGB(pb, Wout, CA, k0, col0);
            }
            frag_compute(As, Bs, acc1, wr, wc, g4, q4);
            __syncthreads();
        }
    }
    {
        LDGA(pa, s_, CS, 0);
        LDGB(pb, Wsg, CA, 0, col0);
        const int KT = CS / 32;
        for (int kt = 0; kt < KT; kt++) {
            STSA(As, pa); STSB(Bs, pb);
            __syncthreads();
            if (kt + 1 < KT) {
                int k0 = (kt + 1) * 32;
                LDGA(pa, s_, CS, k0);
                LDGB(pb, Wsg, CA, k0, col0);
            }
            frag_compute(As, Bs, acc2, wr, wc, g4, q4);
            __syncthreads();
        }
    }

    #pragma unroll
    for (int mt = 0; mt < 2; mt++)
        #pragma unroll
        for (int nt = 0; nt < 4; nt++)
            #pragma unroll
            for (int t = 0; t < 4; t++) {
                int n = col0 + wc + nt * 8 + 2 * q4 + (t & 1);
                acc1[mt][nt][t] *= sigmoidf_(acc2[mt][nt][t] + __ldg(&bsg[n]));
            }

    float* st = sm;
    stage_acc(st, acc1, wr, wc, g4, q4);
    __syncthreads();
    #pragma unroll
    for (int rep = 0; rep < 32; rep++) {
        int idx = rep * 256 + tid;
        int r = idx >> 6, c = idx & 63;
        out[(long)(row0 + r) * CA + col0 + c] = st[r * SPITCH + c];
    }
}

// ---------------- pair bias v7: bf16 MMA + ldmatrix fragment loads -----------
// Block handles (b, p=j, q-tile of 64 i values). z slab contiguous (32KB).
// smem: Z16[64 x WP bf16x2 words] (res aliased on top) + Wb16[16 x WP] = 21760 B.
// beta preloaded into 4 regs/thread (linear coalesced), added after MMA.
// Output: g_bias[b][h][p][q0..q0+63] (contiguous per h).
#define WP 68
#define PB_Z_WORDS (64 * WP)                         // 4352
#define PB_WB_OFF  PB_Z_WORDS
#define PB_SMEM ((PB_Z_WORDS + 16 * WP) * 4)         // 21760 B
__global__ void __launch_bounds__(256)
pairbias7_kernel(const float* __restrict__ z, const float* __restrict__ beta,
                 const float* __restrict__ Wb, const float* __restrict__ gz,
                 const float* __restrict__ bz) {
    extern __shared__ float smf[];
    uint32_t* Z16  = (uint32_t*)smf;           // [64][WP] bf16x2
    uint32_t* Wb16 = Z16 + PB_WB_OFF;          // [16][WP] bf16x2
    float*    res  = smf;                      // aliased over Z16 after MMA
    __shared__ float gzs[CZ], bzs[CZ];

    int tid = threadIdx.x, wid = tid >> 5, lane = tid & 31;
    int g4 = lane >> 2, q4 = lane & 3;
    int b = blockIdx.z, p = blockIdx.y, q0 = blockIdx.x * 64;

    const float* zb = z + ((long)(b * SS + p) * SS + q0) * CZ;
    const float* betab = beta + ((long)(b * SS + p) * SS + q0) * HH;

    // preload beta slab (1024 consecutive floats) into regs, coalesced
    float betar[4];
    #pragma unroll
    for (int rep = 0; rep < 4; rep++)
        betar[rep] = betab[rep * 256 + tid];

    // stage Wb transposed as bf16x2: Wb16[h][j] = (Wb[2j][h], Wb[2j+1][h])
    for (int idx = tid; idx < (CZ / 2) * HH; idx += 256) {
        int j = idx >> 4, h = idx & 15;
        Wb16[h * WP + j] = pack_bf16x2(Wb[(2 * j) * HH + h], Wb[(2 * j + 1) * HH + h]);
    }
    for (int idx = tid; idx < CZ; idx += 256) { gzs[idx] = gz[idx]; bzs[idx] = bz[idx]; }
    __syncthreads();

    // LN of 64 contiguous z-rows -> bf16x2. Warp w: rows 8w..8w+7 (MLP 8).
    {
        float4 vr[8];
        #pragma unroll
        for (int rr = 0; rr < 8; rr++) {
            int pl = wid * 8 + rr;
            vr[rr] = *(const float4*)&zb[(long)pl * CZ + lane * 4];
        }
        float sums[8], sqs[8];
        #pragma unroll
        for (int rr = 0; rr < 8; rr++) {
            float4 v = vr[rr];
            sums[rr] = v.x + v.y + v.z + v.w;
            sqs[rr]  = v.x * v.x + v.y * v.y + v.z * v.z + v.w * v.w;
        }
        #pragma unroll
        for (int o = 16; o; o >>= 1) {
            #pragma unroll
            for (int rr = 0; rr < 8; rr++) {
                sums[rr] += __shfl_xor_sync(0xffffffffu, sums[rr], o);
                sqs[rr]  += __shfl_xor_sync(0xffffffffu, sqs[rr],  o);
            }
        }
        #pragma unroll
        for (int rr = 0; rr < 8; rr++) {
            int pl = wid * 8 + rr;
            float mean = sums[rr] * (1.0f / CZ);
            float var  = sqs[rr] * (1.0f / CZ) - mean * mean;
            float rstd = rsqrtf(var + EPS);
            float4 v = vr[rr];
            int c = lane * 4;
            float z0 = (v.x - mean) * rstd * gzs[c + 0] + bzs[c + 0];
            float z1 = (v.y - mean) * rstd * gzs[c + 1] + bzs[c + 1];
            float z2 = (v.z - mean) * rstd * gzs[c + 2] + bzs[c + 2];
            float z3 = (v.w - mean) * rstd * gzs[c + 3] + bzs[c + 3];
            uint2 o2;
            o2.x = pack_bf16x2(z0, z1);
            o2.y = pack_bf16x2(z2, z3);
            *(uint2*)&Z16[pl * WP + lane * 2] = o2;
        }
    }
    __syncthreads();

    // mma bf16 m16n8k16 with ldmatrix fragment loads. ALL 8 warps:
    // warp w: row-group (w&3)*16, h-half (w>>2)*8. 8 kc (k=16 each).
    float acc[4];
    #pragma unroll
    for (int t = 0; t < 4; t++) acc[t] = 0.f;
    {
        int wr = (wid & 3) * 16;
        int hb = (wid >> 2) * 8;
        // A: x4 — m0 rows wr..+7 w[8kc..+3]; m1 rows +8..+15 same; m2/m3 w+4
        uint32_t a_addr = smem_u32(Z16) +
            (((wr + (lane & 15)) * WP + ((lane >> 4) << 2)) << 2);
        // B: x2 — m0 rows hb..+7 w[8kc..+3]; m1 same rows w+4 (lanes 0-15 used)
        uint32_t b_addr = smem_u32(Wb16) +
            (((hb + (lane & 7)) * WP + (((lane >> 3) & 1) << 2)) << 2);
        #pragma unroll
        for (int kc = 0; kc < 8; kc++) {
            uint32_t af[4], bf[2];
            asm volatile("ldmatrix.sync.aligned.m8n8.x4.shared.b16 {%0,%1,%2,%3}, [%4];"
                : "=r"(af[0]), "=r"(af[1]), "=r"(af[2]), "=r"(af[3])
                : "r"(a_addr + kc * 32));
            asm volatile("ldmatrix.sync.aligned.m8n8.x2.shared.b16 {%0,%1}, [%2];"
                : "=r"(bf[0]), "=r"(bf[1])
                : "r"(b_addr + kc * 32));
            mma_bf16(acc, af, bf);
        }
    }
    __syncthreads();   // all Z16 reads done; res may alias Z16 now

    // write res[row*17 + h]
    {
        int wr = (wid & 3) * 16;
        int hb = (wid >> 2) * 8;
        #pragma unroll
        for (int t = 0; t < 4; t++) {
            int row = wr + g4 + ((t >= 2) ? 8 : 0);
            int h = hb + 2 * q4 + (t & 1);
            res[row * 17 + h] = acc[t];
        }
    }
    __syncthreads();

    // add beta (linear mapping: idx = ql*16 + h)
    #pragma unroll
    for (int rep = 0; rep < 4; rep++) {
        int idx = rep * 256 + tid;
        int ql = idx >> 4, hh = idx & 15;
        res[ql * 17 + hh] += betar[rep];
    }
    __syncthreads();

    // coalesced store: g_bias[b][h][p][q0+ql] (contiguous runs of 64 per h)
    #pragma unroll
    for (int rep = 0; rep < 4; rep++) {
        int idx = rep * 256 + tid;
        int h = idx >> 6, ql = idx & 63;
        g_bias[(((long)(b * HH + h) * SS) + p) * SS + q0 + ql] = res[ql * 17 + h];
    }
}

// ---------------- fused attention: softmax(scale*QK^T + bias) @ V, gated ----
// bias layout [b,h,j,i] consumed directly via __ldg (L2-resident — just written).
#define QP 52
#define KP 52
#define VP 68
#define PP 68
#define AT_K (128 * QP)
#define AT_V (AT_K + 64 * KP)
#define AT_PB (AT_V + 48 * VP)
#define AT_WORDS (AT_PB + 128 * PP)
#define ATT_SMEM (AT_WORDS * 4)              // 87808 B

__global__ void __launch_bounds__(256, 2)
attn_kernel(const float* __restrict__ qg, const float* __restrict__ kg,
            const float* __restrict__ vg, const float* __restrict__ biasg,
            const float* __restrict__ gateg, float* __restrict__ outg) {
    extern __shared__ char smem[];
    uint32_t* Qs = (uint32_t*)smem;
    uint32_t* Ks = Qs + AT_K;
    uint32_t* Vs = Qs + AT_V;
    uint32_t* Ps = Qs + AT_PB;

    int tid = threadIdx.x, wid = tid >> 5, lane = tid & 31;
    int g4 = lane >> 2, q4 = lane & 3;
    int bh = blockIdx.y;
    int b = bh >> 4, h = bh & 15;
    int i0 = blockIdx.x * 128;
    const float* qb = qg + ((long)bh * SS + i0) * HD;
    const float* kb_ = kg + (long)bh * SS * HD;
    const float* vb = vg + (long)bh * SS * HD;
    const float* biasb = biasg + (long)bh * SS * SS;   // [j][i]

    #pragma unroll
    for (int rep = 0; rep < 6; rep++) {
        int idx = rep * 256 + tid;
        int r = idx / 12, c4 = (idx % 12) * 4;
        float4 v = *(const float4*)&qb[(long)r * HD + c4];
        uint32_t* d = &Qs[r * QP + c4];
        d[0] = f2tf32(v.x); d[1] = f2tf32(v.y); d[2] = f2tf32(v.z); d[3] = f2tf32(v.w);
    }

    int wr = wid * 16;
    float accO[6][4];
    #pragma unroll
    for (int n = 0; n < 6; n++)
        #pragma unroll
        for (int t = 0; t < 4; t++) accO[n][t] = 0.f;
    float mrow[2] = {-1e30f, -1e30f};
    float lrow[2] = {0.f, 0.f};

    for (int j = 0; j < 12; j++) {
        __syncthreads();
        #pragma unroll
        for (int rep = 0; rep < 3; rep++) {
            int idx = rep * 256 + tid;
            int r = idx / 12, c4 = (idx % 12) * 4;
            float4 v = *(const float4*)&kb_[(long)(j * 64 + r) * HD + c4];
            uint32_t* d = &Ks[r * KP + c4];
            d[0] = f2tf32(v.x); d[1] = f2tf32(v.y); d[2] = f2tf32(v.z); d[3] = f2tf32(v.w);
        }
        #pragma unroll
        for (int rep = 0; rep < 12; rep++) {
            int idx = rep * 256 + tid;
            int r = idx / 48, d = idx % 48;
            Vs[d * VP + r] = f2tf32(vb[(long)(j * 64 + r) * HD + d]);
        }
        __syncthreads();

        float S[8][4];
        #pragma unroll
        for (int nt = 0; nt < 8; nt++)
            #pragma unroll
            for (int t = 0; t < 4; t++) S[nt][t] = 0.f;
        #pragma unroll
        for (int kc = 0; kc < 6; kc++) {
            int kbx = kc * 8 + q4;
            uint32_t af[4];
            af[0] = Qs[(wr + g4) * QP + kbx];
            af[1] = Qs[(wr + g4 + 8) * QP + kbx];
            af[2] = Qs[(wr + g4) * QP + kbx + 4];
            af[3] = Qs[(wr + g4 + 8) * QP + kbx + 4];
            #pragma unroll
            for (int nt = 0; nt < 8; nt++) {
                uint32_t bf2[2];
                bf2[0] = Ks[(nt * 8 + g4) * KP + kbx];
                bf2[1] = Ks[(nt * 8 + g4) * KP + kbx + 4];
                mma_tf32(S[nt], af, bf2);
            }
        }
        // bias read directly from gmem (L2-resident), at fragment coordinates
        const float* bj = biasb + (long)(j * 64) * SS + i0;
        int r0 = wr + g4, r1 = r0 + 8;
        float mn0 = mrow[0], mn1 = mrow[1];
        #pragma unroll
        for (int nt = 0; nt < 8; nt++) {
            #pragma unroll
            for (int t = 0; t < 4; t++) {
                int rr = (t >= 2) ? r1 : r0;
                int cc = nt * 8 + 2 * q4 + (t & 1);
                float val = S[nt][t] * SCALE + __ldg(&bj[(long)cc * SS + rr]);
                S[nt][t] = val;
                if (t < 2) mn0 = fmaxf(mn0, val); else mn1 = fmaxf(mn1, val);
            }
        }
        mn0 = fmaxf(mn0, __shfl_xor_sync(0xffffffffu, mn0, 1));
        mn0 = fmaxf(mn0, __shfl_xor_sync(0xffffffffu, mn0, 2));
        mn1 = fmaxf(mn1, __shfl_xor_sync(0xffffffffu, mn1, 1));
        mn1 = fmaxf(mn1, __shfl_xor_sync(0xffffffffu, mn1, 2));
        float al0 = __expf(mrow[0] - mn0);
        float al1 = __expf(mrow[1] - mn1);
        mrow[0] = mn0; mrow[1] = mn1;
        float s0 = 0.f, s1 = 0.f;
        #pragma unroll
        for (int nt = 0; nt < 8; nt++) {
            #pragma unroll
            for (int t = 0; t < 4; t++) {
                float p = __expf(S[nt][t] - ((t >= 2) ? mn1 : mn0));
                S[nt][t] = p;
                if (t < 2) s0 += p; else s1 += p;
                int rr = (t >= 2) ? r1 : r0;
                int cc = nt * 8 + 2 * q4 + (t & 1);
                Ps[rr * PP + cc] = f2tf32(p);
            }
        }
        s0 += __shfl_xor_sync(0xffffffffu, s0, 1);
        s0 += __shfl_xor_sync(0xffffffffu, s0, 2);
        s1 += __shfl_xor_sync(0xffffffffu, s1, 1);
        s1 += __shfl_xor_sync(0xffffffffu, s1, 2);
        lrow[0] = lrow[0] * al0 + s0;
        lrow[1] = lrow[1] * al1 + s1;
        #pragma unroll
        for (int n = 0; n < 6; n++) {
            accO[n][0] *= al0; accO[n][1] *= al0;
            accO[n][2] *= al1; accO[n][3] *= al1;
        }
        __syncwarp();
        #pragma unroll
        for (int kc = 0; kc < 8; kc++) {
            int kbx = kc * 8 + q4;
            uint32_t af[4];
            af[0] = Ps[(wr + g4) * PP + kbx];
            af[1] = Ps[(wr + g4 + 8) * PP + kbx];
            af[2] = Ps[(wr + g4) * PP + kbx + 4];
            af[3] = Ps[(wr + g4 + 8) * PP + kbx + 4];
            #pragma unroll
            for (int n = 0; n < 6; n++) {
                uint32_t bf2[2];
                bf2[0] = Vs[(n * 8 + g4) * VP + kbx];
                bf2[1] = Vs[(n * 8 + g4) * VP + kbx + 4];
                mma_tf32(accO[n], af, bf2);
            }
        }
    }

    float inv0 = 1.0f / lrow[0], inv1 = 1.0f / lrow[1];
    #pragma unroll
    for (int n = 0; n < 6; n++) {
        #pragma unroll
        for (int t = 0; t < 4; t++) {
            int r = wr + g4 + ((t >= 2) ? 8 : 0);
            int c = n * 8 + 2 * q4 + (t & 1);
            long gi = ((long)(b * SS + i0 + r)) * CA + h * HD + c;
            float o = accO[n][t] * ((t >= 2) ? inv1 : inv0);
            outg[gi] = o * sigmoidf_(gateg[gi]);
        }
    }
}

// ---------------- host side --------------------------------------------------
static float* sym(const void* symbol) {
    void* p = nullptr;
    cudaGetSymbolAddress(&p, symbol);
    return (float*)p;
}

extern "C" void kernel_launch(void* const* d_in, const int* in_sizes, int n_in,
                              void* d_out, int out_size) {
    const float* a        = (const float*)d_in[0];
    const float* s        = (const float*)d_in[1];
    const float* z        = (const float*)d_in[2];
    const float* beta     = (const float*)d_in[3];
    const float* gamma_s  = (const float*)d_in[4];
    const float* W_ada_g  = (const float*)d_in[5];
    const float* b_ada_g  = (const float*)d_in[6];
    const float* W_ada_o  = (const float*)d_in[7];
    const float* Wq       = (const float*)d_in[8];
    const float* bq       = (const float*)d_in[9];
    const float* Wk       = (const float*)d_in[10];
    const float* Wv       = (const float*)d_in[11];
    const float* Wb       = (const float*)d_in[12];
    const float* gz       = (const float*)d_in[13];
    const float* bz       = (const float*)d_in[14];
    const float* Wg       = (const float*)d_in[15];
    const float* Wout     = (const float*)d_in[16];
    const float* Ws_gate  = (const float*)d_in[17];
    const float* bs_gate  = (const float*)d_in[18];
    float* out = (float*)d_out;

    float* p_q    = sym(g_q);
    float* p_k    = sym(g_k);
    float* p_v    = sym(g_v);
    float* p_gate = sym(g_gate);
    float* p_bias = sym(g_bias);
    float* p_go   = sym(g_go);

    cudaFuncSetAttribute(gemm_ada,        cudaFuncAttributeMaxDynamicSharedMemorySize, ADA_SMEM);
    cudaFuncSetAttribute(gemm_proj4,      cudaFuncAttributeMaxDynamicSharedMemorySize, PROJ_SMEM);
    cudaFuncSetAttribute(gemm_final,      cudaFuncAttributeMaxDynamicSharedMemorySize, PROJ_SMEM);
    cudaFuncSetAttribute(pairbias7_kernel,cudaFuncAttributeMaxDynamicSharedMemorySize, PB_SMEM);
    cudaFuncSetAttribute(attn_kernel,     cudaFuncAttributeMaxDynamicSharedMemorySize, ATT_SMEM);

    // 1. layer norms
    ln_kernel<<<MM, 256>>>(s, a, gamma_s);
    // 2. adaLN (fused dual GEMM)
    gemm_ada<<<dim3(CA / 64, MM / 128), 256, ADA_SMEM>>>(W_ada_g, W_ada_o, b_ada_g);
    // 3. 4-way projections (2 CTAs/SM)
    gemm_proj4<<<dim3(4 * CA / 64, MM / 128), 256, PROJ_SMEM>>>(Wq, Wk, Wv, Wg, bq);
    // 4. pair bias (bf16 MMA + ldmatrix)
    pairbias7_kernel<<<dim3(SS / 64, SS, BB), 256, PB_SMEM>>>(z, beta, Wb, gz, bz);
    // 5. fused attention (direct-gmem bias)
    attn_kernel<<<dim3(SS / 128, BB * HH), 256, ATT_SMEM>>>(p_q, p_k, p_v, p_bias, p_gate, p_go);
    // 6. fused output GEMM + s-gate
    gemm_final<<<dim3(CA / 64, MM / 128), 256, PROJ_SMEM>>>(Wout, s, Ws_gate, bs_gate, out);
}

// round 12
// speedup vs baseline: 3.5533x; 1.0138x over previous
#include <cuda_runtime.h>
#include <cuda_bf16.h>
#include <math.h>
#include <cstdint>

// Problem constants
#define BB   2
#define SS   768
#define CA   768
#define CS   384
#define CZ   128
#define HH   16
#define HD   48
#define MM   (BB*SS)          // 1536
#define EPS  1e-5f
#define SCALE (0.14433756729740643f)  // 1/sqrt(48)

// ---------------- scratch (device globals) ----------------------------------
__device__ float g_sn   [MM*CS];
__device__ float g_lna  [MM*CA];
__device__ float g_an   [MM*CA];
__device__ float g_q    [BB*HH*SS*HD];      // [b,h,s,d]
__device__ float g_k    [BB*HH*SS*HD];      // [b,h,s,d]
__device__ float g_v    [BB*HH*SS*HD];      // [b,h,s,d]
__device__ float g_gate [MM*CA];
__device__ float g_bias [BB*HH*SS*SS];      // pair bias, layout [b,h,j,i] (i contiguous)
__device__ float g_go   [MM*CA];

// ---------------- helpers ----------------------------------------------------
__device__ __forceinline__ float sigmoidf_(float x) { return 1.0f / (1.0f + expf(-x)); }

__device__ __forceinline__ uint32_t f2tf32(float f) {
    uint32_t r;
    asm("cvt.rna.tf32.f32 %0, %1;" : "=r"(r) : "f"(f));
    return r;
}
__device__ __forceinline__ uint32_t pack_bf16x2(float lo, float hi) {
    uint32_t r;
    asm("cvt.rn.bf16x2.f32 %0, %1, %2;" : "=r"(r) : "f"(hi), "f"(lo));
    return r;
}

__device__ __forceinline__ void mma_tf32(float* d, const uint32_t* a, const uint32_t* b) {
    asm volatile("mma.sync.aligned.m16n8k8.row.col.f32.tf32.tf32.f32 "
        "{%0,%1,%2,%3}, {%4,%5,%6,%7}, {%8,%9}, {%0,%1,%2,%3};"
        : "+f"(d[0]), "+f"(d[1]), "+f"(d[2]), "+f"(d[3])
        : "r"(a[0]), "r"(a[1]), "r"(a[2]), "r"(a[3]), "r"(b[0]), "r"(b[1]));
}
__device__ __forceinline__ void mma_bf16(float* d, const uint32_t* a, const uint32_t* b) {
    asm volatile("mma.sync.aligned.m16n8k16.row.col.f32.bf16.bf16.f32 "
        "{%0,%1,%2,%3}, {%4,%5,%6,%7}, {%8,%9}, {%0,%1,%2,%3};"
        : "+f"(d[0]), "+f"(d[1]), "+f"(d[2]), "+f"(d[3])
        : "r"(a[0]), "r"(a[1]), "r"(a[2]), "r"(a[3]), "r"(b[0]), "r"(b[1]));
}

__device__ float2 blockReduceSum2(float a, float b) {
    __shared__ float sa[32], sb[32];
    int lane = threadIdx.x & 31, wid = threadIdx.x >> 5;
    #pragma unroll
    for (int o = 16; o; o >>= 1) {
        a += __shfl_xor_sync(0xffffffffu, a, o);
        b += __shfl_xor_sync(0xffffffffu, b, o);
    }
    if (lane == 0) { sa[wid] = a; sb[wid] = b; }
    __syncthreads();
    if (wid == 0) {
        int nw = (blockDim.x + 31) >> 5;
        a = (lane < nw) ? sa[lane] : 0.0f;
        b = (lane < nw) ? sb[lane] : 0.0f;
        #pragma unroll
        for (int o = 16; o; o >>= 1) {
            a += __shfl_xor_sync(0xffffffffu, a, o);
            b += __shfl_xor_sync(0xffffffffu, b, o);
        }
        if (lane == 0) { sa[0] = a; sb[0] = b; }
    }
    __syncthreads();
    float2 r = make_float2(sa[0], sb[0]);
    __syncthreads();
    return r;
}

// ---------------- LN kernel --------------------------------------------------
__global__ void ln_kernel(const float* __restrict__ s, const float* __restrict__ a,
                          const float* __restrict__ gamma_s) {
    int r = blockIdx.x;
    int tid = threadIdx.x;
    const float* srow = s + (long)r * CS;
    float sum = 0.f, sq = 0.f;
    for (int c = tid; c < CS; c += blockDim.x) { float v = srow[c]; sum += v; sq += v * v; }
    float2 t = blockReduceSum2(sum, sq);
    float mean = t.x / CS, var = t.y / CS - mean * mean;
    float rstd = rsqrtf(var + EPS);
    for (int c = tid; c < CS; c += blockDim.x)
        g_sn[(long)r * CS + c] = (srow[c] - mean) * rstd * gamma_s[c];

    const float* arow = a + (long)r * CA;
    sum = 0.f; sq = 0.f;
    for (int c = tid; c < CA; c += blockDim.x) { float v = arow[c]; sum += v; sq += v * v; }
    t = blockReduceSum2(sum, sq);
    mean = t.x / CA; var = t.y / CA - mean * mean;
    rstd = rsqrtf(var + EPS);
    for (int c = tid; c < CA; c += blockDim.x)
        g_lna[(long)r * CA + c] = (arow[c] - mean) * rstd;
}

// ---------------- common GEMM machinery (128x64 tile, BK=32) ----------------
#define APITCH 36
#define BPITCH 36
#define A_WORDS (128 * APITCH)               // 4608
#define B_WORDS (64 * BPITCH)                // 2304
#define SPITCH 68
#define STAGE_WORDS (128 * SPITCH)           // 8704

__device__ __forceinline__ void frag_compute(const uint32_t* As, const uint32_t* Bs,
        float (&acc)[2][4][4], int wr, int wc, int g4, int q4) {
    #pragma unroll
    for (int kc = 0; kc < 4; kc++) {
        int kb = kc * 8 + q4;
        uint32_t af[2][4];
        #pragma unroll
        for (int mt = 0; mt < 2; mt++) {
            int r = wr + mt * 16 + g4;
            af[mt][0] = As[r * APITCH + kb];
            af[mt][1] = As[(r + 8) * APITCH + kb];
            af[mt][2] = As[r * APITCH + kb + 4];
            af[mt][3] = As[(r + 8) * APITCH + kb + 4];
        }
        #pragma unroll
        for (int nt = 0; nt < 4; nt++) {
            int c = wc + nt * 8 + g4;
            uint32_t bf[2] = {Bs[c * BPITCH + kb], Bs[c * BPITCH + kb + 4]};
            #pragma unroll
            for (int mt = 0; mt < 2; mt++)
                mma_tf32(acc[mt][nt], af[mt], bf);
        }
    }
}

__device__ __forceinline__ void frag_compute2(const uint32_t* As, const uint32_t* Bs1,
        const uint32_t* Bs2, float (&acc1)[2][4][4], float (&acc2)[2][4][4],
        int wr, int wc, int g4, int q4) {
    #pragma unroll
    for (int kc = 0; kc < 4; kc++) {
        int kb = kc * 8 + q4;
        uint32_t af[2][4];
        #pragma unroll
        for (int mt = 0; mt < 2; mt++) {
            int r = wr + mt * 16 + g4;
            af[mt][0] = As[r * APITCH + kb];
            af[mt][1] = As[(r + 8) * APITCH + kb];
            af[mt][2] = As[r * APITCH + kb + 4];
            af[mt][3] = As[(r + 8) * APITCH + kb + 4];
        }
        #pragma unroll
        for (int nt = 0; nt < 4; nt++) {
            int c = wc + nt * 8 + g4;
            uint32_t b1[2] = {Bs1[c * BPITCH + kb], Bs1[c * BPITCH + kb + 4]};
            uint32_t b2[2] = {Bs2[c * BPITCH + kb], Bs2[c * BPITCH + kb + 4]};
            #pragma unroll
            for (int mt = 0; mt < 2; mt++) {
                mma_tf32(acc1[mt][nt], af[mt], b1);
                mma_tf32(acc2[mt][nt], af[mt], b2);
            }
        }
    }
}

__device__ __forceinline__ void stage_acc(float* st, const float (&acc)[2][4][4],
        int wr, int wc, int g4, int q4) {
    #pragma unroll
    for (int mt = 0; mt < 2; mt++) {
        #pragma unroll
        for (int nt = 0; nt < 4; nt++) {
            int rr = wr + mt * 16 + g4;
            int cc = wc + nt * 8 + 2 * q4;
            st[rr * SPITCH + cc]           = acc[mt][nt][0];
            st[rr * SPITCH + cc + 1]       = acc[mt][nt][1];
            st[(rr + 8) * SPITCH + cc]     = acc[mt][nt][2];
            st[(rr + 8) * SPITCH + cc + 1] = acc[mt][nt][3];
        }
    }
}

#define ZERO_ACC(acc) { \
    _Pragma("unroll") for (int i = 0; i < 2; i++) \
    _Pragma("unroll") for (int j = 0; j < 4; j++) \
    _Pragma("unroll") for (int t = 0; t < 4; t++) acc[i][j][t] = 0.f; }

#define LDGA(pa, Abase, lda, k0) { \
    _Pragma("unroll") for (int rep = 0; rep < 4; rep++) { \
        int lin = rep * 256 + tid; int r = lin >> 3, c4 = (lin & 7) * 4; \
        pa[rep] = *(const float4*)&(Abase)[(long)(row0 + r) * (lda) + (k0) + c4]; } }
#define STSA(As, pa) { \
    _Pragma("unroll") for (int rep = 0; rep < 4; rep++) { \
        int lin = rep * 256 + tid; int r = lin >> 3, c4 = (lin & 7) * 4; \
        uint32_t* dst = &(As)[r * APITCH + c4]; \
        dst[0] = f2tf32(pa[rep].x); dst[1] = f2tf32(pa[rep].y); \
        dst[2] = f2tf32(pa[rep].z); dst[3] = f2tf32(pa[rep].w); } }
#define LDGB(pb, Bbase, ldb, k0, c0) { \
    _Pragma("unroll") for (int rep = 0; rep < 8; rep++) { \
        int lin = rep * 256 + tid; int kk = lin >> 6, n = lin & 63; \
        pb[rep] = (Bbase)[(long)((k0) + kk) * (ldb) + (c0) + n]; } }
#define STSB(Bs, pb) { \
    _Pragma("unroll") for (int rep = 0; rep < 8; rep++) { \
        int lin = rep * 256 + tid; int kk = lin >> 6, n = lin & 63; \
        (Bs)[n * BPITCH + kk] = f2tf32(pb[rep]); } }

// ---------------- adaLN fused dual GEMM --------------------------------------
#define ADA_SMEM (2 * STAGE_WORDS * 4)   // 69632 B
__global__ void __launch_bounds__(256)
gemm_ada(const float* __restrict__ Wg_, const float* __restrict__ Wo_,
         const float* __restrict__ badag) {
    extern __shared__ float sm[];
    uint32_t* As  = (uint32_t*)sm;
    uint32_t* Bs1 = As + A_WORDS;
    uint32_t* Bs2 = Bs1 + B_WORDS;

    int tid = threadIdx.x, wid = tid >> 5;
    int g4 = (tid & 31) >> 2, q4 = tid & 3;
    int wr = (wid & 3) * 32, wc = (wid >> 2) * 32;
    int row0 = blockIdx.y * 128, col0 = blockIdx.x * 64;
    const float* A = g_sn;

    float acc1[2][4][4], acc2[2][4][4];
    ZERO_ACC(acc1); ZERO_ACC(acc2);
    float4 pa[4]; float pb1[8], pb2[8];

    LDGA(pa, A, CS, 0);
    LDGB(pb1, Wg_, CA, 0, col0);
    LDGB(pb2, Wo_, CA, 0, col0);
    const int KT = CS / 32;
    for (int kt = 0; kt < KT; kt++) {
        STSA(As, pa); STSB(Bs1, pb1); STSB(Bs2, pb2);
        __syncthreads();
        if (kt + 1 < KT) {
            int k0 = (kt + 1) * 32;
            LDGA(pa, A, CS, k0);
            LDGB(pb1, Wg_, CA, k0, col0);
            LDGB(pb2, Wo_, CA, k0, col0);
        }
        frag_compute2(As, Bs1, Bs2, acc1, acc2, wr, wc, g4, q4);
        __syncthreads();
    }

    float* st1 = sm;
    float* st2 = sm + STAGE_WORDS;
    stage_acc(st1, acc1, wr, wc, g4, q4);
    stage_acc(st2, acc2, wr, wc, g4, q4);
    __syncthreads();
    #pragma unroll
    for (int rep = 0; rep < 32; rep++) {
        int idx = rep * 256 + tid;
        int r = idx >> 6, c = idx & 63;
        int m = row0 + r, n = col0 + c;
        float v1 = st1[r * SPITCH + c], v2 = st2[r * SPITCH + c];
        g_an[(long)m * CA + n] = sigmoidf_(v1 + badag[n]) * g_lna[(long)m * CA + n] + v2;
    }
}

// ---------------- fused 4-way projection GEMM --------------------------------
#define PROJ_SMEM (STAGE_WORDS * 4)      // 34816 B
__global__ void __launch_bounds__(256, 2)
gemm_proj4(const float* __restrict__ Wq, const float* __restrict__ Wk,
           const float* __restrict__ Wv, const float* __restrict__ Wg_,
           const float* __restrict__ bq) {
    extern __shared__ float sm[];
    uint32_t* As = (uint32_t*)sm;
    uint32_t* Bs = As + A_WORDS;

    int tid = threadIdx.x, wid = tid >> 5;
    int g4 = (tid & 31) >> 2, q4 = tid & 3;
    int wr = (wid & 3) * 32, wc = (wid >> 2) * 32;
    int row0 = blockIdx.y * 128;
    int cg = blockIdx.x * 64;
    int w = cg / CA, coln = cg % CA;
    const float* B = (w == 0) ? Wq : (w == 1) ? Wk : (w == 2) ? Wv : Wg_;
    const float* A = g_an;

    float acc[2][4][4];
    ZERO_ACC(acc);
    float4 pa[4]; float pb[8];

    LDGA(pa, A, CA, 0);
    LDGB(pb, B, CA, 0, coln);
    const int KT = CA / 32;
    for (int kt = 0; kt < KT; kt++) {
        STSA(As, pa); STSB(Bs, pb);
        __syncthreads();
        if (kt + 1 < KT) {
            int k0 = (kt + 1) * 32;
            LDGA(pa, A, CA, k0);
            LDGB(pb, B, CA, k0, coln);
        }
        frag_compute(As, Bs, acc, wr, wc, g4, q4);
        __syncthreads();
    }

    float* st = sm;
    stage_acc(st, acc, wr, wc, g4, q4);
    __syncthreads();
    float* dst = (w == 0) ? g_q : (w == 1) ? g_k : g_v;
    #pragma unroll
    for (int rep = 0; rep < 32; rep++) {
        int idx = rep * 256 + tid;
        int r = idx >> 6, c = idx & 63;
        int m = row0 + r, n = coln + c;
        float v = st[r * SPITCH + c];
        if (w == 3) {
            g_gate[(long)m * CA + n] = v;
        } else {
            if (w == 0) v += bq[n];
            int b = m / SS, si = m % SS, h = n / HD, d = n % HD;
            dst[(((long)(b * HH + h) * SS) + si) * HD + d] = v;
        }
    }
}

// ---------------- fused output GEMM ------------------------------------------
__global__ void __launch_bounds__(256)
gemm_final(const float* __restrict__ Wout, const float* __restrict__ s_,
           const float* __restrict__ Wsg, const float* __restrict__ bsg,
           float* __restrict__ out) {
    extern __shared__ float sm[];
    uint32_t* As = (uint32_t*)sm;
    uint32_t* Bs = As + A_WORDS;

    int tid = threadIdx.x, wid = tid >> 5;
    int g4 = (tid & 31) >> 2, q4 = tid & 3;
    int wr = (wid & 3) * 32, wc = (wid >> 2) * 32;
    int row0 = blockIdx.y * 128, col0 = blockIdx.x * 64;

    float acc1[2][4][4], acc2[2][4][4];
    ZERO_ACC(acc1); ZERO_ACC(acc2);
    float4 pa[4]; float pb[8];

    {
        const float* A = g_go;
        LDGA(pa, A, CA, 0);
        LDGB(pb, Wout, CA, 0, col0);
        const int KT = CA / 32;
        for (int kt = 0; kt < KT; kt++) {
            STSA(As, pa); STSB(Bs, pb);
            __syncthreads();
            if (kt + 1 < KT) {
                int k0 = (kt + 1) * 32;
                LDGA(pa, A, CA, k0);
                LDGB(pb, Wout, CA, k0, col0);
            }
            frag_compute(As, Bs, acc1, wr, wc, g4, q4);
            __syncthreads();
        }
    }
    {
        LDGA(pa, s_, CS, 0);
        LDGB(pb, Wsg, CA, 0, col0);
        const int KT = CS / 32;
        for (int kt = 0; kt < KT; kt++) {
            STSA(As, pa); STSB(Bs, pb);
            __syncthreads();
            if (kt + 1 < KT) {
                int k0 = (kt + 1) * 32;
                LDGA(pa, s_, CS, k0);
                LDGB(pb, Wsg, CA, k0, col0);
            }
            frag_compute(As, Bs, acc2, wr, wc, g4, q4);
            __syncthreads();
        }
    }

    #pragma unroll
    for (int mt = 0; mt < 2; mt++)
        #pragma unroll
        for (int nt = 0; nt < 4; nt++)
            #pragma unroll
            for (int t = 0; t < 4; t++) {
                int n = col0 + wc + nt * 8 + 2 * q4 + (t & 1);
                acc1[mt][nt][t] *= sigmoidf_(acc2[mt][nt][t] + __ldg(&bsg[n]));
            }

    float* st = sm;
    stage_acc(st, acc1, wr, wc, g4, q4);
    __syncthreads();
    #pragma unroll
    for (int rep = 0; rep < 32; rep++) {
        int idx = rep * 256 + tid;
        int r = idx >> 6, c = idx & 63;
        out[(long)(row0 + r) * CA + col0 + c] = st[r * SPITCH + c];
    }
}

// ---------------- pair bias v6: bf16 m16n8k16 MMA (R10 version) --------------
#define WP 68
#define PB_Z_WORDS (64 * WP)                         // 4352
#define PB_WB_OFF  PB_Z_WORDS
#define PB_SMEM ((PB_Z_WORDS + 16 * WP) * 4)         // 21760 B
__global__ void __launch_bounds__(256)
pairbias6_kernel(const float* __restrict__ z, const float* __restrict__ beta,
                 const float* __restrict__ Wb, const float* __restrict__ gz,
                 const float* __restrict__ bz) {
    extern __shared__ float smf[];
    uint32_t* Z16  = (uint32_t*)smf;           // [64][WP] bf16x2
    uint32_t* Wb16 = Z16 + PB_WB_OFF;          // [16][WP] bf16x2
    float*    res  = smf;                      // aliased over Z16 after MMA
    __shared__ float gzs[CZ], bzs[CZ];

    int tid = threadIdx.x, wid = tid >> 5, lane = tid & 31;
    int g4 = lane >> 2, q4 = lane & 3;
    int b = blockIdx.z, p = blockIdx.y, q0 = blockIdx.x * 64;

    const float* zb = z + ((long)(b * SS + p) * SS + q0) * CZ;
    const float* betab = beta + ((long)(b * SS + p) * SS + q0) * HH;

    float betar[4];
    #pragma unroll
    for (int rep = 0; rep < 4; rep++)
        betar[rep] = betab[rep * 256 + tid];

    for (int idx = tid; idx < (CZ / 2) * HH; idx += 256) {
        int j = idx >> 4, h = idx & 15;
        Wb16[h * WP + j] = pack_bf16x2(Wb[(2 * j) * HH + h], Wb[(2 * j + 1) * HH + h]);
    }
    for (int idx = tid; idx < CZ; idx += 256) { gzs[idx] = gz[idx]; bzs[idx] = bz[idx]; }
    __syncthreads();

    {
        float4 vr[8];
        #pragma unroll
        for (int rr = 0; rr < 8; rr++) {
            int pl = wid * 8 + rr;
            vr[rr] = *(const float4*)&zb[(long)pl * CZ + lane * 4];
        }
        float sums[8], sqs[8];
        #pragma unroll
        for (int rr = 0; rr < 8; rr++) {
            float4 v = vr[rr];
            sums[rr] = v.x + v.y + v.z + v.w;
            sqs[rr]  = v.x * v.x + v.y * v.y + v.z * v.z + v.w * v.w;
        }
        #pragma unroll
        for (int o = 16; o; o >>= 1) {
            #pragma unroll
            for (int rr = 0; rr < 8; rr++) {
                sums[rr] += __shfl_xor_sync(0xffffffffu, sums[rr], o);
                sqs[rr]  += __shfl_xor_sync(0xffffffffu, sqs[rr],  o);
            }
        }
        #pragma unroll
        for (int rr = 0; rr < 8; rr++) {
            int pl = wid * 8 + rr;
            float mean = sums[rr] * (1.0f / CZ);
            float var  = sqs[rr] * (1.0f / CZ) - mean * mean;
            float rstd = rsqrtf(var + EPS);
            float4 v = vr[rr];
            int c = lane * 4;
            float z0 = (v.x - mean) * rstd * gzs[c + 0] + bzs[c + 0];
            float z1 = (v.y - mean) * rstd * gzs[c + 1] + bzs[c + 1];
            float z2 = (v.z - mean) * rstd * gzs[c + 2] + bzs[c + 2];
            float z3 = (v.w - mean) * rstd * gzs[c + 3] + bzs[c + 3];
            uint2 o2;
            o2.x = pack_bf16x2(z0, z1);
            o2.y = pack_bf16x2(z2, z3);
            *(uint2*)&Z16[pl * WP + lane * 2] = o2;
        }
    }
    __syncthreads();

    float acc[4];
    #pragma unroll
    for (int t = 0; t < 4; t++) acc[t] = 0.f;
    {
        int wr = (wid & 3) * 16;
        int hb = (wid >> 2) * 8;
        #pragma unroll
        for (int kc = 0; kc < 8; kc++) {
            int kb = kc * 8 + q4;
            uint32_t af[4];
            af[0] = Z16[(wr + g4) * WP + kb];
            af[1] = Z16[(wr + g4 + 8) * WP + kb];
            af[2] = Z16[(wr + g4) * WP + kb + 4];
            af[3] = Z16[(wr + g4 + 8) * WP + kb + 4];
            uint32_t bf[2];
            bf[0] = Wb16[(hb + g4) * WP + kb];
            bf[1] = Wb16[(hb + g4) * WP + kb + 4];
            mma_bf16(acc, af, bf);
        }
    }
    __syncthreads();

    {
        int wr = (wid & 3) * 16;
        int hb = (wid >> 2) * 8;
        #pragma unroll
        for (int t = 0; t < 4; t++) {
            int row = wr + g4 + ((t >= 2) ? 8 : 0);
            int h = hb + 2 * q4 + (t & 1);
            res[row * 17 + h] = acc[t];
        }
    }
    __syncthreads();

    #pragma unroll
    for (int rep = 0; rep < 4; rep++) {
        int idx = rep * 256 + tid;
        int ql = idx >> 4, hh = idx & 15;
        res[ql * 17 + hh] += betar[rep];
    }
    __syncthreads();

    #pragma unroll
    for (int rep = 0; rep < 4; rep++) {
        int idx = rep * 256 + tid;
        int h = idx >> 6, ql = idx & 63;
        g_bias[(((long)(b * HH + h) * SS) + p) * SS + q0 + ql] = res[ql * 17 + h];
    }
}

// ---------------- fused attention: pipelined K/V, direct-gmem bias -----------
#define QP 52
#define KP 52
#define VP 68
#define PP 68
#define AT_K (128 * QP)
#define AT_V (AT_K + 64 * KP)
#define AT_PB (AT_V + 48 * VP)
#define AT_WORDS (AT_PB + 128 * PP)
#define ATT_SMEM (AT_WORDS * 4)              // 87808 B

__global__ void __launch_bounds__(256, 2)
attn_kernel(const float* __restrict__ qg, const float* __restrict__ kg,
            const float* __restrict__ vg, const float* __restrict__ biasg,
            const float* __restrict__ gateg, float* __restrict__ outg) {
    extern __shared__ char smem[];
    uint32_t* Qs = (uint32_t*)smem;
    uint32_t* Ks = Qs + AT_K;
    uint32_t* Vs = Qs + AT_V;
    uint32_t* Ps = Qs + AT_PB;

    int tid = threadIdx.x, wid = tid >> 5, lane = tid & 31;
    int g4 = lane >> 2, q4 = lane & 3;
    int bh = blockIdx.y;
    int b = bh >> 4, h = bh & 15;
    int i0 = blockIdx.x * 128;
    const float* qb = qg + ((long)bh * SS + i0) * HD;
    const float* kb_ = kg + (long)bh * SS * HD;
    const float* vb = vg + (long)bh * SS * HD;
    const float* biasb = biasg + (long)bh * SS * SS;   // [j][i]

    #pragma unroll
    for (int rep = 0; rep < 6; rep++) {
        int idx = rep * 256 + tid;
        int r = idx / 12, c4 = (idx % 12) * 4;
        float4 v = *(const float4*)&qb[(long)r * HD + c4];
        uint32_t* d = &Qs[r * QP + c4];
        d[0] = f2tf32(v.x); d[1] = f2tf32(v.y); d[2] = f2tf32(v.z); d[3] = f2tf32(v.w);
    }

    int wr = wid * 16;
    float accO[6][4];
    #pragma unroll
    for (int n = 0; n < 6; n++)
        #pragma unroll
        for (int t = 0; t < 4; t++) accO[n][t] = 0.f;
    float mrow[2] = {-1e30f, -1e30f};
    float lrow[2] = {0.f, 0.f};

    // register prefetch buffers for K (3 x float4) and V (12 floats)
    float4 pk[3]; float pv[12];
    #pragma unroll
    for (int rep = 0; rep < 3; rep++) {
        int idx = rep * 256 + tid;
        int r = idx / 12, c4 = (idx % 12) * 4;
        pk[rep] = *(const float4*)&kb_[(long)r * HD + c4];
    }
    #pragma unroll
    for (int rep = 0; rep < 12; rep++) {
        int idx = rep * 256 + tid;
        int r = idx / 48, d = idx % 48;
        pv[rep] = vb[(long)r * HD + d];
    }

    for (int j = 0; j < 12; j++) {
        __syncthreads();
        // stage prefetched K/V into smem
        #pragma unroll
        for (int rep = 0; rep < 3; rep++) {
            int idx = rep * 256 + tid;
            int r = idx / 12, c4 = (idx % 12) * 4;
            uint32_t* d = &Ks[r * KP + c4];
            d[0] = f2tf32(pk[rep].x); d[1] = f2tf32(pk[rep].y);
            d[2] = f2tf32(pk[rep].z); d[3] = f2tf32(pk[rep].w);
        }
        #pragma unroll
        for (int rep = 0; rep < 12; rep++) {
            int idx = rep * 256 + tid;
            int r = idx / 48, d = idx % 48;
            Vs[d * VP + r] = f2tf32(pv[rep]);
        }
        __syncthreads();
        // prefetch next tile (overlaps with QK compute below)
        if (j + 1 < 12) {
            #pragma unroll
            for (int rep = 0; rep < 3; rep++) {
                int idx = rep * 256 + tid;
                int r = idx / 12, c4 = (idx % 12) * 4;
                pk[rep] = *(const float4*)&kb_[(long)((j + 1) * 64 + r) * HD + c4];
            }
            #pragma unroll
            for (int rep = 0; rep < 12; rep++) {
                int idx = rep * 256 + tid;
                int r = idx / 48, d = idx % 48;
                pv[rep] = vb[(long)((j + 1) * 64 + r) * HD + d];
            }
        }

        float S[8][4];
        #pragma unroll
        for (int nt = 0; nt < 8; nt++)
            #pragma unroll
            for (int t = 0; t < 4; t++) S[nt][t] = 0.f;
        #pragma unroll
        for (int kc = 0; kc < 6; kc++) {
            int kbx = kc * 8 + q4;
            uint32_t af[4];
            af[0] = Qs[(wr + g4) * QP + kbx];
            af[1] = Qs[(wr + g4 + 8) * QP + kbx];
            af[2] = Qs[(wr + g4) * QP + kbx + 4];
            af[3] = Qs[(wr + g4 + 8) * QP + kbx + 4];
            #pragma unroll
            for (int nt = 0; nt < 8; nt++) {
                uint32_t bf2[2];
                bf2[0] = Ks[(nt * 8 + g4) * KP + kbx];
                bf2[1] = Ks[(nt * 8 + g4) * KP + kbx + 4];
                mma_tf32(S[nt], af, bf2);
            }
        }
        // bias read directly from gmem (L2-resident), at fragment coordinates
        const float* bj = biasb + (long)(j * 64) * SS + i0;
        int r0 = wr + g4, r1 = r0 + 8;
        float mn0 = mrow[0], mn1 = mrow[1];
        #pragma unroll
        for (int nt = 0; nt < 8; nt++) {
            #pragma unroll
            for (int t = 0; t < 4; t++) {
                int rr = (t >= 2) ? r1 : r0;
                int cc = nt * 8 + 2 * q4 + (t & 1);
                float val = S[nt][t] * SCALE + __ldg(&bj[(long)cc * SS + rr]);
                S[nt][t] = val;
                if (t < 2) mn0 = fmaxf(mn0, val); else mn1 = fmaxf(mn1, val);
            }
        }
        mn0 = fmaxf(mn0, __shfl_xor_sync(0xffffffffu, mn0, 1));
        mn0 = fmaxf(mn0, __shfl_xor_sync(0xffffffffu, mn0, 2));
        mn1 = fmaxf(mn1, __shfl_xor_sync(0xffffffffu, mn1, 1));
        mn1 = fmaxf(mn1, __shfl_xor_sync(0xffffffffu, mn1, 2));
        float al0 = __expf(mrow[0] - mn0);
        float al1 = __expf(mrow[1] - mn1);
        mrow[0] = mn0; mrow[1] = mn1;
        float s0 = 0.f, s1 = 0.f;
        #pragma unroll
        for (int nt = 0; nt < 8; nt++) {
            #pragma unroll
            for (int t = 0; t < 4; t++) {
                float p = __expf(S[nt][t] - ((t >= 2) ? mn1 : mn0));
                S[nt][t] = p;
                if (t < 2) s0 += p; else s1 += p;
                int rr = (t >= 2) ? r1 : r0;
                int cc = nt * 8 + 2 * q4 + (t & 1);
                Ps[rr * PP + cc] = f2tf32(p);
            }
        }
        s0 += __shfl_xor_sync(0xffffffffu, s0, 1);
        s0 += __shfl_xor_sync(0xffffffffu, s0, 2);
        s1 += __shfl_xor_sync(0xffffffffu, s1, 1);
        s1 += __shfl_xor_sync(0xffffffffu, s1, 2);
        lrow[0] = lrow[0] * al0 + s0;
        lrow[1] = lrow[1] * al1 + s1;
        #pragma unroll
        for (int n = 0; n < 6; n++) {
            accO[n][0] *= al0; accO[n][1] *= al0;
            accO[n][2] *= al1; accO[n][3] *= al1;
        }
        __syncwarp();
        #pragma unroll
        for (int kc = 0; kc < 8; kc++) {
            int kbx = kc * 8 + q4;
            uint32_t af[4];
            af[0] = Ps[(wr + g4) * PP + kbx];
            af[1] = Ps[(wr + g4 + 8) * PP + kbx];
            af[2] = Ps[(wr + g4) * PP + kbx + 4];
            af[3] = Ps[(wr + g4 + 8) * PP + kbx + 4];
            #pragma unroll
            for (int n = 0; n < 6; n++) {
                uint32_t bf2[2];
                bf2[0] = Vs[(n * 8 + g4) * VP + kbx];
                bf2[1] = Vs[(n * 8 + g4) * VP + kbx + 4];
                mma_tf32(accO[n], af, bf2);
            }
        }
    }

    float inv0 = 1.0f / lrow[0], inv1 = 1.0f / lrow[1];
    #pragma unroll
    for (int n = 0; n < 6; n++) {
        #pragma unroll
        for (int t = 0; t < 4; t++) {
            int r = wr + g4 + ((t >= 2) ? 8 : 0);
            int c = n * 8 + 2 * q4 + (t & 1);
            long gi = ((long)(b * SS + i0 + r)) * CA + h * HD + c;
            float o = accO[n][t] * ((t >= 2) ? inv1 : inv0);
            outg[gi] = o * sigmoidf_(gateg[gi]);
        }
    }
}

// ---------------- host side --------------------------------------------------
static float* sym(const void* symbol) {
    void* p = nullptr;
    cudaGetSymbolAddress(&p, symbol);
    return (float*)p;
}

extern "C" void kernel_launch(void* const* d_in, const int* in_sizes, int n_in,
                              void* d_out, int out_size) {
    const float* a        = (const float*)d_in[0];
    const float* s        = (const float*)d_in[1];
    const float* z        = (const float*)d_in[2];
    const float* beta     = (const float*)d_in[3];
    const float* gamma_s  = (const float*)d_in[4];
    const float* W_ada_g  = (const float*)d_in[5];
    const float* b_ada_g  = (const float*)d_in[6];
    const float* W_ada_o  = (const float*)d_in[7];
    const float* Wq       = (const float*)d_in[8];
    const float* bq       = (const float*)d_in[9];
    const float* Wk       = (const float*)d_in[10];
    const float* Wv       = (const float*)d_in[11];
    const float* Wb       = (const float*)d_in[12];
    const float* gz       = (const float*)d_in[13];
    const float* bz       = (const float*)d_in[14];
    const float* Wg       = (const float*)d_in[15];
    const float* Wout     = (const float*)d_in[16];
    const float* Ws_gate  = (const float*)d_in[17];
    const float* bs_gate  = (const float*)d_in[18];
    float* out = (float*)d_out;

    float* p_q    = sym(g_q);
    float* p_k    = sym(g_k);
    float* p_v    = sym(g_v);
    float* p_gate = sym(g_gate);
    float* p_bias = sym(g_bias);
    float* p_go   = sym(g_go);

    cudaFuncSetAttribute(gemm_ada,        cudaFuncAttributeMaxDynamicSharedMemorySize, ADA_SMEM);
    cudaFuncSetAttribute(gemm_proj4,      cudaFuncAttributeMaxDynamicSharedMemorySize, PROJ_SMEM);
    cudaFuncSetAttribute(gemm_final,      cudaFuncAttributeMaxDynamicSharedMemorySize, PROJ_SMEM);
    cudaFuncSetAttribute(pairbias6_kernel,cudaFuncAttributeMaxDynamicSharedMemorySize, PB_SMEM);
    cudaFuncSetAttribute(attn_kernel,     cudaFuncAttributeMaxDynamicSharedMemorySize, ATT_SMEM);

    // 1. layer norms
    ln_kernel<<<MM, 256>>>(s, a, gamma_s);
    // 2. adaLN (fused dual GEMM)
    gemm_ada<<<dim3(CA / 64, MM / 128), 256, ADA_SMEM>>>(W_ada_g, W_ada_o, b_ada_g);
    // 3. 4-way projections (2 CTAs/SM)
    gemm_proj4<<<dim3(4 * CA / 64, MM / 128), 256, PROJ_SMEM>>>(Wq, Wk, Wv, Wg, bq);
    // 4. pair bias (bf16 MMA, v6)
    pairbias6_kernel<<<dim3(SS / 64, SS, BB), 256, PB_SMEM>>>(z, beta, Wb, gz, bz);
    // 5. fused attention (pipelined K/V, direct-gmem bias)
    attn_kernel<<<dim3(SS / 128, BB * HH), 256, ATT_SMEM>>>(p_q, p_k, p_v, p_bias, p_gate, p_go);
    // 6. fused output GEMM + s-gate
    gemm_final<<<dim3(CA / 64, MM / 128), 256, PROJ_SMEM>>>(Wout, s, Ws_gate, bs_gate, out);
}

// round 13
// speedup vs baseline: 3.5549x; 1.0005x over previous
#include <cuda_runtime.h>
#include <cuda_bf16.h>
#include <math.h>
#include <cstdint>

// Problem constants
#define BB   2
#define SS   768
#define CA   768
#define CS   384
#define CZ   128
#define HH   16
#define HD   48
#define MM   (BB*SS)          // 1536
#define EPS  1e-5f
#define SCALE (0.14433756729740643f)  // 1/sqrt(48)

// ---------------- scratch (device globals) ----------------------------------
__device__ float g_sn   [MM*CS];
__device__ float g_lna  [MM*CA];
__device__ float g_an   [MM*CA];
__device__ float g_q    [BB*HH*SS*HD];      // [b,h,s,d]
__device__ float g_k    [BB*HH*SS*HD];      // [b,h,s,d]
__device__ float g_v    [BB*HH*SS*HD];      // [b,h,s,d]
__device__ float g_gate [MM*CA];
__device__ float g_bias [BB*HH*SS*SS];      // pair bias, layout [b,h,j,i] (i contiguous)
__device__ float g_go   [MM*CA];

// ---------------- helpers ----------------------------------------------------
__device__ __forceinline__ float sigmoidf_(float x) { return 1.0f / (1.0f + expf(-x)); }

__device__ __forceinline__ uint32_t f2tf32(float f) {
    uint32_t r;
    asm("cvt.rna.tf32.f32 %0, %1;" : "=r"(r) : "f"(f));
    return r;
}
__device__ __forceinline__ uint32_t pack_bf16x2(float lo, float hi) {
    uint32_t r;
    asm("cvt.rn.bf16x2.f32 %0, %1, %2;" : "=r"(r) : "f"(hi), "f"(lo));
    return r;
}
__device__ __forceinline__ uint32_t smem_u32(const void* p) {
    uint32_t a;
    asm("{ .reg .u64 t; cvta.to.shared.u64 t, %1; cvt.u32.u64 %0, t; }"
        : "=r"(a) : "l"(p));
    return a;
}

#define CP16(dst, src) asm volatile("cp.async.ca.shared.global [%0], [%1], 16;" :: "r"(dst), "l"(src))
#define CP4(dst, src)  asm volatile("cp.async.ca.shared.global [%0], [%1], 4;"  :: "r"(dst), "l"(src))
#define CP_COMMIT()    asm volatile("cp.async.commit_group;" ::: "memory")
#define CP_WAIT1()     asm volatile("cp.async.wait_group 1;" ::: "memory")
#define CP_WAIT0()     asm volatile("cp.async.wait_group 0;" ::: "memory")

__device__ __forceinline__ void mma_tf32(float* d, const uint32_t* a, const uint32_t* b) {
    asm volatile("mma.sync.aligned.m16n8k8.row.col.f32.tf32.tf32.f32 "
        "{%0,%1,%2,%3}, {%4,%5,%6,%7}, {%8,%9}, {%0,%1,%2,%3};"
        : "+f"(d[0]), "+f"(d[1]), "+f"(d[2]), "+f"(d[3])
        : "r"(a[0]), "r"(a[1]), "r"(a[2]), "r"(a[3]), "r"(b[0]), "r"(b[1]));
}
__device__ __forceinline__ void mma_bf16(float* d, const uint32_t* a, const uint32_t* b) {
    asm volatile("mma.sync.aligned.m16n8k16.row.col.f32.bf16.bf16.f32 "
        "{%0,%1,%2,%3}, {%4,%5,%6,%7}, {%8,%9}, {%0,%1,%2,%3};"
        : "+f"(d[0]), "+f"(d[1]), "+f"(d[2]), "+f"(d[3])
        : "r"(a[0]), "r"(a[1]), "r"(a[2]), "r"(a[3]), "r"(b[0]), "r"(b[1]));
}

__device__ float2 blockReduceSum2(float a, float b) {
    __shared__ float sa[32], sb[32];
    int lane = threadIdx.x & 31, wid = threadIdx.x >> 5;
    #pragma unroll
    for (int o = 16; o; o >>= 1) {
        a += __shfl_xor_sync(0xffffffffu, a, o);
        b += __shfl_xor_sync(0xffffffffu, b, o);
    }
    if (lane == 0) { sa[wid] = a; sb[wid] = b; }
    __syncthreads();
    if (wid == 0) {
        int nw = (blockDim.x + 31) >> 5;
        a = (lane < nw) ? sa[lane] : 0.0f;
        b = (lane < nw) ? sb[lane] : 0.0f;
        #pragma unroll
        for (int o = 16; o; o >>= 1) {
            a += __shfl_xor_sync(0xffffffffu, a, o);
            b += __shfl_xor_sync(0xffffffffu, b, o);
        }
        if (lane == 0) { sa[0] = a; sb[0] = b; }
    }
    __syncthreads();
    float2 r = make_float2(sa[0], sb[0]);
    __syncthreads();
    return r;
}

// ---------------- LN kernel --------------------------------------------------
__global__ void ln_kernel(const float* __restrict__ s, const float* __restrict__ a,
                          const float* __restrict__ gamma_s) {
    int r = blockIdx.x;
    int tid = threadIdx.x;
    const float* srow = s + (long)r * CS;
    float sum = 0.f, sq = 0.f;
    for (int c = tid; c < CS; c += blockDim.x) { float v = srow[c]; sum += v; sq += v * v; }
    float2 t = blockReduceSum2(sum, sq);
    float mean = t.x / CS, var = t.y / CS - mean * mean;
    float rstd = rsqrtf(var + EPS);
    for (int c = tid; c < CS; c += blockDim.x)
        g_sn[(long)r * CS + c] = (srow[c] - mean) * rstd * gamma_s[c];

    const float* arow = a + (long)r * CA;
    sum = 0.f; sq = 0.f;
    for (int c = tid; c < CA; c += blockDim.x) { float v = arow[c]; sum += v; sq += v * v; }
    t = blockReduceSum2(sum, sq);
    mean = t.x / CA; var = t.y / CA - mean * mean;
    rstd = rsqrtf(var + EPS);
    for (int c = tid; c < CA; c += blockDim.x)
        g_lna[(long)r * CA + c] = (arow[c] - mean) * rstd;
}

// ---------------- common GEMM machinery (128x64 tile, BK=32, cp.async) ------
#define APITCH 36
#define BPITCH 36
#define A_WORDS (128 * APITCH)               // 4608
#define B_WORDS (64 * BPITCH)                // 2304
#define SPITCH 68
#define STAGE_WORDS (128 * SPITCH)           // 8704

// fragments loaded as fp32 from smem, converted to tf32 in regs (same cvt.rna
// as the old STS-path conversion -> numerically identical).
__device__ __forceinline__ void frag_compute_cvt(const float* As, const float* Bs,
        float (&acc)[2][4][4], int wr, int wc, int g4, int q4) {
    #pragma unroll
    for (int kc = 0; kc < 4; kc++) {
        int kb = kc * 8 + q4;
        uint32_t af[2][4];
        #pragma unroll
        for (int mt = 0; mt < 2; mt++) {
            int r = wr + mt * 16 + g4;
            af[mt][0] = f2tf32(As[r * APITCH + kb]);
            af[mt][1] = f2tf32(As[(r + 8) * APITCH + kb]);
            af[mt][2] = f2tf32(As[r * APITCH + kb + 4]);
            af[mt][3] = f2tf32(As[(r + 8) * APITCH + kb + 4]);
        }
        #pragma unroll
        for (int nt = 0; nt < 4; nt++) {
            int c = wc + nt * 8 + g4;
            uint32_t bf[2] = {f2tf32(Bs[c * BPITCH + kb]), f2tf32(Bs[c * BPITCH + kb + 4])};
            #pragma unroll
            for (int mt = 0; mt < 2; mt++)
                mma_tf32(acc[mt][nt], af[mt], bf);
        }
    }
}

__device__ __forceinline__ void frag_compute2_cvt(const float* As, const float* Bs1,
        const float* Bs2, float (&acc1)[2][4][4], float (&acc2)[2][4][4],
        int wr, int wc, int g4, int q4) {
    #pragma unroll
    for (int kc = 0; kc < 4; kc++) {
        int kb = kc * 8 + q4;
        uint32_t af[2][4];
        #pragma unroll
        for (int mt = 0; mt < 2; mt++) {
            int r = wr + mt * 16 + g4;
            af[mt][0] = f2tf32(As[r * APITCH + kb]);
            af[mt][1] = f2tf32(As[(r + 8) * APITCH + kb]);
            af[mt][2] = f2tf32(As[r * APITCH + kb + 4]);
            af[mt][3] = f2tf32(As[(r + 8) * APITCH + kb + 4]);
        }
        #pragma unroll
        for (int nt = 0; nt < 4; nt++) {
            int c = wc + nt * 8 + g4;
            uint32_t b1[2] = {f2tf32(Bs1[c * BPITCH + kb]), f2tf32(Bs1[c * BPITCH + kb + 4])};
            uint32_t b2[2] = {f2tf32(Bs2[c * BPITCH + kb]), f2tf32(Bs2[c * BPITCH + kb + 4])};
            #pragma unroll
            for (int mt = 0; mt < 2; mt++) {
                mma_tf32(acc1[mt][nt], af[mt], b1);
                mma_tf32(acc2[mt][nt], af[mt], b2);
            }
        }
    }
}

__device__ __forceinline__ void stage_acc(float* st, const float (&acc)[2][4][4],
        int wr, int wc, int g4, int q4) {
    #pragma unroll
    for (int mt = 0; mt < 2; mt++) {
        #pragma unroll
        for (int nt = 0; nt < 4; nt++) {
            int rr = wr + mt * 16 + g4;
            int cc = wc + nt * 8 + 2 * q4;
            st[rr * SPITCH + cc]           = acc[mt][nt][0];
            st[rr * SPITCH + cc + 1]       = acc[mt][nt][1];
            st[(rr + 8) * SPITCH + cc]     = acc[mt][nt][2];
            st[(rr + 8) * SPITCH + cc + 1] = acc[mt][nt][3];
        }
    }
}

#define ZERO_ACC(acc) { \
    _Pragma("unroll") for (int i = 0; i < 2; i++) \
    _Pragma("unroll") for (int j = 0; j < 4; j++) \
    _Pragma("unroll") for (int t = 0; t < 4; t++) acc[i][j][t] = 0.f; }

// cp.async tile issue: A 128x32 fp32 (16B copies), B 32x64 transpose (4B copies)
#define ISSUEA(Abase, lda, k0, bofs) { \
    _Pragma("unroll") for (int rep = 0; rep < 4; rep++) { \
        int lin = rep * 256 + tid; int r = lin >> 3, c4 = (lin & 7) * 4; \
        CP16(su + ((bofs) + r * APITCH + c4) * 4, \
             &(Abase)[(long)(row0 + r) * (lda) + (k0) + c4]); } }
#define ISSUEB(Bbase, ldb, k0, c0, bofs) { \
    _Pragma("unroll") for (int rep = 0; rep < 8; rep++) { \
        int lin = rep * 256 + tid; int kk = lin >> 6, n = lin & 63; \
        CP4(su + ((bofs) + n * BPITCH + kk) * 4, \
            &(Bbase)[(long)((k0) + kk) * (ldb) + (c0) + n]); } }

// ---------------- adaLN fused dual GEMM (cp.async double-buffered) -----------
#define ADA_STRIDE (A_WORDS + 2 * B_WORDS)            // 9216 words
#define ADA_SMEM (2 * ADA_STRIDE * 4)                 // 73728 B (stage aliases)
__global__ void __launch_bounds__(256, 2)
gemm_ada(const float* __restrict__ Wg_, const float* __restrict__ Wo_,
         const float* __restrict__ badag) {
    extern __shared__ float sm[];
    uint32_t su = smem_u32(sm);

    int tid = threadIdx.x, wid = tid >> 5;
    int g4 = (tid & 31) >> 2, q4 = tid & 3;
    int wr = (wid & 3) * 32, wc = (wid >> 2) * 32;
    int row0 = blockIdx.y * 128, col0 = blockIdx.x * 64;
    const float* A = g_sn;

    float acc1[2][4][4], acc2[2][4][4];
    ZERO_ACC(acc1); ZERO_ACC(acc2);

    ISSUEA(A, CS, 0, 0);
    ISSUEB(Wg_, CA, 0, col0, A_WORDS);
    ISSUEB(Wo_, CA, 0, col0, A_WORDS + B_WORDS);
    CP_COMMIT();
    const int KT = CS / 32;
    for (int kt = 0; kt < KT; kt++) {
        int cur = (kt & 1) * ADA_STRIDE;
        if (kt + 1 < KT) {
            int nxt = ((kt + 1) & 1) * ADA_STRIDE;
            int k0 = (kt + 1) * 32;
            ISSUEA(A, CS, k0, nxt);
            ISSUEB(Wg_, CA, k0, col0, nxt + A_WORDS);
            ISSUEB(Wo_, CA, k0, col0, nxt + A_WORDS + B_WORDS);
            CP_COMMIT();
            CP_WAIT1();
        } else { CP_WAIT0(); }
        __syncthreads();
        frag_compute2_cvt(sm + cur, sm + cur + A_WORDS, sm + cur + A_WORDS + B_WORDS,
                          acc1, acc2, wr, wc, g4, q4);
        __syncthreads();
    }

    float* st1 = sm;
    float* st2 = sm + STAGE_WORDS;
    stage_acc(st1, acc1, wr, wc, g4, q4);
    stage_acc(st2, acc2, wr, wc, g4, q4);
    __syncthreads();
    #pragma unroll
    for (int rep = 0; rep < 32; rep++) {
        int idx = rep * 256 + tid;
        int r = idx >> 6, c = idx & 63;
        int m = row0 + r, n = col0 + c;
        float v1 = st1[r * SPITCH + c], v2 = st2[r * SPITCH + c];
        g_an[(long)m * CA + n] = sigmoidf_(v1 + badag[n]) * g_lna[(long)m * CA + n] + v2;
    }
}

// ---------------- fused 4-way projection GEMM (cp.async double-buffered) -----
#define GM_STRIDE (A_WORDS + B_WORDS)                 // 6912 words
#define PROJ_SMEM (2 * GM_STRIDE * 4)                 // 55296 B (stage aliases)
__global__ void __launch_bounds__(256, 3)
gemm_proj4(const float* __restrict__ Wq, const float* __restrict__ Wk,
           const float* __restrict__ Wv, const float* __restrict__ Wg_,
           const float* __restrict__ bq) {
    extern __shared__ float sm[];
    uint32_t su = smem_u32(sm);

    int tid = threadIdx.x, wid = tid >> 5;
    int g4 = (tid & 31) >> 2, q4 = tid & 3;
    int wr = (wid & 3) * 32, wc = (wid >> 2) * 32;
    int row0 = blockIdx.y * 128;
    int cg = blockIdx.x * 64;
    int w = cg / CA, coln = cg % CA;
    const float* B = (w == 0) ? Wq : (w == 1) ? Wk : (w == 2) ? Wv : Wg_;
    const float* A = g_an;

    float acc[2][4][4];
    ZERO_ACC(acc);

    ISSUEA(A, CA, 0, 0);
    ISSUEB(B, CA, 0, coln, A_WORDS);
    CP_COMMIT();
    const int KT = CA / 32;
    for (int kt = 0; kt < KT; kt++) {
        int cur = (kt & 1) * GM_STRIDE;
        if (kt + 1 < KT) {
            int nxt = ((kt + 1) & 1) * GM_STRIDE;
            int k0 = (kt + 1) * 32;
            ISSUEA(A, CA, k0, nxt);
            ISSUEB(B, CA, k0, coln, nxt + A_WORDS);
            CP_COMMIT();
            CP_WAIT1();
        } else { CP_WAIT0(); }
        __syncthreads();
        frag_compute_cvt(sm + cur, sm + cur + A_WORDS, acc, wr, wc, g4, q4);
        __syncthreads();
    }

    float* st = sm;
    stage_acc(st, acc, wr, wc, g4, q4);
    __syncthreads();
    float* dst = (w == 0) ? g_q : (w == 1) ? g_k : g_v;
    #pragma unroll
    for (int rep = 0; rep < 32; rep++) {
        int idx = rep * 256 + tid;
        int r = idx >> 6, c = idx & 63;
        int m = row0 + r, n = coln + c;
        float v = st[r * SPITCH + c];
        if (w == 3) {
            g_gate[(long)m * CA + n] = v;
        } else {
            if (w == 0) v += bq[n];
            int b = m / SS, si = m % SS, h = n / HD, d = n % HD;
            dst[(((long)(b * HH + h) * SS) + si) * HD + d] = v;
        }
    }
}

// ---------------- fused output GEMM (cp.async double-buffered) ---------------
__global__ void __launch_bounds__(256, 2)
gemm_final(const float* __restrict__ Wout, const float* __restrict__ s_,
           const float* __restrict__ Wsg, const float* __restrict__ bsg,
           float* __restrict__ out) {
    extern __shared__ float sm[];
    uint32_t su = smem_u32(sm);

    int tid = threadIdx.x, wid = tid >> 5;
    int g4 = (tid & 31) >> 2, q4 = tid & 3;
    int wr = (wid & 3) * 32, wc = (wid >> 2) * 32;
    int row0 = blockIdx.y * 128, col0 = blockIdx.x * 64;

    float acc1[2][4][4], acc2[2][4][4];
    ZERO_ACC(acc1); ZERO_ACC(acc2);

    // loop 1: go @ Wout, K = 768
    {
        const float* A = g_go;
        ISSUEA(A, CA, 0, 0);
        ISSUEB(Wout, CA, 0, col0, A_WORDS);
        CP_COMMIT();
        const int KT = CA / 32;
        for (int kt = 0; kt < KT; kt++) {
            int cur = (kt & 1) * GM_STRIDE;
            if (kt + 1 < KT) {
                int nxt = ((kt + 1) & 1) * GM_STRIDE;
                int k0 = (kt + 1) * 32;
                ISSUEA(A, CA, k0, nxt);
                ISSUEB(Wout, CA, k0, col0, nxt + A_WORDS);
                CP_COMMIT();
                CP_WAIT1();
            } else { CP_WAIT0(); }
            __syncthreads();
            frag_compute_cvt(sm + cur, sm + cur + A_WORDS, acc1, wr, wc, g4, q4);
            __syncthreads();
        }
    }
    // loop 2: s @ Ws_gate, K = 384
    {
        ISSUEA(s_, CS, 0, 0);
        ISSUEB(Wsg, CA, 0, col0, A_WORDS);
        CP_COMMIT();
        const int KT = CS / 32;
        for (int kt = 0; kt < KT; kt++) {
            int cur = (kt & 1) * GM_STRIDE;
            if (kt + 1 < KT) {
                int nxt = ((kt + 1) & 1) * GM_STRIDE;
                int k0 = (kt + 1) * 32;
                ISSUEA(s_, CS, k0, nxt);
                ISSUEB(Wsg, CA, k0, col0, nxt + A_WORDS);
                CP_COMMIT();
                CP_WAIT1();
            } else { CP_WAIT0(); }
            __syncthreads();
            frag_compute_cvt(sm + cur, sm + cur + A_WORDS, acc2, wr, wc, g4, q4);
            __syncthreads();
        }
    }

    #pragma unroll
    for (int mt = 0; mt < 2; mt++)
        #pragma unroll
        for (int nt = 0; nt < 4; nt++)
            #pragma unroll
            for (int t = 0; t < 4; t++) {
                int n = col0 + wc + nt * 8 + 2 * q4 + (t & 1);
                acc1[mt][nt][t] *= sigmoidf_(acc2[mt][nt][t] + __ldg(&bsg[n]));
            }

    float* st = sm;
    stage_acc(st, acc1, wr, wc, g4, q4);
    __syncthreads();
    #pragma unroll
    for (int rep = 0; rep < 32; rep++) {
        int idx = rep * 256 + tid;
        int r = idx >> 6, c = idx & 63;
        out[(long)(row0 + r) * CA + col0 + c] = st[r * SPITCH + c];
    }
}

// ---------------- pair bias v6: bf16 m16n8k16 MMA (R10/R12 version) ----------
#define WP 68
#define PB_Z_WORDS (64 * WP)                         // 4352
#define PB_WB_OFF  PB_Z_WORDS
#define PB_SMEM ((PB_Z_WORDS + 16 * WP) * 4)         // 21760 B
__global__ void __launch_bounds__(256)
pairbias6_kernel(const float* __restrict__ z, const float* __restrict__ beta,
                 const float* __restrict__ Wb, const float* __restrict__ gz,
                 const float* __restrict__ bz) {
    extern __shared__ float smf[];
    uint32_t* Z16  = (uint32_t*)smf;           // [64][WP] bf16x2
    uint32_t* Wb16 = Z16 + PB_WB_OFF;          // [16][WP] bf16x2
    float*    res  = smf;                      // aliased over Z16 after MMA
    __shared__ float gzs[CZ], bzs[CZ];

    int tid = threadIdx.x, wid = tid >> 5, lane = tid & 31;
    int g4 = lane >> 2, q4 = lane & 3;
    int b = blockIdx.z, p = blockIdx.y, q0 = blockIdx.x * 64;

    const float* zb = z + ((long)(b * SS + p) * SS + q0) * CZ;
    const float* betab = beta + ((long)(b * SS + p) * SS + q0) * HH;

    float betar[4];
    #pragma unroll
    for (int rep = 0; rep < 4; rep++)
        betar[rep] = betab[rep * 256 + tid];

    for (int idx = tid; idx < (CZ / 2) * HH; idx += 256) {
        int j = idx >> 4, h = idx & 15;
        Wb16[h * WP + j] = pack_bf16x2(Wb[(2 * j) * HH + h], Wb[(2 * j + 1) * HH + h]);
    }
    for (int idx = tid; idx < CZ; idx += 256) { gzs[idx] = gz[idx]; bzs[idx] = bz[idx]; }
    __syncthreads();

    {
        float4 vr[8];
        #pragma unroll
        for (int rr = 0; rr < 8; rr++) {
            int pl = wid * 8 + rr;
            vr[rr] = *(const float4*)&zb[(long)pl * CZ + lane * 4];
        }
        float sums[8], sqs[8];
        #pragma unroll
        for (int rr = 0; rr < 8; rr++) {
            float4 v = vr[rr];
            sums[rr] = v.x + v.y + v.z + v.w;
            sqs[rr]  = v.x * v.x + v.y * v.y + v.z * v.z + v.w * v.w;
        }
        #pragma unroll
        for (int o = 16; o; o >>= 1) {
            #pragma unroll
            for (int rr = 0; rr < 8; rr++) {
                sums[rr] += __shfl_xor_sync(0xffffffffu, sums[rr], o);
                sqs[rr]  += __shfl_xor_sync(0xffffffffu, sqs[rr],  o);
            }
        }
        #pragma unroll
        for (int rr = 0; rr < 8; rr++) {
            int pl = wid * 8 + rr;
            float mean = sums[rr] * (1.0f / CZ);
            float var  = sqs[rr] * (1.0f / CZ) - mean * mean;
            float rstd = rsqrtf(var + EPS);
            float4 v = vr[rr];
            int c = lane * 4;
            float z0 = (v.x - mean) * rstd * gzs[c + 0] + bzs[c + 0];
            float z1 = (v.y - mean) * rstd * gzs[c + 1] + bzs[c + 1];
            float z2 = (v.z - mean) * rstd * gzs[c + 2] + bzs[c + 2];
            float z3 = (v.w - mean) * rstd * gzs[c + 3] + bzs[c + 3];
            uint2 o2;
            o2.x = pack_bf16x2(z0, z1);
            o2.y = pack_bf16x2(z2, z3);
            *(uint2*)&Z16[pl * WP + lane * 2] = o2;
        }
    }
    __syncthreads();

    float acc[4];
    #pragma unroll
    for (int t = 0; t < 4; t++) acc[t] = 0.f;
    {
        int wr = (wid & 3) * 16;
        int hb = (wid >> 2) * 8;
        #pragma unroll
        for (int kc = 0; kc < 8; kc++) {
            int kb = kc * 8 + q4;
            uint32_t af[4];
            af[0] = Z16[(wr + g4) * WP + kb];
            af[1] = Z16[(wr + g4 + 8) * WP + kb];
            af[2] = Z16[(wr + g4) * WP + kb + 4];
            af[3] = Z16[(wr + g4 + 8) * WP + kb + 4];
            uint32_t bf[2];
            bf[0] = Wb16[(hb + g4) * WP + kb];
            bf[1] = Wb16[(hb + g4) * WP + kb + 4];
            mma_bf16(acc, af, bf);
        }
    }
    __syncthreads();

    {
        int wr = (wid & 3) * 16;
        int hb = (wid >> 2) * 8;
        #pragma unroll
        for (int t = 0; t < 4; t++) {
            int row = wr + g4 + ((t >= 2) ? 8 : 0);
            int h = hb + 2 * q4 + (t & 1);
            res[row * 17 + h] = acc[t];
        }
    }
    __syncthreads();

    #pragma unroll
    for (int rep = 0; rep < 4; rep++) {
        int idx = rep * 256 + tid;
        int ql = idx >> 4, hh = idx & 15;
        res[ql * 17 + hh] += betar[rep];
    }
    __syncthreads();

    #pragma unroll
    for (int rep = 0; rep < 4; rep++) {
        int idx = rep * 256 + tid;
        int h = idx >> 6, ql = idx & 63;
        g_bias[(((long)(b * HH + h) * SS) + p) * SS + q0 + ql] = res[ql * 17 + h];
    }
}

// ---------------- fused attention: pipelined K/V, direct-gmem bias -----------
#define QP 52
#define KP 52
#define VP 68
#define PP 68
#define AT_K (128 * QP)
#define AT_V (AT_K + 64 * KP)
#define AT_PB (AT_V + 48 * VP)
#define AT_WORDS (AT_PB + 128 * PP)
#define ATT_SMEM (AT_WORDS * 4)              // 87808 B

__global__ void __launch_bounds__(256, 2)
attn_kernel(const float* __restrict__ qg, const float* __restrict__ kg,
            const float* __restrict__ vg, const float* __restrict__ biasg,
            const float* __restrict__ gateg, float* __restrict__ outg) {
    extern __shared__ char smem[];
    uint32_t* Qs = (uint32_t*)smem;
    uint32_t* Ks = Qs + AT_K;
    uint32_t* Vs = Qs + AT_V;
    uint32_t* Ps = Qs + AT_PB;

    int tid = threadIdx.x, wid = tid >> 5, lane = tid & 31;
    int g4 = lane >> 2, q4 = lane & 3;
    int bh = blockIdx.y;
    int b = bh >> 4, h = bh & 15;
    int i0 = blockIdx.x * 128;
    const float* qb = qg + ((long)bh * SS + i0) * HD;
    const float* kb_ = kg + (long)bh * SS * HD;
    const float* vb = vg + (long)bh * SS * HD;
    const float* biasb = biasg + (long)bh * SS * SS;   // [j][i]

    #pragma unroll
    for (int rep = 0; rep < 6; rep++) {
        int idx = rep * 256 + tid;
        int r = idx / 12, c4 = (idx % 12) * 4;
        float4 v = *(const float4*)&qb[(long)r * HD + c4];
        uint32_t* d = &Qs[r * QP + c4];
        d[0] = f2tf32(v.x); d[1] = f2tf32(v.y); d[2] = f2tf32(v.z); d[3] = f2tf32(v.w);
    }

    int wr = wid * 16;
    float accO[6][4];
    #pragma unroll
    for (int n = 0; n < 6; n++)
        #pragma unroll
        for (int t = 0; t < 4; t++) accO[n][t] = 0.f;
    float mrow[2] = {-1e30f, -1e30f};
    float lrow[2] = {0.f, 0.f};

    float4 pk[3]; float pv[12];
    #pragma unroll
    for (int rep = 0; rep < 3; rep++) {
        int idx = rep * 256 + tid;
        int r = idx / 12, c4 = (idx % 12) * 4;
        pk[rep] = *(const float4*)&kb_[(long)r * HD + c4];
    }
    #pragma unroll
    for (int rep = 0; rep < 12; rep++) {
        int idx = rep * 256 + tid;
        int r = idx / 48, d = idx % 48;
        pv[rep] = vb[(long)r * HD + d];
    }

    for (int j = 0; j < 12; j++) {
        __syncthreads();
        #pragma unroll
        for (int rep = 0; rep < 3; rep++) {
            int idx = rep * 256 + tid;
            int r = idx / 12, c4 = (idx % 12) * 4;
            uint32_t* d = &Ks[r * KP + c4];
            d[0] = f2tf32(pk[rep].x); d[1] = f2tf32(pk[rep].y);
            d[2] = f2tf32(pk[rep].z); d[3] = f2tf32(pk[rep].w);
        }
        #pragma unroll
        for (int rep = 0; rep < 12; rep++) {
            int idx = rep * 256 + tid;
            int r = idx / 48, d = idx % 48;
            Vs[d * VP + r] = f2tf32(pv[rep]);
        }
        __syncthreads();
        if (j + 1 < 12) {
            #pragma unroll
            for (int rep = 0; rep < 3; rep++) {
                int idx = rep * 256 + tid;
                int r = idx / 12, c4 = (idx % 12) * 4;
                pk[rep] = *(const float4*)&kb_[(long)((j + 1) * 64 + r) * HD + c4];
            }
            #pragma unroll
            for (int rep = 0; rep < 12; rep++) {
                int idx = rep * 256 + tid;
                int r = idx / 48, d = idx % 48;
                pv[rep] = vb[(long)((j + 1) * 64 + r) * HD + d];
            }
        }

        float S[8][4];
        #pragma unroll
        for (int nt = 0; nt < 8; nt++)
            #pragma unroll
            for (int t = 0; t < 4; t++) S[nt][t] = 0.f;
        #pragma unroll
        for (int kc = 0; kc < 6; kc++) {
            int kbx = kc * 8 + q4;
            uint32_t af[4];
            af[0] = Qs[(wr + g4) * QP + kbx];
            af[1] = Qs[(wr + g4 + 8) * QP + kbx];
            af[2] = Qs[(wr + g4) * QP + kbx + 4];
            af[3] = Qs[(wr + g4 + 8) * QP + kbx + 4];
            #pragma unroll
            for (int nt = 0; nt < 8; nt++) {
                uint32_t bf2[2];
                bf2[0] = Ks[(nt * 8 + g4) * KP + kbx];
                bf2[1] = Ks[(nt * 8 + g4) * KP + kbx + 4];
                mma_tf32(S[nt], af, bf2);
            }
        }
        const float* bj = biasb + (long)(j * 64) * SS + i0;
        int r0 = wr + g4, r1 = r0 + 8;
        float mn0 = mrow[0], mn1 = mrow[1];
        #pragma unroll
        for (int nt = 0; nt < 8; nt++) {
            #pragma unroll
            for (int t = 0; t < 4; t++) {
                int rr = (t >= 2) ? r1 : r0;
                int cc = nt * 8 + 2 * q4 + (t & 1);
                float val = S[nt][t] * SCALE + __ldg(&bj[(long)cc * SS + rr]);
                S[nt][t] = val;
                if (t < 2) mn0 = fmaxf(mn0, val); else mn1 = fmaxf(mn1, val);
            }
        }
        mn0 = fmaxf(mn0, __shfl_xor_sync(0xffffffffu, mn0, 1));
        mn0 = fmaxf(mn0, __shfl_xor_sync(0xffffffffu, mn0, 2));
        mn1 = fmaxf(mn1, __shfl_xor_sync(0xffffffffu, mn1, 1));
        mn1 = fmaxf(mn1, __shfl_xor_sync(0xffffffffu, mn1, 2));
        float al0 = __expf(mrow[0] - mn0);
        float al1 = __expf(mrow[1] - mn1);
        mrow[0] = mn0; mrow[1] = mn1;
        float s0 = 0.f, s1 = 0.f;
        #pragma unroll
        for (int nt = 0; nt < 8; nt++) {
            #pragma unroll
            for (int t = 0; t < 4; t++) {
                float p = __expf(S[nt][t] - ((t >= 2) ? mn1 : mn0));
                S[nt][t] = p;
                if (t < 2) s0 += p; else s1 += p;
                int rr = (t >= 2) ? r1 : r0;
                int cc = nt * 8 + 2 * q4 + (t & 1);
                Ps[rr * PP + cc] = f2tf32(p);
            }
        }
        s0 += __shfl_xor_sync(0xffffffffu, s0, 1);
        s0 += __shfl_xor_sync(0xffffffffu, s0, 2);
        s1 += __shfl_xor_sync(0xffffffffu, s1, 1);
        s1 += __shfl_xor_sync(0xffffffffu, s1, 2);
        lrow[0] = lrow[0] * al0 + s0;
        lrow[1] = lrow[1] * al1 + s1;
        #pragma unroll
        for (int n = 0; n < 6; n++) {
            accO[n][0] *= al0; accO[n][1] *= al0;
            accO[n][2] *= al1; accO[n][3] *= al1;
        }
        __syncwarp();
        #pragma unroll
        for (int kc = 0; kc < 8; kc++) {
            int kbx = kc * 8 + q4;
            uint32_t af[4];
            af[0] = Ps[(wr + g4) * PP + kbx];
            af[1] = Ps[(wr + g4 + 8) * PP + kbx];
            af[2] = Ps[(wr + g4) * PP + kbx + 4];
            af[3] = Ps[(wr + g4 + 8) * PP + kbx + 4];
            #pragma unroll
            for (int n = 0; n < 6; n++) {
                uint32_t bf2[2];
                bf2[0] = Vs[(n * 8 + g4) * VP + kbx];
                bf2[1] = Vs[(n * 8 + g4) * VP + kbx + 4];
                mma_tf32(accO[n], af, bf2);
            }
        }
    }

    float inv0 = 1.0f / lrow[0], inv1 = 1.0f / lrow[1];
    #pragma unroll
    for (int n = 0; n < 6; n++) {
        #pragma unroll
        for (int t = 0; t < 4; t++) {
            int r = wr + g4 + ((t >= 2) ? 8 : 0);
            int c = n * 8 + 2 * q4 + (t & 1);
            long gi = ((long)(b * SS + i0 + r)) * CA + h * HD + c;
            float o = accO[n][t] * ((t >= 2) ? inv1 : inv0);
            outg[gi] = o * sigmoidf_(gateg[gi]);
        }
    }
}

// ---------------- host side --------------------------------------------------
static float* sym(const void* symbol) {
    void* p = nullptr;
    cudaGetSymbolAddress(&p, symbol);
    return (float*)p;
}

extern "C" void kernel_launch(void* const* d_in, const int* in_sizes, int n_in,
                              void* d_out, int out_size) {
    const float* a        = (const float*)d_in[0];
    const float* s        = (const float*)d_in[1];
    const float* z        = (const float*)d_in[2];
    const float* beta     = (const float*)d_in[3];
    const float* gamma_s  = (const float*)d_in[4];
    const float* W_ada_g  = (const float*)d_in[5];
    const float* b_ada_g  = (const float*)d_in[6];
    const float* W_ada_o  = (const float*)d_in[7];
    const float* Wq       = (const float*)d_in[8];
    const float* bq       = (const float*)d_in[9];
    const float* Wk       = (const float*)d_in[10];
    const float* Wv       = (const float*)d_in[11];
    const float* Wb       = (const float*)d_in[12];
    const float* gz       = (const float*)d_in[13];
    const float* bz       = (const float*)d_in[14];
    const float* Wg       = (const float*)d_in[15];
    const float* Wout     = (const float*)d_in[16];
    const float* Ws_gate  = (const float*)d_in[17];
    const float* bs_gate  = (const float*)d_in[18];
    float* out = (float*)d_out;

    float* p_q    = sym(g_q);
    float* p_k    = sym(g_k);
    float* p_v    = sym(g_v);
    float* p_gate = sym(g_gate);
    float* p_bias = sym(g_bias);
    float* p_go   = sym(g_go);

    cudaFuncSetAttribute(gemm_ada,        cudaFuncAttributeMaxDynamicSharedMemorySize, ADA_SMEM);
    cudaFuncSetAttribute(gemm_proj4,      cudaFuncAttributeMaxDynamicSharedMemorySize, PROJ_SMEM);
    cudaFuncSetAttribute(gemm_final,      cudaFuncAttributeMaxDynamicSharedMemorySize, PROJ_SMEM);
    cudaFuncSetAttribute(pairbias6_kernel,cudaFuncAttributeMaxDynamicSharedMemorySize, PB_SMEM);
    cudaFuncSetAttribute(attn_kernel,     cudaFuncAttributeMaxDynamicSharedMemorySize, ATT_SMEM);

    // 1. layer norms
    ln_kernel<<<MM, 256>>>(s, a, gamma_s);
    // 2. adaLN (fused dual GEMM, cp.async)
    gemm_ada<<<dim3(CA / 64, MM / 128), 256, ADA_SMEM>>>(W_ada_g, W_ada_o, b_ada_g);
    // 3. 4-way projections (cp.async)
    gemm_proj4<<<dim3(4 * CA / 64, MM / 128), 256, PROJ_SMEM>>>(Wq, Wk, Wv, Wg, bq);
    // 4. pair bias (bf16 MMA, v6)
    pairbias6_kernel<<<dim3(SS / 64, SS, BB), 256, PB_SMEM>>>(z, beta, Wb, gz, bz);
    // 5. fused attention (pipelined K/V, direct-gmem bias)
    attn_kernel<<<dim3(SS / 128, BB * HH), 256, ATT_SMEM>>>(p_q, p_k, p_v, p_bias, p_gate, p_go);
    // 6. fused output GEMM + s-gate (cp.async)
    gemm_final<<<dim3(CA / 64, MM / 128), 256, PROJ_SMEM>>>(Wout, s, Ws_gate, bs_gate, out);
}